// round 11
// baseline (speedup 1.0000x reference)
#include <cuda_runtime.h>
#include <cuda_bf16.h>
#include <math.h>
#include <stdint.h>

#define BATCH 2
#define TSEQ  2048
#define CDIM  1024
#define NHEAD 16
#define HD    64
#define MROWS (BATCH * TSEQ)     // 4096
#define NQKV  (3 * CDIM)         // 3072
#define KDIM  1024

// ---------------------------------------------------------------------------
// Scratch (allocation-free: __device__ globals). Q/K/V as bf16 hi/lo planes.
// ---------------------------------------------------------------------------
#define QKV_ELEMS (BATCH * NHEAD * TSEQ * HD)
__device__ __align__(256) __nv_bfloat16 g_Qhi[QKV_ELEMS];
__device__ __align__(256) __nv_bfloat16 g_Qlo[QKV_ELEMS];
__device__ __align__(256) __nv_bfloat16 g_Khi[QKV_ELEMS];
__device__ __align__(256) __nv_bfloat16 g_Klo[QKV_ELEMS];
__device__ __align__(256) __nv_bfloat16 g_Vhi[QKV_ELEMS];
__device__ __align__(256) __nv_bfloat16 g_Vlo[QKV_ELEMS];
__device__ __align__(256) __nv_bfloat16 g_Xhi[MROWS * CDIM];
__device__ __align__(256) __nv_bfloat16 g_Xlo[MROWS * CDIM];
__device__ __align__(256) __nv_bfloat16 g_WaThi[NQKV * CDIM];
__device__ __align__(256) __nv_bfloat16 g_WaTlo[NQKV * CDIM];
__device__ __align__(256) __nv_bfloat16 g_WpThi[CDIM * CDIM];
__device__ __align__(256) __nv_bfloat16 g_WpTlo[CDIM * CDIM];
__device__ __align__(256) __nv_bfloat16 g_Ohi[MROWS * CDIM];
__device__ __align__(256) __nv_bfloat16 g_Olo[MROWS * CDIM];

// ---------------------------------------------------------------------------
// PTX helpers (arch-generic only: cp.async, ldmatrix, mma.sync)
// ---------------------------------------------------------------------------
__device__ __forceinline__ uint32_t smem_u32(const void* p) {
    uint32_t a;
    asm("{ .reg .u64 t; cvta.to.shared.u64 t, %1; cvt.u32.u64 %0, t; }"
        : "=r"(a) : "l"(p));
    return a;
}

#define CPA16(dst, src) \
    asm volatile("cp.async.cg.shared.global [%0], [%1], 16;" :: "r"(dst), "l"(src))
#define CPA_COMMIT() asm volatile("cp.async.commit_group;" ::: "memory")
#define CPA_WAIT2()  asm volatile("cp.async.wait_group 2;" ::: "memory")
#define CPA_WAIT1()  asm volatile("cp.async.wait_group 1;" ::: "memory")
#define CPA_WAIT0()  asm volatile("cp.async.wait_group 0;" ::: "memory")

#define LDSM4(r, addr)                                                        \
    asm volatile("ldmatrix.sync.aligned.m8n8.x4.shared.b16 {%0,%1,%2,%3}, [%4];" \
        : "=r"((r)[0]), "=r"((r)[1]), "=r"((r)[2]), "=r"((r)[3]) : "r"(addr))

#define LDSM4T(r, addr)                                                       \
    asm volatile("ldmatrix.sync.aligned.m8n8.x4.trans.shared.b16 {%0,%1,%2,%3}, [%4];" \
        : "=r"((r)[0]), "=r"((r)[1]), "=r"((r)[2]), "=r"((r)[3]) : "r"(addr))

#define MMA_BF16(d, a, b0v, b1v)                                              \
    asm volatile("mma.sync.aligned.m16n8k16.row.col.f32.bf16.bf16.f32 "       \
        "{%0,%1,%2,%3}, {%4,%5,%6,%7}, {%8,%9}, {%0,%1,%2,%3};"               \
        : "+f"((d)[0]), "+f"((d)[1]), "+f"((d)[2]), "+f"((d)[3])              \
        : "r"((a)[0]), "r"((a)[1]), "r"((a)[2]), "r"((a)[3]),                 \
          "r"(b0v), "r"(b1v))

// ---------------------------------------------------------------------------
// Prep kernels
// ---------------------------------------------------------------------------
__global__ void split_kernel(const float* __restrict__ in,
                             __nv_bfloat16* __restrict__ hi,
                             __nv_bfloat16* __restrict__ lo, int n4) {
    for (int i = blockIdx.x * blockDim.x + threadIdx.x; i < n4;
         i += gridDim.x * blockDim.x) {
        float4 v = ((const float4*)in)[i];
        __nv_bfloat16 hx = __float2bfloat16_rn(v.x);
        __nv_bfloat16 hy = __float2bfloat16_rn(v.y);
        __nv_bfloat16 hz = __float2bfloat16_rn(v.z);
        __nv_bfloat16 hw = __float2bfloat16_rn(v.w);
        __nv_bfloat16 lx = __float2bfloat16_rn(v.x - __bfloat162float(hx));
        __nv_bfloat16 ly = __float2bfloat16_rn(v.y - __bfloat162float(hy));
        __nv_bfloat16 lz = __float2bfloat16_rn(v.z - __bfloat162float(hz));
        __nv_bfloat16 lw = __float2bfloat16_rn(v.w - __bfloat162float(hw));
        ((__nv_bfloat162*)hi)[2 * i + 0] = __nv_bfloat162(hx, hy);
        ((__nv_bfloat162*)hi)[2 * i + 1] = __nv_bfloat162(hz, hw);
        ((__nv_bfloat162*)lo)[2 * i + 0] = __nv_bfloat162(lx, ly);
        ((__nv_bfloat162*)lo)[2 * i + 1] = __nv_bfloat162(lz, lw);
    }
}

__global__ void transpose_split_kernel(const float* __restrict__ in,
                                       __nv_bfloat16* __restrict__ ohi,
                                       __nv_bfloat16* __restrict__ olo,
                                       int R, int C) {
    __shared__ float t[32][33];
    const int c0 = blockIdx.x * 32, r0 = blockIdx.y * 32;
    const int x = threadIdx.x & 31, y0 = threadIdx.x >> 5;
#pragma unroll
    for (int i = 0; i < 4; ++i) {
        int y = y0 + i * 8;
        t[y][x] = in[(size_t)(r0 + y) * C + c0 + x];
    }
    __syncthreads();
#pragma unroll
    for (int i = 0; i < 4; ++i) {
        int yy = y0 + i * 8;
        float v = t[x][yy];
        __nv_bfloat16 hi = __float2bfloat16_rn(v);
        __nv_bfloat16 lo = __float2bfloat16_rn(v - __bfloat162float(hi));
        size_t o = (size_t)(c0 + yy) * R + r0 + x;
        ohi[o] = hi;
        olo[o] = lo;
    }
}

// ---------------------------------------------------------------------------
// mma.sync bf16 split-3 GEMM. CTA 128x128, 8 warps, BK=32, 4-stage cp.async.
// R10: fragment-level software pipeline — dedicated register buffers per
// k16-half (buf0=kh0, buf1=kh1) so LDSM of one half overlaps MMAs of the
// other (removes the WAR serialization seen at tensor=52.6%).
// MODE 0: fake-quant + scatter to bf16 hi/lo Q/K/V planes.
// MODE 1: epilogue writes Cout row-major fp32.
// ---------------------------------------------------------------------------
#define STAGE_BYTES 32768        // Ahi 8K | Alo 8K | Bhi 8K | Blo 8K
#define NSTAGES 4
#define SMEM_DYN (STAGE_BYTES * NSTAGES)   // 131072

template <int MODE>
__global__ __launch_bounds__(256, 1) void mma_gemm_kernel(
    const __nv_bfloat16* __restrict__ Ahi, const __nv_bfloat16* __restrict__ Alo,
    const __nv_bfloat16* __restrict__ Bhi, const __nv_bfloat16* __restrict__ Blo,
    const float* __restrict__ bias, int Ncols,
    const float* __restrict__ scale_p, const float* __restrict__ zp_p,
    float* __restrict__ Cout)
{
    extern __shared__ __align__(1024) char smem[];
    const uint32_t sb = smem_u32(smem);
    const int tid = threadIdx.x;
    const int wid = tid >> 5, lane = tid & 31;
    const int m0 = blockIdx.y * 128, n0 = blockIdx.x * 128;
    const int wm = wid & 3;
    const int wn = wid >> 2;

    float acc[2][8][4];
#pragma unroll
    for (int i = 0; i < 2; ++i)
#pragma unroll
        for (int j = 0; j < 8; ++j)
#pragma unroll
            for (int k = 0; k < 4; ++k) acc[i][j][k] = 0.0f;

    auto load_stage = [&](int kt, int s) {
        const uint32_t st = sb + (uint32_t)s * STAGE_BYTES;
        const int kb = kt * 32;
#pragma unroll
        for (int p = 0; p < 2; ++p) {
            const __nv_bfloat16* src = p ? Alo : Ahi;
            const uint32_t po = st + p * 8192;
#pragma unroll
            for (int i = 0; i < 2; ++i) {
                int idx = tid + i * 256;
                int row = idx >> 2, c = idx & 3;
                uint32_t dst = po + row * 64 + ((c ^ ((row >> 1) & 3)) << 4);
                CPA16(dst, src + (size_t)(m0 + row) * KDIM + kb + c * 8);
            }
        }
#pragma unroll
        for (int p = 0; p < 2; ++p) {
            const __nv_bfloat16* src = p ? Blo : Bhi;
            const uint32_t po = st + 16384 + p * 8192;
#pragma unroll
            for (int i = 0; i < 2; ++i) {
                int idx = tid + i * 256;
                int row = idx >> 2, c = idx & 3;
                uint32_t dst = po + row * 64 + ((c ^ ((row >> 1) & 3)) << 4);
                CPA16(dst, src + (size_t)(n0 + row) * KDIM + kb + c * 8);
            }
        }
        CPA_COMMIT();
    };

    // Fragment buffers: FA[buf][plane][mf][4], FB[buf][plane][16].
    // buf 0 <-> kh=0, buf 1 <-> kh=1 (fixed mapping, constant indices).
    uint32_t FA0[2][2][4], FA1[2][2][4];
    uint32_t FB0[2][16],   FB1[2][16];

    const int arow_lo = ((lane >> 3) & 1) * 8 + (lane & 7);
    const int acol_sel = (lane >> 4) & 1;
    const int brow_lo = ((lane >> 4) & 1) * 8 + (lane & 7);
    const int bcol_sel = (lane >> 3) & 1;

#define LD_FRAGS(FA, FB, stbase, kh)                                          \
    do {                                                                      \
        const uint32_t _st = (stbase);                                        \
        const int _cb = (kh) * 2;                                             \
        _Pragma("unroll")                                                     \
        for (int p = 0; p < 2; ++p) {                                         \
            _Pragma("unroll")                                                 \
            for (int mf = 0; mf < 2; ++mf) {                                  \
                int row = wm * 32 + mf * 16 + arow_lo;                        \
                int c = _cb + acol_sel;                                       \
                LDSM4(FA[p][mf], _st + p * 8192 + row * 64                    \
                                 + ((c ^ ((row >> 1) & 3)) << 4));            \
            }                                                                 \
        }                                                                     \
        _Pragma("unroll")                                                     \
        for (int p = 0; p < 2; ++p) {                                         \
            _Pragma("unroll")                                                 \
            for (int nq = 0; nq < 4; ++nq) {                                  \
                int row = wn * 64 + nq * 16 + brow_lo;                        \
                int c = _cb + bcol_sel;                                       \
                LDSM4(&FB[p][nq * 4], _st + 16384 + p * 8192 + row * 64       \
                                      + ((c ^ ((row >> 1) & 3)) << 4));       \
            }                                                                 \
        }                                                                     \
    } while (0)

#define DO_MMAS(FA, FB)                                                       \
    do {                                                                      \
        _Pragma("unroll")                                                     \
        for (int mf = 0; mf < 2; ++mf) {                                      \
            _Pragma("unroll")                                                 \
            for (int nf = 0; nf < 8; ++nf) {                                  \
                const int bi = (nf >> 1) * 4 + (nf & 1) * 2;                  \
                MMA_BF16(acc[mf][nf], FA[0][mf], FB[0][bi], FB[0][bi + 1]);   \
                MMA_BF16(acc[mf][nf], FA[1][mf], FB[0][bi], FB[0][bi + 1]);   \
                MMA_BF16(acc[mf][nf], FA[0][mf], FB[1][bi], FB[1][bi + 1]);   \
            }                                                                 \
        }                                                                     \
    } while (0)

    load_stage(0, 0);
    load_stage(1, 1);
    load_stage(2, 2);

    const int NK = KDIM / 32;   // 32
    CPA_WAIT2();                // stage 0 ready
    __syncthreads();
    LD_FRAGS(FA0, FB0, sb + 0u * STAGE_BYTES, 0);   // kh0 of stage 0

    for (int kt = 0; kt < NK; ++kt) {
        const int s = kt & (NSTAGES - 1);
        const uint32_t st = sb + (uint32_t)s * STAGE_BYTES;

        // Prefetch kh1 fragments of this stage, then run kh0's MMAs.
        LD_FRAGS(FA1, FB1, st, 1);
        DO_MMAS(FA0, FB0);

        if (kt + 3 < NK) load_stage(kt + 3, (kt + 3) & (NSTAGES - 1));

        if (kt + 1 < NK) {
            // Make stage kt+1 ready, prefetch its kh0 fragments.
            if (kt <= NK - 4)      { CPA_WAIT2(); }
            else if (kt == NK - 3) { CPA_WAIT1(); }
            else                   { CPA_WAIT0(); }
            __syncthreads();
            const uint32_t stn = sb + (uint32_t)((kt + 1) & (NSTAGES - 1)) * STAGE_BYTES;
            LD_FRAGS(FA0, FB0, stn, 0);
        }

        DO_MMAS(FA1, FB1);
    }

    float scl = 1.0f, zp = 0.0f;
    if (MODE == 0) { scl = *scale_p; zp = *zp_p; }

#pragma unroll
    for (int mf = 0; mf < 2; ++mf) {
#pragma unroll
        for (int nf = 0; nf < 8; ++nf) {
            const int n = n0 + wn * 64 + nf * 8 + (lane & 3) * 2;
            const float2 bv = *(const float2*)(bias + n);
#pragma unroll
            for (int half = 0; half < 2; ++half) {
                const int m = m0 + wm * 32 + mf * 16 + (lane >> 2) + half * 8;
                float v0 = acc[mf][nf][half * 2 + 0] + bv.x;
                float v1 = acc[mf][nf][half * 2 + 1] + bv.y;
                if (MODE == 0) {
                    const int bb = m >> 11;
                    const int t = m & 2047;
                    const int which = n >> 10;
                    const int cI = n & 1023;
                    const int h = cI >> 6, d = cI & 63;
                    const size_t idx = (((size_t)(bb * NHEAD + h) * TSEQ + t) * HD + d);
                    if (which != 0) {   // fake-quant K/V
                        float q0 = fminf(fmaxf(rintf(v0 / scl + zp), 0.0f), 255.0f);
                        float q1 = fminf(fmaxf(rintf(v1 / scl + zp), 0.0f), 255.0f);
                        v0 = (q0 - zp) * scl;
                        v1 = (q1 - zp) * scl;
                    }
                    __nv_bfloat16 h0 = __float2bfloat16_rn(v0);
                    __nv_bfloat16 h1 = __float2bfloat16_rn(v1);
                    __nv_bfloat16 l0 = __float2bfloat16_rn(v0 - __bfloat162float(h0));
                    __nv_bfloat16 l1 = __float2bfloat16_rn(v1 - __bfloat162float(h1));
                    __nv_bfloat162 hv(h0, h1), lv(l0, l1);
                    if (which == 0) {
                        *(__nv_bfloat162*)(g_Qhi + idx) = hv;
                        *(__nv_bfloat162*)(g_Qlo + idx) = lv;
                    } else if (which == 1) {
                        *(__nv_bfloat162*)(g_Khi + idx) = hv;
                        *(__nv_bfloat162*)(g_Klo + idx) = lv;
                    } else {
                        *(__nv_bfloat162*)(g_Vhi + idx) = hv;
                        *(__nv_bfloat162*)(g_Vlo + idx) = lv;
                    }
                } else {
                    *(float2*)(Cout + (size_t)m * Ncols + n) = make_float2(v0, v1);
                }
            }
        }
    }
#undef LD_FRAGS
#undef DO_MMAS
}

// ---------------------------------------------------------------------------
// Tensor-core causal flash attention (FA2-style, proven in R9), unchanged.
// ---------------------------------------------------------------------------
#define FS_QH 0
#define FS_QL 16384
#define FS_ST 32768
#define FS_STAGE 32768           // KH 8K | KL 8K | VH 8K | VL 8K
#define FS_TOTAL (FS_ST + 2 * FS_STAGE)   // 98304

__global__ __launch_bounds__(128, 2) void flash_mma_kernel()
{
    extern __shared__ __align__(1024) char fsm[];
    const uint32_t sb = smem_u32(fsm);
    const int qb = (TSEQ / 128 - 1) - blockIdx.x;   // long blocks first
    const int h = blockIdx.y, b = blockIdx.z;
    const int tid = threadIdx.x, warp = tid >> 5, lane = tid & 31;
    const size_t bh = (size_t)(b * NHEAD + h) * TSEQ * HD;

    const __nv_bfloat16* Qh = g_Qhi + bh + (size_t)qb * 128 * HD;
    const __nv_bfloat16* Ql = g_Qlo + bh + (size_t)qb * 128 * HD;
    const __nv_bfloat16* Kh = g_Khi + bh;
    const __nv_bfloat16* Kl = g_Klo + bh;
    const __nv_bfloat16* Vh = g_Vhi + bh;
    const __nv_bfloat16* Vl = g_Vlo + bh;

#pragma unroll
    for (int p = 0; p < 2; ++p) {
        const __nv_bfloat16* src = p ? Ql : Qh;
        const uint32_t base = sb + (p ? FS_QL : FS_QH);
#pragma unroll
        for (int i = 0; i < 8; ++i) {
            int idx = tid + i * 128;
            int row = idx >> 3, c = idx & 7;
            CPA16(base + row * 128 + ((c ^ (row & 7)) << 4), src + row * 64 + c * 8);
        }
    }

    auto load_tile = [&](int j, int s) {
        const uint32_t st = sb + FS_ST + (uint32_t)s * FS_STAGE;
        const __nv_bfloat16* srcs[4] = {
            Kh + (size_t)j * 64 * HD, Kl + (size_t)j * 64 * HD,
            Vh + (size_t)j * 64 * HD, Vl + (size_t)j * 64 * HD };
#pragma unroll
        for (int p = 0; p < 4; ++p) {
#pragma unroll
            for (int i = 0; i < 4; ++i) {
                int idx = tid + i * 128;
                int row = idx >> 3, c = idx & 7;
                CPA16(st + p * 8192 + row * 128 + ((c ^ (row & 7)) << 4),
                      srcs[p] + row * 64 + c * 8);
            }
        }
    };

    load_tile(0, 0);
    CPA_COMMIT();
    load_tile(1, 1);
    CPA_COMMIT();

    float O[2][8][4];
#pragma unroll
    for (int mf = 0; mf < 2; ++mf)
#pragma unroll
        for (int nf = 0; nf < 8; ++nf)
#pragma unroll
            for (int e = 0; e < 4; ++e) O[mf][nf][e] = 0.0f;
    float rm[2][2], rl[2][2];
#pragma unroll
    for (int mf = 0; mf < 2; ++mf)
#pragma unroll
        for (int hf = 0; hf < 2; ++hf) { rm[mf][hf] = -1e30f; rl[mf][hf] = 0.0f; }

    const int ntiles = 2 * qb + 2;
    CPA_WAIT1();

    for (int j = 0; j < ntiles; ++j) {
        const int s = j & 1;
        __syncthreads();
        const uint32_t st = sb + FS_ST + (uint32_t)s * FS_STAGE;

        float S[2][8][4];
#pragma unroll
        for (int mf = 0; mf < 2; ++mf)
#pragma unroll
            for (int nf = 0; nf < 8; ++nf)
#pragma unroll
                for (int e = 0; e < 4; ++e) S[mf][nf][e] = 0.0f;

#pragma unroll
        for (int ks = 0; ks < 4; ++ks) {
            uint32_t aQ[2][2][4];
#pragma unroll
            for (int p = 0; p < 2; ++p) {
#pragma unroll
                for (int mf = 0; mf < 2; ++mf) {
                    int row = warp * 32 + mf * 16 + ((lane >> 3) & 1) * 8 + (lane & 7);
                    int c = ks * 2 + ((lane >> 4) & 1);
                    LDSM4(aQ[p][mf], sb + (p ? FS_QL : FS_QH) + row * 128
                                     + ((c ^ (row & 7)) << 4));
                }
            }
            uint32_t bK[2][4][4];
#pragma unroll
            for (int p = 0; p < 2; ++p) {
#pragma unroll
                for (int kg = 0; kg < 4; ++kg) {
                    int row = kg * 16 + ((lane >> 4) & 1) * 8 + (lane & 7);
                    int c = ks * 2 + ((lane >> 3) & 1);
                    LDSM4(bK[p][kg], st + p * 8192 + row * 128
                                     + ((c ^ (row & 7)) << 4));
                }
            }
#pragma unroll
            for (int mf = 0; mf < 2; ++mf) {
#pragma unroll
                for (int nf = 0; nf < 8; ++nf) {
                    const int kg = nf >> 1, o = (nf & 1) * 2;
                    MMA_BF16(S[mf][nf], aQ[0][mf], bK[0][kg][o], bK[0][kg][o + 1]);
                    MMA_BF16(S[mf][nf], aQ[1][mf], bK[0][kg][o], bK[0][kg][o + 1]);
                    MMA_BF16(S[mf][nf], aQ[0][mf], bK[1][kg][o], bK[1][kg][o + 1]);
                }
            }
        }

        const bool maskT = (j >= 2 * qb);
#pragma unroll
        for (int mf = 0; mf < 2; ++mf)
#pragma unroll
            for (int nf = 0; nf < 8; ++nf)
#pragma unroll
                for (int e = 0; e < 4; ++e) {
                    float sv = S[mf][nf][e] * 0.125f;
                    if (maskT) {
                        const int key = j * 64 + nf * 8 + (lane & 3) * 2 + (e & 1);
                        const int rowg = qb * 128 + warp * 32 + mf * 16
                                       + (lane >> 2) + (e >> 1) * 8;
                        if (key > rowg) sv = -1e30f;
                    }
                    S[mf][nf][e] = sv;
                }

#pragma unroll
        for (int mf = 0; mf < 2; ++mf) {
#pragma unroll
            for (int hf = 0; hf < 2; ++hf) {
                float mx = -1e30f;
#pragma unroll
                for (int nf = 0; nf < 8; ++nf)
                    mx = fmaxf(mx, fmaxf(S[mf][nf][hf * 2], S[mf][nf][hf * 2 + 1]));
                mx = fmaxf(mx, __shfl_xor_sync(0xFFFFFFFFu, mx, 1));
                mx = fmaxf(mx, __shfl_xor_sync(0xFFFFFFFFu, mx, 2));
                const float mnew = fmaxf(rm[mf][hf], mx);
                const float corr = __expf(rm[mf][hf] - mnew);
                rm[mf][hf] = mnew;
                float ps = 0.0f;
#pragma unroll
                for (int nf = 0; nf < 8; ++nf) {
                    float p0 = __expf(S[mf][nf][hf * 2 + 0] - mnew);
                    float p1 = __expf(S[mf][nf][hf * 2 + 1] - mnew);
                    S[mf][nf][hf * 2 + 0] = p0;
                    S[mf][nf][hf * 2 + 1] = p1;
                    ps += p0 + p1;
                }
                ps += __shfl_xor_sync(0xFFFFFFFFu, ps, 1);
                ps += __shfl_xor_sync(0xFFFFFFFFu, ps, 2);
                rl[mf][hf] = rl[mf][hf] * corr + ps;
#pragma unroll
                for (int nf = 0; nf < 8; ++nf) {
                    O[mf][nf][hf * 2 + 0] *= corr;
                    O[mf][nf][hf * 2 + 1] *= corr;
                }
            }
        }

#pragma unroll
        for (int kc = 0; kc < 4; ++kc) {
            uint32_t aP[2][2][4];
#pragma unroll
            for (int mf = 0; mf < 2; ++mf) {
#pragma unroll
                for (int e = 0; e < 2; ++e) {
                    const int nf = 2 * kc + e;
#pragma unroll
                    for (int hf = 0; hf < 2; ++hf) {
                        float x = S[mf][nf][hf * 2 + 0];
                        float y = S[mf][nf][hf * 2 + 1];
                        __nv_bfloat16 hx = __float2bfloat16_rn(x);
                        __nv_bfloat16 hy = __float2bfloat16_rn(y);
                        __nv_bfloat162 hv(hx, hy);
                        __nv_bfloat162 lv(
                            __float2bfloat16_rn(x - __bfloat162float(hx)),
                            __float2bfloat16_rn(y - __bfloat162float(hy)));
                        aP[0][mf][e * 2 + hf] = *(uint32_t*)&hv;
                        aP[1][mf][e * 2 + hf] = *(uint32_t*)&lv;
                    }
                }
            }
            uint32_t bV[2][4][4];
#pragma unroll
            for (int p = 0; p < 2; ++p) {
#pragma unroll
                for (int dg = 0; dg < 4; ++dg) {
                    int row = kc * 16 + ((lane >> 3) & 1) * 8 + (lane & 7);
                    int c = dg * 2 + ((lane >> 4) & 1);
                    LDSM4T(bV[p][dg], st + (2 + p) * 8192 + row * 128
                                      + ((c ^ (row & 7)) << 4));
                }
            }
#pragma unroll
            for (int mf = 0; mf < 2; ++mf) {
#pragma unroll
                for (int nf = 0; nf < 8; ++nf) {
                    const int dg = nf >> 1, o = (nf & 1) * 2;
                    MMA_BF16(O[mf][nf], aP[0][mf], bV[0][dg][o], bV[0][dg][o + 1]);
                    MMA_BF16(O[mf][nf], aP[1][mf], bV[0][dg][o], bV[0][dg][o + 1]);
                    MMA_BF16(O[mf][nf], aP[0][mf], bV[1][dg][o], bV[1][dg][o + 1]);
                }
            }
        }

        __syncthreads();
        if (j + 2 < ntiles) { load_tile(j + 2, s); CPA_COMMIT(); }
        if (j + 1 < ntiles) {
            if (j + 2 < ntiles) { CPA_WAIT1(); } else { CPA_WAIT0(); }
        }
    }

#pragma unroll
    for (int mf = 0; mf < 2; ++mf) {
#pragma unroll
        for (int hf = 0; hf < 2; ++hf) {
            const float inv = 1.0f / rl[mf][hf];
            const int row = qb * 128 + warp * 32 + mf * 16 + (lane >> 2) + hf * 8;
            const size_t ob = ((size_t)(b * TSEQ) + row) * CDIM + h * 64;
#pragma unroll
            for (int nf = 0; nf < 8; ++nf) {
                const int d = nf * 8 + (lane & 3) * 2;
                float v0 = O[mf][nf][hf * 2 + 0] * inv;
                float v1 = O[mf][nf][hf * 2 + 1] * inv;
                __nv_bfloat16 h0 = __float2bfloat16_rn(v0);
                __nv_bfloat16 h1 = __float2bfloat16_rn(v1);
                __nv_bfloat162 hv(h0, h1);
                __nv_bfloat162 lv(
                    __float2bfloat16_rn(v0 - __bfloat162float(h0)),
                    __float2bfloat16_rn(v1 - __bfloat162float(h1)));
                *(__nv_bfloat162*)(g_Ohi + ob + d) = hv;
                *(__nv_bfloat162*)(g_Olo + ob + d) = lv;
            }
        }
    }
}

// ---------------------------------------------------------------------------
// Launch
// ---------------------------------------------------------------------------
extern "C" void kernel_launch(void* const* d_in, const int* in_sizes, int n_in,
                              void* d_out, int out_size)
{
    const float* hidden   = (const float*)d_in[0];
    const float* W_attn   = (const float*)d_in[1];
    const float* b_attn   = (const float*)d_in[2];
    const float* W_proj   = (const float*)d_in[3];
    const float* b_proj   = (const float*)d_in[4];
    const float* kv_scale = (const float*)d_in[5];
    const float* kv_zp    = (const float*)d_in[6];
    float* out = (float*)d_out;

    cudaFuncSetAttribute(mma_gemm_kernel<0>,
                         cudaFuncAttributeMaxDynamicSharedMemorySize, SMEM_DYN);
    cudaFuncSetAttribute(mma_gemm_kernel<1>,
                         cudaFuncAttributeMaxDynamicSharedMemorySize, SMEM_DYN);
    cudaFuncSetAttribute(flash_mma_kernel,
                         cudaFuncAttributeMaxDynamicSharedMemorySize, FS_TOTAL);

    __nv_bfloat16 *Xhi, *Xlo, *WaThi, *WaTlo, *WpThi, *WpTlo, *Ohi, *Olo;
    cudaGetSymbolAddress((void**)&Xhi, g_Xhi);
    cudaGetSymbolAddress((void**)&Xlo, g_Xlo);
    cudaGetSymbolAddress((void**)&WaThi, g_WaThi);
    cudaGetSymbolAddress((void**)&WaTlo, g_WaTlo);
    cudaGetSymbolAddress((void**)&WpThi, g_WpThi);
    cudaGetSymbolAddress((void**)&WpTlo, g_WpTlo);
    cudaGetSymbolAddress((void**)&Ohi, g_Ohi);
    cudaGetSymbolAddress((void**)&Olo, g_Olo);

    // Prep
    split_kernel<<<1024, 256>>>(hidden, Xhi, Xlo, MROWS * CDIM / 4);
    transpose_split_kernel<<<dim3(NQKV / 32, CDIM / 32), 256>>>(W_attn, WaThi, WaTlo, CDIM, NQKV);
    transpose_split_kernel<<<dim3(CDIM / 32, CDIM / 32), 256>>>(W_proj, WpThi, WpTlo, CDIM, CDIM);

    // QKV GEMM + bias + fake-quant + bf16 hi/lo scatter
    mma_gemm_kernel<0><<<dim3(NQKV / 128, MROWS / 128), 256, SMEM_DYN>>>(
        Xhi, Xlo, WaThi, WaTlo, b_attn, NQKV, kv_scale, kv_zp, nullptr);

    // Tensor-core causal flash attention
    flash_mma_kernel<<<dim3(TSEQ / 128, NHEAD, BATCH), 128, FS_TOTAL>>>();

    // Output projection
    mma_gemm_kernel<1><<<dim3(CDIM / 128, MROWS / 128), 256, SMEM_DYN>>>(
        Ohi, Olo, WpThi, WpTlo, b_proj, CDIM, nullptr, nullptr, out);
}

// round 12
// speedup vs baseline: 1.0616x; 1.0616x over previous
#include <cuda_runtime.h>
#include <cuda_bf16.h>
#include <math.h>
#include <stdint.h>

#define BATCH 2
#define TSEQ  2048
#define CDIM  1024
#define NHEAD 16
#define HD    64
#define MROWS (BATCH * TSEQ)     // 4096
#define NQKV  (3 * CDIM)         // 3072
#define KDIM  1024

// ---------------------------------------------------------------------------
// Scratch (allocation-free: __device__ globals). Q/K/V as bf16 hi/lo planes.
// ---------------------------------------------------------------------------
#define QKV_ELEMS (BATCH * NHEAD * TSEQ * HD)
__device__ __align__(256) __nv_bfloat16 g_Qhi[QKV_ELEMS];
__device__ __align__(256) __nv_bfloat16 g_Qlo[QKV_ELEMS];
__device__ __align__(256) __nv_bfloat16 g_Khi[QKV_ELEMS];
__device__ __align__(256) __nv_bfloat16 g_Klo[QKV_ELEMS];
__device__ __align__(256) __nv_bfloat16 g_Vhi[QKV_ELEMS];
__device__ __align__(256) __nv_bfloat16 g_Vlo[QKV_ELEMS];
__device__ __align__(256) __nv_bfloat16 g_Xhi[MROWS * CDIM];
__device__ __align__(256) __nv_bfloat16 g_Xlo[MROWS * CDIM];
__device__ __align__(256) __nv_bfloat16 g_WaThi[NQKV * CDIM];
__device__ __align__(256) __nv_bfloat16 g_WaTlo[NQKV * CDIM];
__device__ __align__(256) __nv_bfloat16 g_WpThi[CDIM * CDIM];
__device__ __align__(256) __nv_bfloat16 g_WpTlo[CDIM * CDIM];
__device__ __align__(256) __nv_bfloat16 g_Ohi[MROWS * CDIM];
__device__ __align__(256) __nv_bfloat16 g_Olo[MROWS * CDIM];

// ---------------------------------------------------------------------------
// PTX helpers (arch-generic only: cp.async, ldmatrix, mma.sync)
// ---------------------------------------------------------------------------
__device__ __forceinline__ uint32_t smem_u32(const void* p) {
    uint32_t a;
    asm("{ .reg .u64 t; cvta.to.shared.u64 t, %1; cvt.u32.u64 %0, t; }"
        : "=r"(a) : "l"(p));
    return a;
}

#define CPA16(dst, src) \
    asm volatile("cp.async.cg.shared.global [%0], [%1], 16;" :: "r"(dst), "l"(src))
#define CPA_COMMIT() asm volatile("cp.async.commit_group;" ::: "memory")
#define CPA_WAIT2()  asm volatile("cp.async.wait_group 2;" ::: "memory")
#define CPA_WAIT1()  asm volatile("cp.async.wait_group 1;" ::: "memory")
#define CPA_WAIT0()  asm volatile("cp.async.wait_group 0;" ::: "memory")

#define LDSM4(r, addr)                                                        \
    asm volatile("ldmatrix.sync.aligned.m8n8.x4.shared.b16 {%0,%1,%2,%3}, [%4];" \
        : "=r"((r)[0]), "=r"((r)[1]), "=r"((r)[2]), "=r"((r)[3]) : "r"(addr))

#define LDSM4T(r, addr)                                                       \
    asm volatile("ldmatrix.sync.aligned.m8n8.x4.trans.shared.b16 {%0,%1,%2,%3}, [%4];" \
        : "=r"((r)[0]), "=r"((r)[1]), "=r"((r)[2]), "=r"((r)[3]) : "r"(addr))

#define MMA_BF16(d, a, b0v, b1v)                                              \
    asm volatile("mma.sync.aligned.m16n8k16.row.col.f32.bf16.bf16.f32 "       \
        "{%0,%1,%2,%3}, {%4,%5,%6,%7}, {%8,%9}, {%0,%1,%2,%3};"               \
        : "+f"((d)[0]), "+f"((d)[1]), "+f"((d)[2]), "+f"((d)[3])              \
        : "r"((a)[0]), "r"((a)[1]), "r"((a)[2]), "r"((a)[3]),                 \
          "r"(b0v), "r"(b1v))

// ---------------------------------------------------------------------------
// Prep kernels
// ---------------------------------------------------------------------------
__global__ void split_kernel(const float* __restrict__ in,
                             __nv_bfloat16* __restrict__ hi,
                             __nv_bfloat16* __restrict__ lo, int n4) {
    for (int i = blockIdx.x * blockDim.x + threadIdx.x; i < n4;
         i += gridDim.x * blockDim.x) {
        float4 v = ((const float4*)in)[i];
        __nv_bfloat16 hx = __float2bfloat16_rn(v.x);
        __nv_bfloat16 hy = __float2bfloat16_rn(v.y);
        __nv_bfloat16 hz = __float2bfloat16_rn(v.z);
        __nv_bfloat16 hw = __float2bfloat16_rn(v.w);
        __nv_bfloat16 lx = __float2bfloat16_rn(v.x - __bfloat162float(hx));
        __nv_bfloat16 ly = __float2bfloat16_rn(v.y - __bfloat162float(hy));
        __nv_bfloat16 lz = __float2bfloat16_rn(v.z - __bfloat162float(hz));
        __nv_bfloat16 lw = __float2bfloat16_rn(v.w - __bfloat162float(hw));
        ((__nv_bfloat162*)hi)[2 * i + 0] = __nv_bfloat162(hx, hy);
        ((__nv_bfloat162*)hi)[2 * i + 1] = __nv_bfloat162(hz, hw);
        ((__nv_bfloat162*)lo)[2 * i + 0] = __nv_bfloat162(lx, ly);
        ((__nv_bfloat162*)lo)[2 * i + 1] = __nv_bfloat162(lz, lw);
    }
}

__global__ void transpose_split_kernel(const float* __restrict__ in,
                                       __nv_bfloat16* __restrict__ ohi,
                                       __nv_bfloat16* __restrict__ olo,
                                       int R, int C) {
    __shared__ float t[32][33];
    const int c0 = blockIdx.x * 32, r0 = blockIdx.y * 32;
    const int x = threadIdx.x & 31, y0 = threadIdx.x >> 5;
#pragma unroll
    for (int i = 0; i < 4; ++i) {
        int y = y0 + i * 8;
        t[y][x] = in[(size_t)(r0 + y) * C + c0 + x];
    }
    __syncthreads();
#pragma unroll
    for (int i = 0; i < 4; ++i) {
        int yy = y0 + i * 8;
        float v = t[x][yy];
        __nv_bfloat16 hi = __float2bfloat16_rn(v);
        __nv_bfloat16 lo = __float2bfloat16_rn(v - __bfloat162float(hi));
        size_t o = (size_t)(c0 + yy) * R + r0 + x;
        ohi[o] = hi;
        olo[o] = lo;
    }
}

// ---------------------------------------------------------------------------
// mma.sync bf16 split-3 GEMM (R9 structure). CTA 128x128, 8 warps, BK=32,
// 4-stage cp.async. R11: plane-major MMA order — all hi*hi, then lo*hi,
// then hi*lo — so consecutive MMAs never share an accumulator (kills the
// RAW chain that held tensor pipe at ~50%).
// MODE 0: fake-quant + scatter to bf16 hi/lo Q/K/V planes.
// MODE 1: epilogue writes Cout row-major fp32.
// ---------------------------------------------------------------------------
#define STAGE_BYTES 32768        // Ahi 8K | Alo 8K | Bhi 8K | Blo 8K
#define NSTAGES 4
#define SMEM_DYN (STAGE_BYTES * NSTAGES)   // 131072

template <int MODE>
__global__ __launch_bounds__(256, 1) void mma_gemm_kernel(
    const __nv_bfloat16* __restrict__ Ahi, const __nv_bfloat16* __restrict__ Alo,
    const __nv_bfloat16* __restrict__ Bhi, const __nv_bfloat16* __restrict__ Blo,
    const float* __restrict__ bias, int Ncols,
    const float* __restrict__ scale_p, const float* __restrict__ zp_p,
    float* __restrict__ Cout)
{
    extern __shared__ __align__(1024) char smem[];
    const uint32_t sb = smem_u32(smem);
    const int tid = threadIdx.x;
    const int wid = tid >> 5, lane = tid & 31;
    const int m0 = blockIdx.y * 128, n0 = blockIdx.x * 128;
    const int wm = wid & 3;
    const int wn = wid >> 2;

    float acc[2][8][4];
#pragma unroll
    for (int i = 0; i < 2; ++i)
#pragma unroll
        for (int j = 0; j < 8; ++j)
#pragma unroll
            for (int k = 0; k < 4; ++k) acc[i][j][k] = 0.0f;

    auto load_stage = [&](int kt, int s) {
        const uint32_t st = sb + (uint32_t)s * STAGE_BYTES;
        const int kb = kt * 32;
#pragma unroll
        for (int p = 0; p < 2; ++p) {
            const __nv_bfloat16* src = p ? Alo : Ahi;
            const uint32_t po = st + p * 8192;
#pragma unroll
            for (int i = 0; i < 2; ++i) {
                int idx = tid + i * 256;
                int row = idx >> 2, c = idx & 3;
                uint32_t dst = po + row * 64 + ((c ^ ((row >> 1) & 3)) << 4);
                CPA16(dst, src + (size_t)(m0 + row) * KDIM + kb + c * 8);
            }
        }
#pragma unroll
        for (int p = 0; p < 2; ++p) {
            const __nv_bfloat16* src = p ? Blo : Bhi;
            const uint32_t po = st + 16384 + p * 8192;
#pragma unroll
            for (int i = 0; i < 2; ++i) {
                int idx = tid + i * 256;
                int row = idx >> 2, c = idx & 3;
                uint32_t dst = po + row * 64 + ((c ^ ((row >> 1) & 3)) << 4);
                CPA16(dst, src + (size_t)(n0 + row) * KDIM + kb + c * 8);
            }
        }
        CPA_COMMIT();
    };

    load_stage(0, 0);
    load_stage(1, 1);
    load_stage(2, 2);

    const int NK = KDIM / 32;
    for (int kt = 0; kt < NK; ++kt) {
        const int s = kt & (NSTAGES - 1);
        if (kt <= NK - 3)      { CPA_WAIT2(); }
        else if (kt == NK - 2) { CPA_WAIT1(); }
        else                   { CPA_WAIT0(); }
        __syncthreads();

        const uint32_t st = sb + (uint32_t)s * STAGE_BYTES;
#pragma unroll
        for (int kh = 0; kh < 2; ++kh) {
            const int cbase = kh * 2;
            uint32_t a[2][2][4];
#pragma unroll
            for (int p = 0; p < 2; ++p) {
#pragma unroll
                for (int mf = 0; mf < 2; ++mf) {
                    int row = wm * 32 + mf * 16 + ((lane >> 3) & 1) * 8 + (lane & 7);
                    int c = cbase + ((lane >> 4) & 1);
                    uint32_t addr = st + p * 8192 + row * 64
                                  + ((c ^ ((row >> 1) & 3)) << 4);
                    LDSM4(a[p][mf], addr);
                }
            }
            uint32_t b[2][16];
#pragma unroll
            for (int p = 0; p < 2; ++p) {
#pragma unroll
                for (int nq = 0; nq < 4; ++nq) {
                    int row = wn * 64 + nq * 16 + ((lane >> 4) & 1) * 8 + (lane & 7);
                    int c = cbase + ((lane >> 3) & 1);
                    uint32_t addr = st + 16384 + p * 8192 + row * 64
                                  + ((c ^ ((row >> 1) & 3)) << 4);
                    LDSM4(&b[p][nq * 4], addr);
                }
            }
            // Plane-major passes: no two consecutive MMAs share an accumulator.
#pragma unroll
            for (int mf = 0; mf < 2; ++mf)
#pragma unroll
                for (int nf = 0; nf < 8; ++nf) {
                    const int bi = (nf >> 1) * 4 + (nf & 1) * 2;
                    MMA_BF16(acc[mf][nf], a[0][mf], b[0][bi], b[0][bi + 1]);
                }
#pragma unroll
            for (int mf = 0; mf < 2; ++mf)
#pragma unroll
                for (int nf = 0; nf < 8; ++nf) {
                    const int bi = (nf >> 1) * 4 + (nf & 1) * 2;
                    MMA_BF16(acc[mf][nf], a[1][mf], b[0][bi], b[0][bi + 1]);
                }
#pragma unroll
            for (int mf = 0; mf < 2; ++mf)
#pragma unroll
                for (int nf = 0; nf < 8; ++nf) {
                    const int bi = (nf >> 1) * 4 + (nf & 1) * 2;
                    MMA_BF16(acc[mf][nf], a[0][mf], b[1][bi], b[1][bi + 1]);
                }
        }

        if (kt + 3 < NK) load_stage(kt + 3, (kt + 3) & (NSTAGES - 1));
    }

    float scl = 1.0f, zp = 0.0f;
    if (MODE == 0) { scl = *scale_p; zp = *zp_p; }

#pragma unroll
    for (int mf = 0; mf < 2; ++mf) {
#pragma unroll
        for (int nf = 0; nf < 8; ++nf) {
            const int n = n0 + wn * 64 + nf * 8 + (lane & 3) * 2;
            const float2 bv = *(const float2*)(bias + n);
#pragma unroll
            for (int half = 0; half < 2; ++half) {
                const int m = m0 + wm * 32 + mf * 16 + (lane >> 2) + half * 8;
                float v0 = acc[mf][nf][half * 2 + 0] + bv.x;
                float v1 = acc[mf][nf][half * 2 + 1] + bv.y;
                if (MODE == 0) {
                    const int bb = m >> 11;
                    const int t = m & 2047;
                    const int which = n >> 10;
                    const int cI = n & 1023;
                    const int h = cI >> 6, d = cI & 63;
                    const size_t idx = (((size_t)(bb * NHEAD + h) * TSEQ + t) * HD + d);
                    if (which != 0) {   // fake-quant K/V
                        float q0 = fminf(fmaxf(rintf(v0 / scl + zp), 0.0f), 255.0f);
                        float q1 = fminf(fmaxf(rintf(v1 / scl + zp), 0.0f), 255.0f);
                        v0 = (q0 - zp) * scl;
                        v1 = (q1 - zp) * scl;
                    }
                    __nv_bfloat16 h0 = __float2bfloat16_rn(v0);
                    __nv_bfloat16 h1 = __float2bfloat16_rn(v1);
                    __nv_bfloat16 l0 = __float2bfloat16_rn(v0 - __bfloat162float(h0));
                    __nv_bfloat16 l1 = __float2bfloat16_rn(v1 - __bfloat162float(h1));
                    __nv_bfloat162 hv(h0, h1), lv(l0, l1);
                    if (which == 0) {
                        *(__nv_bfloat162*)(g_Qhi + idx) = hv;
                        *(__nv_bfloat162*)(g_Qlo + idx) = lv;
                    } else if (which == 1) {
                        *(__nv_bfloat162*)(g_Khi + idx) = hv;
                        *(__nv_bfloat162*)(g_Klo + idx) = lv;
                    } else {
                        *(__nv_bfloat162*)(g_Vhi + idx) = hv;
                        *(__nv_bfloat162*)(g_Vlo + idx) = lv;
                    }
                } else {
                    *(float2*)(Cout + (size_t)m * Ncols + n) = make_float2(v0, v1);
                }
            }
        }
    }
}

// ---------------------------------------------------------------------------
// Tensor-core causal flash attention (FA2-style). R11: plane-major MMA
// passes in both the S and O loops (same RAW-chain fix as the GEMM).
// ---------------------------------------------------------------------------
#define FS_QH 0
#define FS_QL 16384
#define FS_ST 32768
#define FS_STAGE 32768           // KH 8K | KL 8K | VH 8K | VL 8K
#define FS_TOTAL (FS_ST + 2 * FS_STAGE)   // 98304

__global__ __launch_bounds__(128, 2) void flash_mma_kernel()
{
    extern __shared__ __align__(1024) char fsm[];
    const uint32_t sb = smem_u32(fsm);
    const int qb = (TSEQ / 128 - 1) - blockIdx.x;   // long blocks first
    const int h = blockIdx.y, b = blockIdx.z;
    const int tid = threadIdx.x, warp = tid >> 5, lane = tid & 31;
    const size_t bh = (size_t)(b * NHEAD + h) * TSEQ * HD;

    const __nv_bfloat16* Qh = g_Qhi + bh + (size_t)qb * 128 * HD;
    const __nv_bfloat16* Ql = g_Qlo + bh + (size_t)qb * 128 * HD;
    const __nv_bfloat16* Kh = g_Khi + bh;
    const __nv_bfloat16* Kl = g_Klo + bh;
    const __nv_bfloat16* Vh = g_Vhi + bh;
    const __nv_bfloat16* Vl = g_Vlo + bh;

#pragma unroll
    for (int p = 0; p < 2; ++p) {
        const __nv_bfloat16* src = p ? Ql : Qh;
        const uint32_t base = sb + (p ? FS_QL : FS_QH);
#pragma unroll
        for (int i = 0; i < 8; ++i) {
            int idx = tid + i * 128;
            int row = idx >> 3, c = idx & 7;
            CPA16(base + row * 128 + ((c ^ (row & 7)) << 4), src + row * 64 + c * 8);
        }
    }

    auto load_tile = [&](int j, int s) {
        const uint32_t st = sb + FS_ST + (uint32_t)s * FS_STAGE;
        const __nv_bfloat16* srcs[4] = {
            Kh + (size_t)j * 64 * HD, Kl + (size_t)j * 64 * HD,
            Vh + (size_t)j * 64 * HD, Vl + (size_t)j * 64 * HD };
#pragma unroll
        for (int p = 0; p < 4; ++p) {
#pragma unroll
            for (int i = 0; i < 4; ++i) {
                int idx = tid + i * 128;
                int row = idx >> 3, c = idx & 7;
                CPA16(st + p * 8192 + row * 128 + ((c ^ (row & 7)) << 4),
                      srcs[p] + row * 64 + c * 8);
            }
        }
    };

    load_tile(0, 0);
    CPA_COMMIT();
    load_tile(1, 1);
    CPA_COMMIT();

    float O[2][8][4];
#pragma unroll
    for (int mf = 0; mf < 2; ++mf)
#pragma unroll
        for (int nf = 0; nf < 8; ++nf)
#pragma unroll
            for (int e = 0; e < 4; ++e) O[mf][nf][e] = 0.0f;
    float rm[2][2], rl[2][2];
#pragma unroll
    for (int mf = 0; mf < 2; ++mf)
#pragma unroll
        for (int hf = 0; hf < 2; ++hf) { rm[mf][hf] = -1e30f; rl[mf][hf] = 0.0f; }

    const int ntiles = 2 * qb + 2;
    CPA_WAIT1();

    for (int j = 0; j < ntiles; ++j) {
        const int s = j & 1;
        __syncthreads();
        const uint32_t st = sb + FS_ST + (uint32_t)s * FS_STAGE;

        float S[2][8][4];
#pragma unroll
        for (int mf = 0; mf < 2; ++mf)
#pragma unroll
            for (int nf = 0; nf < 8; ++nf)
#pragma unroll
                for (int e = 0; e < 4; ++e) S[mf][nf][e] = 0.0f;

#pragma unroll
        for (int ks = 0; ks < 4; ++ks) {
            uint32_t aQ[2][2][4];
#pragma unroll
            for (int p = 0; p < 2; ++p) {
#pragma unroll
                for (int mf = 0; mf < 2; ++mf) {
                    int row = warp * 32 + mf * 16 + ((lane >> 3) & 1) * 8 + (lane & 7);
                    int c = ks * 2 + ((lane >> 4) & 1);
                    LDSM4(aQ[p][mf], sb + (p ? FS_QL : FS_QH) + row * 128
                                     + ((c ^ (row & 7)) << 4));
                }
            }
            uint32_t bK[2][4][4];
#pragma unroll
            for (int p = 0; p < 2; ++p) {
#pragma unroll
                for (int kg = 0; kg < 4; ++kg) {
                    int row = kg * 16 + ((lane >> 4) & 1) * 8 + (lane & 7);
                    int c = ks * 2 + ((lane >> 3) & 1);
                    LDSM4(bK[p][kg], st + p * 8192 + row * 128
                                     + ((c ^ (row & 7)) << 4));
                }
            }
            // Plane-major passes
#pragma unroll
            for (int mf = 0; mf < 2; ++mf)
#pragma unroll
                for (int nf = 0; nf < 8; ++nf) {
                    const int kg = nf >> 1, o = (nf & 1) * 2;
                    MMA_BF16(S[mf][nf], aQ[0][mf], bK[0][kg][o], bK[0][kg][o + 1]);
                }
#pragma unroll
            for (int mf = 0; mf < 2; ++mf)
#pragma unroll
                for (int nf = 0; nf < 8; ++nf) {
                    const int kg = nf >> 1, o = (nf & 1) * 2;
                    MMA_BF16(S[mf][nf], aQ[1][mf], bK[0][kg][o], bK[0][kg][o + 1]);
                }
#pragma unroll
            for (int mf = 0; mf < 2; ++mf)
#pragma unroll
                for (int nf = 0; nf < 8; ++nf) {
                    const int kg = nf >> 1, o = (nf & 1) * 2;
                    MMA_BF16(S[mf][nf], aQ[0][mf], bK[1][kg][o], bK[1][kg][o + 1]);
                }
        }

        const bool maskT = (j >= 2 * qb);
#pragma unroll
        for (int mf = 0; mf < 2; ++mf)
#pragma unroll
            for (int nf = 0; nf < 8; ++nf)
#pragma unroll
                for (int e = 0; e < 4; ++e) {
                    float sv = S[mf][nf][e] * 0.125f;
                    if (maskT) {
                        const int key = j * 64 + nf * 8 + (lane & 3) * 2 + (e & 1);
                        const int rowg = qb * 128 + warp * 32 + mf * 16
                                       + (lane >> 2) + (e >> 1) * 8;
                        if (key > rowg) sv = -1e30f;
                    }
                    S[mf][nf][e] = sv;
                }

#pragma unroll
        for (int mf = 0; mf < 2; ++mf) {
#pragma unroll
            for (int hf = 0; hf < 2; ++hf) {
                float mx = -1e30f;
#pragma unroll
                for (int nf = 0; nf < 8; ++nf)
                    mx = fmaxf(mx, fmaxf(S[mf][nf][hf * 2], S[mf][nf][hf * 2 + 1]));
                mx = fmaxf(mx, __shfl_xor_sync(0xFFFFFFFFu, mx, 1));
                mx = fmaxf(mx, __shfl_xor_sync(0xFFFFFFFFu, mx, 2));
                const float mnew = fmaxf(rm[mf][hf], mx);
                const float corr = __expf(rm[mf][hf] - mnew);
                rm[mf][hf] = mnew;
                float ps = 0.0f;
#pragma unroll
                for (int nf = 0; nf < 8; ++nf) {
                    float p0 = __expf(S[mf][nf][hf * 2 + 0] - mnew);
                    float p1 = __expf(S[mf][nf][hf * 2 + 1] - mnew);
                    S[mf][nf][hf * 2 + 0] = p0;
                    S[mf][nf][hf * 2 + 1] = p1;
                    ps += p0 + p1;
                }
                ps += __shfl_xor_sync(0xFFFFFFFFu, ps, 1);
                ps += __shfl_xor_sync(0xFFFFFFFFu, ps, 2);
                rl[mf][hf] = rl[mf][hf] * corr + ps;
#pragma unroll
                for (int nf = 0; nf < 8; ++nf) {
                    O[mf][nf][hf * 2 + 0] *= corr;
                    O[mf][nf][hf * 2 + 1] *= corr;
                }
            }
        }

#pragma unroll
        for (int kc = 0; kc < 4; ++kc) {
            uint32_t aP[2][2][4];
#pragma unroll
            for (int mf = 0; mf < 2; ++mf) {
#pragma unroll
                for (int e = 0; e < 2; ++e) {
                    const int nf = 2 * kc + e;
#pragma unroll
                    for (int hf = 0; hf < 2; ++hf) {
                        float x = S[mf][nf][hf * 2 + 0];
                        float y = S[mf][nf][hf * 2 + 1];
                        __nv_bfloat16 hx = __float2bfloat16_rn(x);
                        __nv_bfloat16 hy = __float2bfloat16_rn(y);
                        __nv_bfloat162 hv(hx, hy);
                        __nv_bfloat162 lv(
                            __float2bfloat16_rn(x - __bfloat162float(hx)),
                            __float2bfloat16_rn(y - __bfloat162float(hy)));
                        aP[0][mf][e * 2 + hf] = *(uint32_t*)&hv;
                        aP[1][mf][e * 2 + hf] = *(uint32_t*)&lv;
                    }
                }
            }
            uint32_t bV[2][4][4];
#pragma unroll
            for (int p = 0; p < 2; ++p) {
#pragma unroll
                for (int dg = 0; dg < 4; ++dg) {
                    int row = kc * 16 + ((lane >> 3) & 1) * 8 + (lane & 7);
                    int c = dg * 2 + ((lane >> 4) & 1);
                    LDSM4T(bV[p][dg], st + (2 + p) * 8192 + row * 128
                                      + ((c ^ (row & 7)) << 4));
                }
            }
            // Plane-major passes
#pragma unroll
            for (int mf = 0; mf < 2; ++mf)
#pragma unroll
                for (int nf = 0; nf < 8; ++nf) {
                    const int dg = nf >> 1, o = (nf & 1) * 2;
                    MMA_BF16(O[mf][nf], aP[0][mf], bV[0][dg][o], bV[0][dg][o + 1]);
                }
#pragma unroll
            for (int mf = 0; mf < 2; ++mf)
#pragma unroll
                for (int nf = 0; nf < 8; ++nf) {
                    const int dg = nf >> 1, o = (nf & 1) * 2;
                    MMA_BF16(O[mf][nf], aP[1][mf], bV[0][dg][o], bV[0][dg][o + 1]);
                }
#pragma unroll
            for (int mf = 0; mf < 2; ++mf)
#pragma unroll
                for (int nf = 0; nf < 8; ++nf) {
                    const int dg = nf >> 1, o = (nf & 1) * 2;
                    MMA_BF16(O[mf][nf], aP[0][mf], bV[1][dg][o], bV[1][dg][o + 1]);
                }
        }

        __syncthreads();
        if (j + 2 < ntiles) { load_tile(j + 2, s); CPA_COMMIT(); }
        if (j + 1 < ntiles) {
            if (j + 2 < ntiles) { CPA_WAIT1(); } else { CPA_WAIT0(); }
        }
    }

#pragma unroll
    for (int mf = 0; mf < 2; ++mf) {
#pragma unroll
        for (int hf = 0; hf < 2; ++hf) {
            const float inv = 1.0f / rl[mf][hf];
            const int row = qb * 128 + warp * 32 + mf * 16 + (lane >> 2) + hf * 8;
            const size_t ob = ((size_t)(b * TSEQ) + row) * CDIM + h * 64;
#pragma unroll
            for (int nf = 0; nf < 8; ++nf) {
                const int d = nf * 8 + (lane & 3) * 2;
                float v0 = O[mf][nf][hf * 2 + 0] * inv;
                float v1 = O[mf][nf][hf * 2 + 1] * inv;
                __nv_bfloat16 h0 = __float2bfloat16_rn(v0);
                __nv_bfloat16 h1 = __float2bfloat16_rn(v1);
                __nv_bfloat162 hv(h0, h1);
                __nv_bfloat162 lv(
                    __float2bfloat16_rn(v0 - __bfloat162float(h0)),
                    __float2bfloat16_rn(v1 - __bfloat162float(h1)));
                *(__nv_bfloat162*)(g_Ohi + ob + d) = hv;
                *(__nv_bfloat162*)(g_Olo + ob + d) = lv;
            }
        }
    }
}

// ---------------------------------------------------------------------------
// Launch
// ---------------------------------------------------------------------------
extern "C" void kernel_launch(void* const* d_in, const int* in_sizes, int n_in,
                              void* d_out, int out_size)
{
    const float* hidden   = (const float*)d_in[0];
    const float* W_attn   = (const float*)d_in[1];
    const float* b_attn   = (const float*)d_in[2];
    const float* W_proj   = (const float*)d_in[3];
    const float* b_proj   = (const float*)d_in[4];
    const float* kv_scale = (const float*)d_in[5];
    const float* kv_zp    = (const float*)d_in[6];
    float* out = (float*)d_out;

    cudaFuncSetAttribute(mma_gemm_kernel<0>,
                         cudaFuncAttributeMaxDynamicSharedMemorySize, SMEM_DYN);
    cudaFuncSetAttribute(mma_gemm_kernel<1>,
                         cudaFuncAttributeMaxDynamicSharedMemorySize, SMEM_DYN);
    cudaFuncSetAttribute(flash_mma_kernel,
                         cudaFuncAttributeMaxDynamicSharedMemorySize, FS_TOTAL);

    __nv_bfloat16 *Xhi, *Xlo, *WaThi, *WaTlo, *WpThi, *WpTlo, *Ohi, *Olo;
    cudaGetSymbolAddress((void**)&Xhi, g_Xhi);
    cudaGetSymbolAddress((void**)&Xlo, g_Xlo);
    cudaGetSymbolAddress((void**)&WaThi, g_WaThi);
    cudaGetSymbolAddress((void**)&WaTlo, g_WaTlo);
    cudaGetSymbolAddress((void**)&WpThi, g_WpThi);
    cudaGetSymbolAddress((void**)&WpTlo, g_WpTlo);
    cudaGetSymbolAddress((void**)&Ohi, g_Ohi);
    cudaGetSymbolAddress((void**)&Olo, g_Olo);

    // Prep
    split_kernel<<<1024, 256>>>(hidden, Xhi, Xlo, MROWS * CDIM / 4);
    transpose_split_kernel<<<dim3(NQKV / 32, CDIM / 32), 256>>>(W_attn, WaThi, WaTlo, CDIM, NQKV);
    transpose_split_kernel<<<dim3(CDIM / 32, CDIM / 32), 256>>>(W_proj, WpThi, WpTlo, CDIM, CDIM);

    // QKV GEMM + bias + fake-quant + bf16 hi/lo scatter
    mma_gemm_kernel<0><<<dim3(NQKV / 128, MROWS / 128), 256, SMEM_DYN>>>(
        Xhi, Xlo, WaThi, WaTlo, b_attn, NQKV, kv_scale, kv_zp, nullptr);

    // Tensor-core causal flash attention
    flash_mma_kernel<<<dim3(TSEQ / 128, NHEAD, BATCH), 128, FS_TOTAL>>>();

    // Output projection
    mma_gemm_kernel<1><<<dim3(CDIM / 128, MROWS / 128), 256, SMEM_DYN>>>(
        Ohi, Olo, WpThi, WpTlo, b_proj, CDIM, nullptr, nullptr, out);
}

// round 13
// speedup vs baseline: 1.1113x; 1.0469x over previous
#include <cuda_runtime.h>
#include <cuda_bf16.h>
#include <math.h>
#include <stdint.h>

#define BATCH 2
#define TSEQ  2048
#define CDIM  1024
#define NHEAD 16
#define HD    64
#define MROWS (BATCH * TSEQ)     // 4096
#define NQKV  (3 * CDIM)         // 3072
#define KDIM  1024

// ---------------------------------------------------------------------------
// Scratch (allocation-free: __device__ globals). Q/K/V as bf16 hi/lo planes.
// ---------------------------------------------------------------------------
#define QKV_ELEMS (BATCH * NHEAD * TSEQ * HD)
__device__ __align__(256) __nv_bfloat16 g_Qhi[QKV_ELEMS];
__device__ __align__(256) __nv_bfloat16 g_Qlo[QKV_ELEMS];
__device__ __align__(256) __nv_bfloat16 g_Khi[QKV_ELEMS];
__device__ __align__(256) __nv_bfloat16 g_Klo[QKV_ELEMS];
__device__ __align__(256) __nv_bfloat16 g_Vhi[QKV_ELEMS];
__device__ __align__(256) __nv_bfloat16 g_Vlo[QKV_ELEMS];
__device__ __align__(256) __nv_bfloat16 g_Xhi[MROWS * CDIM];
__device__ __align__(256) __nv_bfloat16 g_Xlo[MROWS * CDIM];
__device__ __align__(256) __nv_bfloat16 g_WaThi[NQKV * CDIM];
__device__ __align__(256) __nv_bfloat16 g_WaTlo[NQKV * CDIM];
__device__ __align__(256) __nv_bfloat16 g_WpThi[CDIM * CDIM];
__device__ __align__(256) __nv_bfloat16 g_WpTlo[CDIM * CDIM];
__device__ __align__(256) __nv_bfloat16 g_Ohi[MROWS * CDIM];
__device__ __align__(256) __nv_bfloat16 g_Olo[MROWS * CDIM];

// ---------------------------------------------------------------------------
// PTX helpers (arch-generic only: cp.async, ldmatrix, mma.sync)
// ---------------------------------------------------------------------------
__device__ __forceinline__ uint32_t smem_u32(const void* p) {
    uint32_t a;
    asm("{ .reg .u64 t; cvta.to.shared.u64 t, %1; cvt.u32.u64 %0, t; }"
        : "=r"(a) : "l"(p));
    return a;
}

#define CPA16(dst, src) \
    asm volatile("cp.async.cg.shared.global [%0], [%1], 16;" :: "r"(dst), "l"(src))
#define CPA_COMMIT() asm volatile("cp.async.commit_group;" ::: "memory")
#define CPA_WAIT1()  asm volatile("cp.async.wait_group 1;" ::: "memory")
#define CPA_WAIT0()  asm volatile("cp.async.wait_group 0;" ::: "memory")

#define LDSM4(r, addr)                                                        \
    asm volatile("ldmatrix.sync.aligned.m8n8.x4.shared.b16 {%0,%1,%2,%3}, [%4];" \
        : "=r"((r)[0]), "=r"((r)[1]), "=r"((r)[2]), "=r"((r)[3]) : "r"(addr))

#define LDSM4T(r, addr)                                                       \
    asm volatile("ldmatrix.sync.aligned.m8n8.x4.trans.shared.b16 {%0,%1,%2,%3}, [%4];" \
        : "=r"((r)[0]), "=r"((r)[1]), "=r"((r)[2]), "=r"((r)[3]) : "r"(addr))

#define MMA_BF16(d, a, b0v, b1v)                                              \
    asm volatile("mma.sync.aligned.m16n8k16.row.col.f32.bf16.bf16.f32 "       \
        "{%0,%1,%2,%3}, {%4,%5,%6,%7}, {%8,%9}, {%0,%1,%2,%3};"               \
        : "+f"((d)[0]), "+f"((d)[1]), "+f"((d)[2]), "+f"((d)[3])              \
        : "r"((a)[0]), "r"((a)[1]), "r"((a)[2]), "r"((a)[3]),                 \
          "r"(b0v), "r"(b1v))

// ---------------------------------------------------------------------------
// Prep kernels
// ---------------------------------------------------------------------------
__global__ void split_kernel(const float* __restrict__ in,
                             __nv_bfloat16* __restrict__ hi,
                             __nv_bfloat16* __restrict__ lo, int n4) {
    for (int i = blockIdx.x * blockDim.x + threadIdx.x; i < n4;
         i += gridDim.x * blockDim.x) {
        float4 v = ((const float4*)in)[i];
        __nv_bfloat16 hx = __float2bfloat16_rn(v.x);
        __nv_bfloat16 hy = __float2bfloat16_rn(v.y);
        __nv_bfloat16 hz = __float2bfloat16_rn(v.z);
        __nv_bfloat16 hw = __float2bfloat16_rn(v.w);
        __nv_bfloat16 lx = __float2bfloat16_rn(v.x - __bfloat162float(hx));
        __nv_bfloat16 ly = __float2bfloat16_rn(v.y - __bfloat162float(hy));
        __nv_bfloat16 lz = __float2bfloat16_rn(v.z - __bfloat162float(hz));
        __nv_bfloat16 lw = __float2bfloat16_rn(v.w - __bfloat162float(hw));
        ((__nv_bfloat162*)hi)[2 * i + 0] = __nv_bfloat162(hx, hy);
        ((__nv_bfloat162*)hi)[2 * i + 1] = __nv_bfloat162(hz, hw);
        ((__nv_bfloat162*)lo)[2 * i + 0] = __nv_bfloat162(lx, ly);
        ((__nv_bfloat162*)lo)[2 * i + 1] = __nv_bfloat162(lz, lw);
    }
}

__global__ void transpose_split_kernel(const float* __restrict__ in,
                                       __nv_bfloat16* __restrict__ ohi,
                                       __nv_bfloat16* __restrict__ olo,
                                       int R, int C) {
    __shared__ float t[32][33];
    const int c0 = blockIdx.x * 32, r0 = blockIdx.y * 32;
    const int x = threadIdx.x & 31, y0 = threadIdx.x >> 5;
#pragma unroll
    for (int i = 0; i < 4; ++i) {
        int y = y0 + i * 8;
        t[y][x] = in[(size_t)(r0 + y) * C + c0 + x];
    }
    __syncthreads();
#pragma unroll
    for (int i = 0; i < 4; ++i) {
        int yy = y0 + i * 8;
        float v = t[x][yy];
        __nv_bfloat16 hi = __float2bfloat16_rn(v);
        __nv_bfloat16 lo = __float2bfloat16_rn(v - __bfloat162float(hi));
        size_t o = (size_t)(c0 + yy) * R + r0 + x;
        ohi[o] = hi;
        olo[o] = lo;
    }
}

// ---------------------------------------------------------------------------
// mma.sync bf16 split-3 GEMM. CTA 128x128, 8 warps, BK=32.
// R12: 2-stage SMEM (64KB) + __launch_bounds__(256,2) -> 2 CTAs/SM so the
// two CTAs' LDSM/MMA phases decorrelate (occ was the real limiter, not
// intra-warp scheduling: R10/R11 both neutral).
// MODE 0: fake-quant + scatter to bf16 hi/lo Q/K/V planes.
// MODE 1: epilogue writes Cout row-major fp32.
// ---------------------------------------------------------------------------
#define STAGE_BYTES 32768        // Ahi 8K | Alo 8K | Bhi 8K | Blo 8K
#define NSTAGES 2
#define SMEM_DYN (STAGE_BYTES * NSTAGES)   // 65536

template <int MODE>
__global__ __launch_bounds__(256, 2) void mma_gemm_kernel(
    const __nv_bfloat16* __restrict__ Ahi, const __nv_bfloat16* __restrict__ Alo,
    const __nv_bfloat16* __restrict__ Bhi, const __nv_bfloat16* __restrict__ Blo,
    const float* __restrict__ bias, int Ncols,
    const float* __restrict__ scale_p, const float* __restrict__ zp_p,
    float* __restrict__ Cout)
{
    extern __shared__ __align__(1024) char smem[];
    const uint32_t sb = smem_u32(smem);
    const int tid = threadIdx.x;
    const int wid = tid >> 5, lane = tid & 31;
    const int m0 = blockIdx.y * 128, n0 = blockIdx.x * 128;
    const int wm = wid & 3;
    const int wn = wid >> 2;

    float acc[2][8][4];
#pragma unroll
    for (int i = 0; i < 2; ++i)
#pragma unroll
        for (int j = 0; j < 8; ++j)
#pragma unroll
            for (int k = 0; k < 4; ++k) acc[i][j][k] = 0.0f;

    auto load_stage = [&](int kt, int s) {
        const uint32_t st = sb + (uint32_t)s * STAGE_BYTES;
        const int kb = kt * 32;
#pragma unroll
        for (int p = 0; p < 2; ++p) {
            const __nv_bfloat16* src = p ? Alo : Ahi;
            const uint32_t po = st + p * 8192;
#pragma unroll
            for (int i = 0; i < 2; ++i) {
                int idx = tid + i * 256;
                int row = idx >> 2, c = idx & 3;
                uint32_t dst = po + row * 64 + ((c ^ ((row >> 1) & 3)) << 4);
                CPA16(dst, src + (size_t)(m0 + row) * KDIM + kb + c * 8);
            }
        }
#pragma unroll
        for (int p = 0; p < 2; ++p) {
            const __nv_bfloat16* src = p ? Blo : Bhi;
            const uint32_t po = st + 16384 + p * 8192;
#pragma unroll
            for (int i = 0; i < 2; ++i) {
                int idx = tid + i * 256;
                int row = idx >> 2, c = idx & 3;
                uint32_t dst = po + row * 64 + ((c ^ ((row >> 1) & 3)) << 4);
                CPA16(dst, src + (size_t)(n0 + row) * KDIM + kb + c * 8);
            }
        }
        CPA_COMMIT();
    };

    load_stage(0, 0);
    load_stage(1, 1);

    const int NK = KDIM / 32;   // 32
    for (int kt = 0; kt < NK; ++kt) {
        const int s = kt & 1;
        if (kt + 1 < NK) { CPA_WAIT1(); } else { CPA_WAIT0(); }
        __syncthreads();

        const uint32_t st = sb + (uint32_t)s * STAGE_BYTES;
#pragma unroll
        for (int kh = 0; kh < 2; ++kh) {
            const int cbase = kh * 2;
            uint32_t a[2][2][4];
#pragma unroll
            for (int p = 0; p < 2; ++p) {
#pragma unroll
                for (int mf = 0; mf < 2; ++mf) {
                    int row = wm * 32 + mf * 16 + ((lane >> 3) & 1) * 8 + (lane & 7);
                    int c = cbase + ((lane >> 4) & 1);
                    uint32_t addr = st + p * 8192 + row * 64
                                  + ((c ^ ((row >> 1) & 3)) << 4);
                    LDSM4(a[p][mf], addr);
                }
            }
            uint32_t b[2][16];
#pragma unroll
            for (int p = 0; p < 2; ++p) {
#pragma unroll
                for (int nq = 0; nq < 4; ++nq) {
                    int row = wn * 64 + nq * 16 + ((lane >> 4) & 1) * 8 + (lane & 7);
                    int c = cbase + ((lane >> 3) & 1);
                    uint32_t addr = st + 16384 + p * 8192 + row * 64
                                  + ((c ^ ((row >> 1) & 3)) << 4);
                    LDSM4(&b[p][nq * 4], addr);
                }
            }
#pragma unroll
            for (int mf = 0; mf < 2; ++mf)
#pragma unroll
                for (int nf = 0; nf < 8; ++nf) {
                    const int bi = (nf >> 1) * 4 + (nf & 1) * 2;
                    MMA_BF16(acc[mf][nf], a[0][mf], b[0][bi], b[0][bi + 1]);
                }
#pragma unroll
            for (int mf = 0; mf < 2; ++mf)
#pragma unroll
                for (int nf = 0; nf < 8; ++nf) {
                    const int bi = (nf >> 1) * 4 + (nf & 1) * 2;
                    MMA_BF16(acc[mf][nf], a[1][mf], b[0][bi], b[0][bi + 1]);
                }
#pragma unroll
            for (int mf = 0; mf < 2; ++mf)
#pragma unroll
                for (int nf = 0; nf < 8; ++nf) {
                    const int bi = (nf >> 1) * 4 + (nf & 1) * 2;
                    MMA_BF16(acc[mf][nf], a[0][mf], b[1][bi], b[1][bi + 1]);
                }
        }

        __syncthreads();                       // stage s fully consumed
        if (kt + 2 < NK) load_stage(kt + 2, s);
    }

    float scl = 1.0f, zp = 0.0f;
    if (MODE == 0) { scl = *scale_p; zp = *zp_p; }

#pragma unroll
    for (int mf = 0; mf < 2; ++mf) {
#pragma unroll
        for (int nf = 0; nf < 8; ++nf) {
            const int n = n0 + wn * 64 + nf * 8 + (lane & 3) * 2;
            const float2 bv = *(const float2*)(bias + n);
#pragma unroll
            for (int half = 0; half < 2; ++half) {
                const int m = m0 + wm * 32 + mf * 16 + (lane >> 2) + half * 8;
                float v0 = acc[mf][nf][half * 2 + 0] + bv.x;
                float v1 = acc[mf][nf][half * 2 + 1] + bv.y;
                if (MODE == 0) {
                    const int bb = m >> 11;
                    const int t = m & 2047;
                    const int which = n >> 10;
                    const int cI = n & 1023;
                    const int h = cI >> 6, d = cI & 63;
                    const size_t idx = (((size_t)(bb * NHEAD + h) * TSEQ + t) * HD + d);
                    if (which != 0) {   // fake-quant K/V
                        float q0 = fminf(fmaxf(rintf(v0 / scl + zp), 0.0f), 255.0f);
                        float q1 = fminf(fmaxf(rintf(v1 / scl + zp), 0.0f), 255.0f);
                        v0 = (q0 - zp) * scl;
                        v1 = (q1 - zp) * scl;
                    }
                    __nv_bfloat16 h0 = __float2bfloat16_rn(v0);
                    __nv_bfloat16 h1 = __float2bfloat16_rn(v1);
                    __nv_bfloat16 l0 = __float2bfloat16_rn(v0 - __bfloat162float(h0));
                    __nv_bfloat16 l1 = __float2bfloat16_rn(v1 - __bfloat162float(h1));
                    __nv_bfloat162 hv(h0, h1), lv(l0, l1);
                    if (which == 0) {
                        *(__nv_bfloat162*)(g_Qhi + idx) = hv;
                        *(__nv_bfloat162*)(g_Qlo + idx) = lv;
                    } else if (which == 1) {
                        *(__nv_bfloat162*)(g_Khi + idx) = hv;
                        *(__nv_bfloat162*)(g_Klo + idx) = lv;
                    } else {
                        *(__nv_bfloat162*)(g_Vhi + idx) = hv;
                        *(__nv_bfloat162*)(g_Vlo + idx) = lv;
                    }
                } else {
                    *(float2*)(Cout + (size_t)m * Ncols + n) = make_float2(v0, v1);
                }
            }
        }
    }
}

// ---------------------------------------------------------------------------
// Tensor-core causal flash attention (FA2-style, proven in R9/R11).
// ---------------------------------------------------------------------------
#define FS_QH 0
#define FS_QL 16384
#define FS_ST 32768
#define FS_STAGE 32768           // KH 8K | KL 8K | VH 8K | VL 8K
#define FS_TOTAL (FS_ST + 2 * FS_STAGE)   // 98304

__global__ __launch_bounds__(128, 2) void flash_mma_kernel()
{
    extern __shared__ __align__(1024) char fsm[];
    const uint32_t sb = smem_u32(fsm);
    const int qb = (TSEQ / 128 - 1) - blockIdx.x;   // long blocks first
    const int h = blockIdx.y, b = blockIdx.z;
    const int tid = threadIdx.x, warp = tid >> 5, lane = tid & 31;
    const size_t bh = (size_t)(b * NHEAD + h) * TSEQ * HD;

    const __nv_bfloat16* Qh = g_Qhi + bh + (size_t)qb * 128 * HD;
    const __nv_bfloat16* Ql = g_Qlo + bh + (size_t)qb * 128 * HD;
    const __nv_bfloat16* Kh = g_Khi + bh;
    const __nv_bfloat16* Kl = g_Klo + bh;
    const __nv_bfloat16* Vh = g_Vhi + bh;
    const __nv_bfloat16* Vl = g_Vlo + bh;

#pragma unroll
    for (int p = 0; p < 2; ++p) {
        const __nv_bfloat16* src = p ? Ql : Qh;
        const uint32_t base = sb + (p ? FS_QL : FS_QH);
#pragma unroll
        for (int i = 0; i < 8; ++i) {
            int idx = tid + i * 128;
            int row = idx >> 3, c = idx & 7;
            CPA16(base + row * 128 + ((c ^ (row & 7)) << 4), src + row * 64 + c * 8);
        }
    }

    auto load_tile = [&](int j, int s) {
        const uint32_t st = sb + FS_ST + (uint32_t)s * FS_STAGE;
        const __nv_bfloat16* srcs[4] = {
            Kh + (size_t)j * 64 * HD, Kl + (size_t)j * 64 * HD,
            Vh + (size_t)j * 64 * HD, Vl + (size_t)j * 64 * HD };
#pragma unroll
        for (int p = 0; p < 4; ++p) {
#pragma unroll
            for (int i = 0; i < 4; ++i) {
                int idx = tid + i * 128;
                int row = idx >> 3, c = idx & 7;
                CPA16(st + p * 8192 + row * 128 + ((c ^ (row & 7)) << 4),
                      srcs[p] + row * 64 + c * 8);
            }
        }
    };

    load_tile(0, 0);
    CPA_COMMIT();
    load_tile(1, 1);
    CPA_COMMIT();

    float O[2][8][4];
#pragma unroll
    for (int mf = 0; mf < 2; ++mf)
#pragma unroll
        for (int nf = 0; nf < 8; ++nf)
#pragma unroll
            for (int e = 0; e < 4; ++e) O[mf][nf][e] = 0.0f;
    float rm[2][2], rl[2][2];
#pragma unroll
    for (int mf = 0; mf < 2; ++mf)
#pragma unroll
        for (int hf = 0; hf < 2; ++hf) { rm[mf][hf] = -1e30f; rl[mf][hf] = 0.0f; }

    const int ntiles = 2 * qb + 2;
    CPA_WAIT1();

    for (int j = 0; j < ntiles; ++j) {
        const int s = j & 1;
        __syncthreads();
        const uint32_t st = sb + FS_ST + (uint32_t)s * FS_STAGE;

        float S[2][8][4];
#pragma unroll
        for (int mf = 0; mf < 2; ++mf)
#pragma unroll
            for (int nf = 0; nf < 8; ++nf)
#pragma unroll
                for (int e = 0; e < 4; ++e) S[mf][nf][e] = 0.0f;

#pragma unroll
        for (int ks = 0; ks < 4; ++ks) {
            uint32_t aQ[2][2][4];
#pragma unroll
            for (int p = 0; p < 2; ++p) {
#pragma unroll
                for (int mf = 0; mf < 2; ++mf) {
                    int row = warp * 32 + mf * 16 + ((lane >> 3) & 1) * 8 + (lane & 7);
                    int c = ks * 2 + ((lane >> 4) & 1);
                    LDSM4(aQ[p][mf], sb + (p ? FS_QL : FS_QH) + row * 128
                                     + ((c ^ (row & 7)) << 4));
                }
            }
            uint32_t bK[2][4][4];
#pragma unroll
            for (int p = 0; p < 2; ++p) {
#pragma unroll
                for (int kg = 0; kg < 4; ++kg) {
                    int row = kg * 16 + ((lane >> 4) & 1) * 8 + (lane & 7);
                    int c = ks * 2 + ((lane >> 3) & 1);
                    LDSM4(bK[p][kg], st + p * 8192 + row * 128
                                     + ((c ^ (row & 7)) << 4));
                }
            }
#pragma unroll
            for (int mf = 0; mf < 2; ++mf)
#pragma unroll
                for (int nf = 0; nf < 8; ++nf) {
                    const int kg = nf >> 1, o = (nf & 1) * 2;
                    MMA_BF16(S[mf][nf], aQ[0][mf], bK[0][kg][o], bK[0][kg][o + 1]);
                }
#pragma unroll
            for (int mf = 0; mf < 2; ++mf)
#pragma unroll
                for (int nf = 0; nf < 8; ++nf) {
                    const int kg = nf >> 1, o = (nf & 1) * 2;
                    MMA_BF16(S[mf][nf], aQ[1][mf], bK[0][kg][o], bK[0][kg][o + 1]);
                }
#pragma unroll
            for (int mf = 0; mf < 2; ++mf)
#pragma unroll
                for (int nf = 0; nf < 8; ++nf) {
                    const int kg = nf >> 1, o = (nf & 1) * 2;
                    MMA_BF16(S[mf][nf], aQ[0][mf], bK[1][kg][o], bK[1][kg][o + 1]);
                }
        }

        const bool maskT = (j >= 2 * qb);
#pragma unroll
        for (int mf = 0; mf < 2; ++mf)
#pragma unroll
            for (int nf = 0; nf < 8; ++nf)
#pragma unroll
                for (int e = 0; e < 4; ++e) {
                    float sv = S[mf][nf][e] * 0.125f;
                    if (maskT) {
                        const int key = j * 64 + nf * 8 + (lane & 3) * 2 + (e & 1);
                        const int rowg = qb * 128 + warp * 32 + mf * 16
                                       + (lane >> 2) + (e >> 1) * 8;
                        if (key > rowg) sv = -1e30f;
                    }
                    S[mf][nf][e] = sv;
                }

#pragma unroll
        for (int mf = 0; mf < 2; ++mf) {
#pragma unroll
            for (int hf = 0; hf < 2; ++hf) {
                float mx = -1e30f;
#pragma unroll
                for (int nf = 0; nf < 8; ++nf)
                    mx = fmaxf(mx, fmaxf(S[mf][nf][hf * 2], S[mf][nf][hf * 2 + 1]));
                mx = fmaxf(mx, __shfl_xor_sync(0xFFFFFFFFu, mx, 1));
                mx = fmaxf(mx, __shfl_xor_sync(0xFFFFFFFFu, mx, 2));
                const float mnew = fmaxf(rm[mf][hf], mx);
                const float corr = __expf(rm[mf][hf] - mnew);
                rm[mf][hf] = mnew;
                float ps = 0.0f;
#pragma unroll
                for (int nf = 0; nf < 8; ++nf) {
                    float p0 = __expf(S[mf][nf][hf * 2 + 0] - mnew);
                    float p1 = __expf(S[mf][nf][hf * 2 + 1] - mnew);
                    S[mf][nf][hf * 2 + 0] = p0;
                    S[mf][nf][hf * 2 + 1] = p1;
                    ps += p0 + p1;
                }
                ps += __shfl_xor_sync(0xFFFFFFFFu, ps, 1);
                ps += __shfl_xor_sync(0xFFFFFFFFu, ps, 2);
                rl[mf][hf] = rl[mf][hf] * corr + ps;
#pragma unroll
                for (int nf = 0; nf < 8; ++nf) {
                    O[mf][nf][hf * 2 + 0] *= corr;
                    O[mf][nf][hf * 2 + 1] *= corr;
                }
            }
        }

#pragma unroll
        for (int kc = 0; kc < 4; ++kc) {
            uint32_t aP[2][2][4];
#pragma unroll
            for (int mf = 0; mf < 2; ++mf) {
#pragma unroll
                for (int e = 0; e < 2; ++e) {
                    const int nf = 2 * kc + e;
#pragma unroll
                    for (int hf = 0; hf < 2; ++hf) {
                        float x = S[mf][nf][hf * 2 + 0];
                        float y = S[mf][nf][hf * 2 + 1];
                        __nv_bfloat16 hx = __float2bfloat16_rn(x);
                        __nv_bfloat16 hy = __float2bfloat16_rn(y);
                        __nv_bfloat162 hv(hx, hy);
                        __nv_bfloat162 lv(
                            __float2bfloat16_rn(x - __bfloat162float(hx)),
                            __float2bfloat16_rn(y - __bfloat162float(hy)));
                        aP[0][mf][e * 2 + hf] = *(uint32_t*)&hv;
                        aP[1][mf][e * 2 + hf] = *(uint32_t*)&lv;
                    }
                }
            }
            uint32_t bV[2][4][4];
#pragma unroll
            for (int p = 0; p < 2; ++p) {
#pragma unroll
                for (int dg = 0; dg < 4; ++dg) {
                    int row = kc * 16 + ((lane >> 3) & 1) * 8 + (lane & 7);
                    int c = dg * 2 + ((lane >> 4) & 1);
                    LDSM4T(bV[p][dg], st + (2 + p) * 8192 + row * 128
                                      + ((c ^ (row & 7)) << 4));
                }
            }
#pragma unroll
            for (int mf = 0; mf < 2; ++mf)
#pragma unroll
                for (int nf = 0; nf < 8; ++nf) {
                    const int dg = nf >> 1, o = (nf & 1) * 2;
                    MMA_BF16(O[mf][nf], aP[0][mf], bV[0][dg][o], bV[0][dg][o + 1]);
                }
#pragma unroll
            for (int mf = 0; mf < 2; ++mf)
#pragma unroll
                for (int nf = 0; nf < 8; ++nf) {
                    const int dg = nf >> 1, o = (nf & 1) * 2;
                    MMA_BF16(O[mf][nf], aP[1][mf], bV[0][dg][o], bV[0][dg][o + 1]);
                }
#pragma unroll
            for (int mf = 0; mf < 2; ++mf)
#pragma unroll
                for (int nf = 0; nf < 8; ++nf) {
                    const int dg = nf >> 1, o = (nf & 1) * 2;
                    MMA_BF16(O[mf][nf], aP[0][mf], bV[1][dg][o], bV[1][dg][o + 1]);
                }
        }

        __syncthreads();
        if (j + 2 < ntiles) { load_tile(j + 2, s); CPA_COMMIT(); }
        if (j + 1 < ntiles) {
            if (j + 2 < ntiles) { CPA_WAIT1(); } else { CPA_WAIT0(); }
        }
    }

#pragma unroll
    for (int mf = 0; mf < 2; ++mf) {
#pragma unroll
        for (int hf = 0; hf < 2; ++hf) {
            const float inv = 1.0f / rl[mf][hf];
            const int row = qb * 128 + warp * 32 + mf * 16 + (lane >> 2) + hf * 8;
            const size_t ob = ((size_t)(b * TSEQ) + row) * CDIM + h * 64;
#pragma unroll
            for (int nf = 0; nf < 8; ++nf) {
                const int d = nf * 8 + (lane & 3) * 2;
                float v0 = O[mf][nf][hf * 2 + 0] * inv;
                float v1 = O[mf][nf][hf * 2 + 1] * inv;
                __nv_bfloat16 h0 = __float2bfloat16_rn(v0);
                __nv_bfloat16 h1 = __float2bfloat16_rn(v1);
                __nv_bfloat162 hv(h0, h1);
                __nv_bfloat162 lv(
                    __float2bfloat16_rn(v0 - __bfloat162float(h0)),
                    __float2bfloat16_rn(v1 - __bfloat162float(h1)));
                *(__nv_bfloat162*)(g_Ohi + ob + d) = hv;
                *(__nv_bfloat162*)(g_Olo + ob + d) = lv;
            }
        }
    }
}

// ---------------------------------------------------------------------------
// Launch
// ---------------------------------------------------------------------------
extern "C" void kernel_launch(void* const* d_in, const int* in_sizes, int n_in,
                              void* d_out, int out_size)
{
    const float* hidden   = (const float*)d_in[0];
    const float* W_attn   = (const float*)d_in[1];
    const float* b_attn   = (const float*)d_in[2];
    const float* W_proj   = (const float*)d_in[3];
    const float* b_proj   = (const float*)d_in[4];
    const float* kv_scale = (const float*)d_in[5];
    const float* kv_zp    = (const float*)d_in[6];
    float* out = (float*)d_out;

    cudaFuncSetAttribute(mma_gemm_kernel<0>,
                         cudaFuncAttributeMaxDynamicSharedMemorySize, SMEM_DYN);
    cudaFuncSetAttribute(mma_gemm_kernel<1>,
                         cudaFuncAttributeMaxDynamicSharedMemorySize, SMEM_DYN);
    cudaFuncSetAttribute(flash_mma_kernel,
                         cudaFuncAttributeMaxDynamicSharedMemorySize, FS_TOTAL);

    __nv_bfloat16 *Xhi, *Xlo, *WaThi, *WaTlo, *WpThi, *WpTlo, *Ohi, *Olo;
    cudaGetSymbolAddress((void**)&Xhi, g_Xhi);
    cudaGetSymbolAddress((void**)&Xlo, g_Xlo);
    cudaGetSymbolAddress((void**)&WaThi, g_WaThi);
    cudaGetSymbolAddress((void**)&WaTlo, g_WaTlo);
    cudaGetSymbolAddress((void**)&WpThi, g_WpThi);
    cudaGetSymbolAddress((void**)&WpTlo, g_WpTlo);
    cudaGetSymbolAddress((void**)&Ohi, g_Ohi);
    cudaGetSymbolAddress((void**)&Olo, g_Olo);

    // Prep
    split_kernel<<<1024, 256>>>(hidden, Xhi, Xlo, MROWS * CDIM / 4);
    transpose_split_kernel<<<dim3(NQKV / 32, CDIM / 32), 256>>>(W_attn, WaThi, WaTlo, CDIM, NQKV);
    transpose_split_kernel<<<dim3(CDIM / 32, CDIM / 32), 256>>>(W_proj, WpThi, WpTlo, CDIM, CDIM);

    // QKV GEMM + bias + fake-quant + bf16 hi/lo scatter
    mma_gemm_kernel<0><<<dim3(NQKV / 128, MROWS / 128), 256, SMEM_DYN>>>(
        Xhi, Xlo, WaThi, WaTlo, b_attn, NQKV, kv_scale, kv_zp, nullptr);

    // Tensor-core causal flash attention
    flash_mma_kernel<<<dim3(TSEQ / 128, NHEAD, BATCH), 128, FS_TOTAL>>>();

    // Output projection
    mma_gemm_kernel<1><<<dim3(CDIM / 128, MROWS / 128), 256, SMEM_DYN>>>(
        Ohi, Olo, WpThi, WpTlo, b_proj, CDIM, nullptr, nullptr, out);
}

// round 14
// speedup vs baseline: 1.1387x; 1.0246x over previous
#include <cuda_runtime.h>
#include <cuda_fp16.h>
#include <math.h>
#include <stdint.h>

#define BATCH 2
#define TSEQ  2048
#define CDIM  1024
#define NHEAD 16
#define HD    64
#define MROWS (BATCH * TSEQ)     // 4096
#define NQKV  (3 * CDIM)         // 3072
#define KDIM  1024

// ---------------------------------------------------------------------------
// Scratch (allocation-free: __device__ globals). Q/K/V as fp16 hi/lo planes.
// ---------------------------------------------------------------------------
#define QKV_ELEMS (BATCH * NHEAD * TSEQ * HD)
__device__ __align__(256) __half g_Qhi[QKV_ELEMS];
__device__ __align__(256) __half g_Qlo[QKV_ELEMS];
__device__ __align__(256) __half g_Khi[QKV_ELEMS];
__device__ __align__(256) __half g_Klo[QKV_ELEMS];
__device__ __align__(256) __half g_Vhi[QKV_ELEMS];
__device__ __align__(256) __half g_Vlo[QKV_ELEMS];
__device__ __align__(256) __half g_Xhi[MROWS * CDIM];
__device__ __align__(256) __half g_Xlo[MROWS * CDIM];
__device__ __align__(256) __half g_WaThi[NQKV * CDIM];
__device__ __align__(256) __half g_WaTlo[NQKV * CDIM];
__device__ __align__(256) __half g_WpThi[CDIM * CDIM];
__device__ __align__(256) __half g_WpTlo[CDIM * CDIM];
__device__ __align__(256) __half g_Ohi[MROWS * CDIM];
__device__ __align__(256) __half g_Olo[MROWS * CDIM];

// ---------------------------------------------------------------------------
// PTX helpers (arch-generic only: cp.async, ldmatrix, mma.sync)
// ---------------------------------------------------------------------------
__device__ __forceinline__ uint32_t smem_u32(const void* p) {
    uint32_t a;
    asm("{ .reg .u64 t; cvta.to.shared.u64 t, %1; cvt.u32.u64 %0, t; }"
        : "=r"(a) : "l"(p));
    return a;
}

#define CPA16(dst, src) \
    asm volatile("cp.async.cg.shared.global [%0], [%1], 16;" :: "r"(dst), "l"(src))
#define CPA_COMMIT() asm volatile("cp.async.commit_group;" ::: "memory")
#define CPA_WAIT1()  asm volatile("cp.async.wait_group 1;" ::: "memory")
#define CPA_WAIT0()  asm volatile("cp.async.wait_group 0;" ::: "memory")

#define LDSM4(r, addr)                                                        \
    asm volatile("ldmatrix.sync.aligned.m8n8.x4.shared.b16 {%0,%1,%2,%3}, [%4];" \
        : "=r"((r)[0]), "=r"((r)[1]), "=r"((r)[2]), "=r"((r)[3]) : "r"(addr))

#define LDSM4T(r, addr)                                                       \
    asm volatile("ldmatrix.sync.aligned.m8n8.x4.trans.shared.b16 {%0,%1,%2,%3}, [%4];" \
        : "=r"((r)[0]), "=r"((r)[1]), "=r"((r)[2]), "=r"((r)[3]) : "r"(addr))

#define MMA_F16(d, a, b0v, b1v)                                               \
    asm volatile("mma.sync.aligned.m16n8k16.row.col.f32.f16.f16.f32 "         \
        "{%0,%1,%2,%3}, {%4,%5,%6,%7}, {%8,%9}, {%0,%1,%2,%3};"               \
        : "+f"((d)[0]), "+f"((d)[1]), "+f"((d)[2]), "+f"((d)[3])              \
        : "r"((a)[0]), "r"((a)[1]), "r"((a)[2]), "r"((a)[3]),                 \
          "r"(b0v), "r"(b1v))

__device__ __forceinline__ uint32_t pack_h2(__half x, __half y) {
    __half2 h = __halves2half2(x, y);
    return *(uint32_t*)&h;
}

// ---------------------------------------------------------------------------
// Prep kernels: fp16 hi/lo split (+ transpose for weights)
// ---------------------------------------------------------------------------
__global__ void split_kernel(const float* __restrict__ in,
                             __half* __restrict__ hi,
                             __half* __restrict__ lo, int n4) {
    for (int i = blockIdx.x * blockDim.x + threadIdx.x; i < n4;
         i += gridDim.x * blockDim.x) {
        float4 v = ((const float4*)in)[i];
        __half hx = __float2half_rn(v.x);
        __half hy = __float2half_rn(v.y);
        __half hz = __float2half_rn(v.z);
        __half hw = __float2half_rn(v.w);
        __half lx = __float2half_rn(v.x - __half2float(hx));
        __half ly = __float2half_rn(v.y - __half2float(hy));
        __half lz = __float2half_rn(v.z - __half2float(hz));
        __half lw = __float2half_rn(v.w - __half2float(hw));
        ((__half2*)hi)[2 * i + 0] = __halves2half2(hx, hy);
        ((__half2*)hi)[2 * i + 1] = __halves2half2(hz, hw);
        ((__half2*)lo)[2 * i + 0] = __halves2half2(lx, ly);
        ((__half2*)lo)[2 * i + 1] = __halves2half2(lz, lw);
    }
}

__global__ void transpose_split_kernel(const float* __restrict__ in,
                                       __half* __restrict__ ohi,
                                       __half* __restrict__ olo,
                                       int R, int C) {
    __shared__ float t[32][33];
    const int c0 = blockIdx.x * 32, r0 = blockIdx.y * 32;
    const int x = threadIdx.x & 31, y0 = threadIdx.x >> 5;
#pragma unroll
    for (int i = 0; i < 4; ++i) {
        int y = y0 + i * 8;
        t[y][x] = in[(size_t)(r0 + y) * C + c0 + x];
    }
    __syncthreads();
#pragma unroll
    for (int i = 0; i < 4; ++i) {
        int yy = y0 + i * 8;
        float v = t[x][yy];
        __half hi = __float2half_rn(v);
        __half lo = __float2half_rn(v - __half2float(hi));
        size_t o = (size_t)(c0 + yy) * R + r0 + x;
        ohi[o] = hi;
        olo[o] = lo;
    }
}

// ---------------------------------------------------------------------------
// mma.sync fp16 split-3 GEMM. CTA 128x128, 8 warps, BK=32.
// R13: 3-stage SMEM (96KB) + SINGLE barrier per k-tile + 2 CTAs/SM.
// Load distance 2: slot (kt+2)%3 was last read at kt-1; the barrier at the
// top of iteration kt orders all warps past those reads before any warp's
// end-of-iteration load touches the slot.
// MODE 0: fake-quant + scatter to fp16 hi/lo Q/K/V planes.
// MODE 1: epilogue writes Cout row-major fp32.
// ---------------------------------------------------------------------------
#define STAGE_BYTES 32768        // Ahi 8K | Alo 8K | Bhi 8K | Blo 8K
#define NSTAGES 3
#define SMEM_DYN (STAGE_BYTES * NSTAGES)   // 98304

template <int MODE>
__global__ __launch_bounds__(256, 2) void mma_gemm_kernel(
    const __half* __restrict__ Ahi, const __half* __restrict__ Alo,
    const __half* __restrict__ Bhi, const __half* __restrict__ Blo,
    const float* __restrict__ bias, int Ncols,
    const float* __restrict__ scale_p, const float* __restrict__ zp_p,
    float* __restrict__ Cout)
{
    extern __shared__ __align__(1024) char smem[];
    const uint32_t sb = smem_u32(smem);
    const int tid = threadIdx.x;
    const int wid = tid >> 5, lane = tid & 31;
    const int m0 = blockIdx.y * 128, n0 = blockIdx.x * 128;
    const int wm = wid & 3;
    const int wn = wid >> 2;

    float acc[2][8][4];
#pragma unroll
    for (int i = 0; i < 2; ++i)
#pragma unroll
        for (int j = 0; j < 8; ++j)
#pragma unroll
            for (int k = 0; k < 4; ++k) acc[i][j][k] = 0.0f;

    auto load_stage = [&](int kt, int s) {
        const uint32_t st = sb + (uint32_t)s * STAGE_BYTES;
        const int kb = kt * 32;
#pragma unroll
        for (int p = 0; p < 2; ++p) {
            const __half* src = p ? Alo : Ahi;
            const uint32_t po = st + p * 8192;
#pragma unroll
            for (int i = 0; i < 2; ++i) {
                int idx = tid + i * 256;
                int row = idx >> 2, c = idx & 3;
                uint32_t dst = po + row * 64 + ((c ^ ((row >> 1) & 3)) << 4);
                CPA16(dst, src + (size_t)(m0 + row) * KDIM + kb + c * 8);
            }
        }
#pragma unroll
        for (int p = 0; p < 2; ++p) {
            const __half* src = p ? Blo : Bhi;
            const uint32_t po = st + 16384 + p * 8192;
#pragma unroll
            for (int i = 0; i < 2; ++i) {
                int idx = tid + i * 256;
                int row = idx >> 2, c = idx & 3;
                uint32_t dst = po + row * 64 + ((c ^ ((row >> 1) & 3)) << 4);
                CPA16(dst, src + (size_t)(n0 + row) * KDIM + kb + c * 8);
            }
        }
        CPA_COMMIT();
    };

    load_stage(0, 0);
    load_stage(1, 1);

    const int NK = KDIM / 32;   // 32
    for (int kt = 0; kt < NK; ++kt) {
        const int s = kt % NSTAGES;
        if (kt + 1 < NK) { CPA_WAIT1(); } else { CPA_WAIT0(); }
        __syncthreads();                       // single barrier per k-tile

        const uint32_t st = sb + (uint32_t)s * STAGE_BYTES;
#pragma unroll
        for (int kh = 0; kh < 2; ++kh) {
            const int cbase = kh * 2;
            uint32_t a[2][2][4];
#pragma unroll
            for (int p = 0; p < 2; ++p) {
#pragma unroll
                for (int mf = 0; mf < 2; ++mf) {
                    int row = wm * 32 + mf * 16 + ((lane >> 3) & 1) * 8 + (lane & 7);
                    int c = cbase + ((lane >> 4) & 1);
                    uint32_t addr = st + p * 8192 + row * 64
                                  + ((c ^ ((row >> 1) & 3)) << 4);
                    LDSM4(a[p][mf], addr);
                }
            }
            uint32_t b[2][16];
#pragma unroll
            for (int p = 0; p < 2; ++p) {
#pragma unroll
                for (int nq = 0; nq < 4; ++nq) {
                    int row = wn * 64 + nq * 16 + ((lane >> 4) & 1) * 8 + (lane & 7);
                    int c = cbase + ((lane >> 3) & 1);
                    uint32_t addr = st + 16384 + p * 8192 + row * 64
                                  + ((c ^ ((row >> 1) & 3)) << 4);
                    LDSM4(&b[p][nq * 4], addr);
                }
            }
#pragma unroll
            for (int mf = 0; mf < 2; ++mf)
#pragma unroll
                for (int nf = 0; nf < 8; ++nf) {
                    const int bi = (nf >> 1) * 4 + (nf & 1) * 2;
                    MMA_F16(acc[mf][nf], a[0][mf], b[0][bi], b[0][bi + 1]);
                }
#pragma unroll
            for (int mf = 0; mf < 2; ++mf)
#pragma unroll
                for (int nf = 0; nf < 8; ++nf) {
                    const int bi = (nf >> 1) * 4 + (nf & 1) * 2;
                    MMA_F16(acc[mf][nf], a[1][mf], b[0][bi], b[0][bi + 1]);
                }
#pragma unroll
            for (int mf = 0; mf < 2; ++mf)
#pragma unroll
                for (int nf = 0; nf < 8; ++nf) {
                    const int bi = (nf >> 1) * 4 + (nf & 1) * 2;
                    MMA_F16(acc[mf][nf], a[0][mf], b[1][bi], b[1][bi + 1]);
                }
        }

        if (kt + 2 < NK) load_stage(kt + 2, (kt + 2) % NSTAGES);
    }

    float scl = 1.0f, zp = 0.0f;
    if (MODE == 0) { scl = *scale_p; zp = *zp_p; }

#pragma unroll
    for (int mf = 0; mf < 2; ++mf) {
#pragma unroll
        for (int nf = 0; nf < 8; ++nf) {
            const int n = n0 + wn * 64 + nf * 8 + (lane & 3) * 2;
            const float2 bv = *(const float2*)(bias + n);
#pragma unroll
            for (int half = 0; half < 2; ++half) {
                const int m = m0 + wm * 32 + mf * 16 + (lane >> 2) + half * 8;
                float v0 = acc[mf][nf][half * 2 + 0] + bv.x;
                float v1 = acc[mf][nf][half * 2 + 1] + bv.y;
                if (MODE == 0) {
                    const int bb = m >> 11;
                    const int t = m & 2047;
                    const int which = n >> 10;
                    const int cI = n & 1023;
                    const int h = cI >> 6, d = cI & 63;
                    const size_t idx = (((size_t)(bb * NHEAD + h) * TSEQ + t) * HD + d);
                    if (which != 0) {   // fake-quant K/V
                        float q0 = fminf(fmaxf(rintf(v0 / scl + zp), 0.0f), 255.0f);
                        float q1 = fminf(fmaxf(rintf(v1 / scl + zp), 0.0f), 255.0f);
                        v0 = (q0 - zp) * scl;
                        v1 = (q1 - zp) * scl;
                    }
                    __half h0 = __float2half_rn(v0);
                    __half h1 = __float2half_rn(v1);
                    __half l0 = __float2half_rn(v0 - __half2float(h0));
                    __half l1 = __float2half_rn(v1 - __half2float(h1));
                    __half2 hv = __halves2half2(h0, h1);
                    __half2 lv = __halves2half2(l0, l1);
                    if (which == 0) {
                        *(__half2*)(g_Qhi + idx) = hv;
                        *(__half2*)(g_Qlo + idx) = lv;
                    } else if (which == 1) {
                        *(__half2*)(g_Khi + idx) = hv;
                        *(__half2*)(g_Klo + idx) = lv;
                    } else {
                        *(__half2*)(g_Vhi + idx) = hv;
                        *(__half2*)(g_Vlo + idx) = lv;
                    }
                } else {
                    *(float2*)(Cout + (size_t)m * Ncols + n) = make_float2(v0, v1);
                }
            }
        }
    }
}

// ---------------------------------------------------------------------------
// Tensor-core causal flash attention (FA2-style), fp16 split-3.
// ---------------------------------------------------------------------------
#define FS_QH 0
#define FS_QL 16384
#define FS_ST 32768
#define FS_STAGE 32768           // KH 8K | KL 8K | VH 8K | VL 8K
#define FS_TOTAL (FS_ST + 2 * FS_STAGE)   // 98304

__global__ __launch_bounds__(128, 2) void flash_mma_kernel()
{
    extern __shared__ __align__(1024) char fsm[];
    const uint32_t sb = smem_u32(fsm);
    const int qb = (TSEQ / 128 - 1) - blockIdx.x;   // long blocks first
    const int h = blockIdx.y, b = blockIdx.z;
    const int tid = threadIdx.x, warp = tid >> 5, lane = tid & 31;
    const size_t bh = (size_t)(b * NHEAD + h) * TSEQ * HD;

    const __half* Qh = g_Qhi + bh + (size_t)qb * 128 * HD;
    const __half* Ql = g_Qlo + bh + (size_t)qb * 128 * HD;
    const __half* Kh = g_Khi + bh;
    const __half* Kl = g_Klo + bh;
    const __half* Vh = g_Vhi + bh;
    const __half* Vl = g_Vlo + bh;

#pragma unroll
    for (int p = 0; p < 2; ++p) {
        const __half* src = p ? Ql : Qh;
        const uint32_t base = sb + (p ? FS_QL : FS_QH);
#pragma unroll
        for (int i = 0; i < 8; ++i) {
            int idx = tid + i * 128;
            int row = idx >> 3, c = idx & 7;
            CPA16(base + row * 128 + ((c ^ (row & 7)) << 4), src + row * 64 + c * 8);
        }
    }

    auto load_tile = [&](int j, int s) {
        const uint32_t st = sb + FS_ST + (uint32_t)s * FS_STAGE;
        const __half* srcs[4] = {
            Kh + (size_t)j * 64 * HD, Kl + (size_t)j * 64 * HD,
            Vh + (size_t)j * 64 * HD, Vl + (size_t)j * 64 * HD };
#pragma unroll
        for (int p = 0; p < 4; ++p) {
#pragma unroll
            for (int i = 0; i < 4; ++i) {
                int idx = tid + i * 128;
                int row = idx >> 3, c = idx & 7;
                CPA16(st + p * 8192 + row * 128 + ((c ^ (row & 7)) << 4),
                      srcs[p] + row * 64 + c * 8);
            }
        }
    };

    load_tile(0, 0);
    CPA_COMMIT();
    load_tile(1, 1);
    CPA_COMMIT();

    float O[2][8][4];
#pragma unroll
    for (int mf = 0; mf < 2; ++mf)
#pragma unroll
        for (int nf = 0; nf < 8; ++nf)
#pragma unroll
            for (int e = 0; e < 4; ++e) O[mf][nf][e] = 0.0f;
    float rm[2][2], rl[2][2];
#pragma unroll
    for (int mf = 0; mf < 2; ++mf)
#pragma unroll
        for (int hf = 0; hf < 2; ++hf) { rm[mf][hf] = -1e30f; rl[mf][hf] = 0.0f; }

    const int ntiles = 2 * qb + 2;
    CPA_WAIT1();

    for (int j = 0; j < ntiles; ++j) {
        const int s = j & 1;
        __syncthreads();
        const uint32_t st = sb + FS_ST + (uint32_t)s * FS_STAGE;

        float S[2][8][4];
#pragma unroll
        for (int mf = 0; mf < 2; ++mf)
#pragma unroll
            for (int nf = 0; nf < 8; ++nf)
#pragma unroll
                for (int e = 0; e < 4; ++e) S[mf][nf][e] = 0.0f;

#pragma unroll
        for (int ks = 0; ks < 4; ++ks) {
            uint32_t aQ[2][2][4];
#pragma unroll
            for (int p = 0; p < 2; ++p) {
#pragma unroll
                for (int mf = 0; mf < 2; ++mf) {
                    int row = warp * 32 + mf * 16 + ((lane >> 3) & 1) * 8 + (lane & 7);
                    int c = ks * 2 + ((lane >> 4) & 1);
                    LDSM4(aQ[p][mf], sb + (p ? FS_QL : FS_QH) + row * 128
                                     + ((c ^ (row & 7)) << 4));
                }
            }
            uint32_t bK[2][4][4];
#pragma unroll
            for (int p = 0; p < 2; ++p) {
#pragma unroll
                for (int kg = 0; kg < 4; ++kg) {
                    int row = kg * 16 + ((lane >> 4) & 1) * 8 + (lane & 7);
                    int c = ks * 2 + ((lane >> 3) & 1);
                    LDSM4(bK[p][kg], st + p * 8192 + row * 128
                                     + ((c ^ (row & 7)) << 4));
                }
            }
#pragma unroll
            for (int mf = 0; mf < 2; ++mf)
#pragma unroll
                for (int nf = 0; nf < 8; ++nf) {
                    const int kg = nf >> 1, o = (nf & 1) * 2;
                    MMA_F16(S[mf][nf], aQ[0][mf], bK[0][kg][o], bK[0][kg][o + 1]);
                }
#pragma unroll
            for (int mf = 0; mf < 2; ++mf)
#pragma unroll
                for (int nf = 0; nf < 8; ++nf) {
                    const int kg = nf >> 1, o = (nf & 1) * 2;
                    MMA_F16(S[mf][nf], aQ[1][mf], bK[0][kg][o], bK[0][kg][o + 1]);
                }
#pragma unroll
            for (int mf = 0; mf < 2; ++mf)
#pragma unroll
                for (int nf = 0; nf < 8; ++nf) {
                    const int kg = nf >> 1, o = (nf & 1) * 2;
                    MMA_F16(S[mf][nf], aQ[0][mf], bK[1][kg][o], bK[1][kg][o + 1]);
                }
        }

        const bool maskT = (j >= 2 * qb);
#pragma unroll
        for (int mf = 0; mf < 2; ++mf)
#pragma unroll
            for (int nf = 0; nf < 8; ++nf)
#pragma unroll
                for (int e = 0; e < 4; ++e) {
                    float sv = S[mf][nf][e] * 0.125f;
                    if (maskT) {
                        const int key = j * 64 + nf * 8 + (lane & 3) * 2 + (e & 1);
                        const int rowg = qb * 128 + warp * 32 + mf * 16
                                       + (lane >> 2) + (e >> 1) * 8;
                        if (key > rowg) sv = -1e30f;
                    }
                    S[mf][nf][e] = sv;
                }

#pragma unroll
        for (int mf = 0; mf < 2; ++mf) {
#pragma unroll
            for (int hf = 0; hf < 2; ++hf) {
                float mx = -1e30f;
#pragma unroll
                for (int nf = 0; nf < 8; ++nf)
                    mx = fmaxf(mx, fmaxf(S[mf][nf][hf * 2], S[mf][nf][hf * 2 + 1]));
                mx = fmaxf(mx, __shfl_xor_sync(0xFFFFFFFFu, mx, 1));
                mx = fmaxf(mx, __shfl_xor_sync(0xFFFFFFFFu, mx, 2));
                const float mnew = fmaxf(rm[mf][hf], mx);
                const float corr = __expf(rm[mf][hf] - mnew);
                rm[mf][hf] = mnew;
                float ps = 0.0f;
#pragma unroll
                for (int nf = 0; nf < 8; ++nf) {
                    float p0 = __expf(S[mf][nf][hf * 2 + 0] - mnew);
                    float p1 = __expf(S[mf][nf][hf * 2 + 1] - mnew);
                    S[mf][nf][hf * 2 + 0] = p0;
                    S[mf][nf][hf * 2 + 1] = p1;
                    ps += p0 + p1;
                }
                ps += __shfl_xor_sync(0xFFFFFFFFu, ps, 1);
                ps += __shfl_xor_sync(0xFFFFFFFFu, ps, 2);
                rl[mf][hf] = rl[mf][hf] * corr + ps;
#pragma unroll
                for (int nf = 0; nf < 8; ++nf) {
                    O[mf][nf][hf * 2 + 0] *= corr;
                    O[mf][nf][hf * 2 + 1] *= corr;
                }
            }
        }

#pragma unroll
        for (int kc = 0; kc < 4; ++kc) {
            uint32_t aP[2][2][4];
#pragma unroll
            for (int mf = 0; mf < 2; ++mf) {
#pragma unroll
                for (int e = 0; e < 2; ++e) {
                    const int nf = 2 * kc + e;
#pragma unroll
                    for (int hf = 0; hf < 2; ++hf) {
                        float x = S[mf][nf][hf * 2 + 0];
                        float y = S[mf][nf][hf * 2 + 1];
                        __half hx = __float2half_rn(x);
                        __half hy = __float2half_rn(y);
                        aP[0][mf][e * 2 + hf] = pack_h2(hx, hy);
                        aP[1][mf][e * 2 + hf] = pack_h2(
                            __float2half_rn(x - __half2float(hx)),
                            __float2half_rn(y - __half2float(hy)));
                    }
                }
            }
            uint32_t bV[2][4][4];
#pragma unroll
            for (int p = 0; p < 2; ++p) {
#pragma unroll
                for (int dg = 0; dg < 4; ++dg) {
                    int row = kc * 16 + ((lane >> 3) & 1) * 8 + (lane & 7);
                    int c = dg * 2 + ((lane >> 4) & 1);
                    LDSM4T(bV[p][dg], st + (2 + p) * 8192 + row * 128
                                      + ((c ^ (row & 7)) << 4));
                }
            }
#pragma unroll
            for (int mf = 0; mf < 2; ++mf)
#pragma unroll
                for (int nf = 0; nf < 8; ++nf) {
                    const int dg = nf >> 1, o = (nf & 1) * 2;
                    MMA_F16(O[mf][nf], aP[0][mf], bV[0][dg][o], bV[0][dg][o + 1]);
                }
#pragma unroll
            for (int mf = 0; mf < 2; ++mf)
#pragma unroll
                for (int nf = 0; nf < 8; ++nf) {
                    const int dg = nf >> 1, o = (nf & 1) * 2;
                    MMA_F16(O[mf][nf], aP[1][mf], bV[0][dg][o], bV[0][dg][o + 1]);
                }
#pragma unroll
            for (int mf = 0; mf < 2; ++mf)
#pragma unroll
                for (int nf = 0; nf < 8; ++nf) {
                    const int dg = nf >> 1, o = (nf & 1) * 2;
                    MMA_F16(O[mf][nf], aP[0][mf], bV[1][dg][o], bV[1][dg][o + 1]);
                }
        }

        __syncthreads();
        if (j + 2 < ntiles) { load_tile(j + 2, s); CPA_COMMIT(); }
        if (j + 1 < ntiles) {
            if (j + 2 < ntiles) { CPA_WAIT1(); } else { CPA_WAIT0(); }
        }
    }

#pragma unroll
    for (int mf = 0; mf < 2; ++mf) {
#pragma unroll
        for (int hf = 0; hf < 2; ++hf) {
            const float inv = 1.0f / rl[mf][hf];
            const int row = qb * 128 + warp * 32 + mf * 16 + (lane >> 2) + hf * 8;
            const size_t ob = ((size_t)(b * TSEQ) + row) * CDIM + h * 64;
#pragma unroll
            for (int nf = 0; nf < 8; ++nf) {
                const int d = nf * 8 + (lane & 3) * 2;
                float v0 = O[mf][nf][hf * 2 + 0] * inv;
                float v1 = O[mf][nf][hf * 2 + 1] * inv;
                __half h0 = __float2half_rn(v0);
                __half h1 = __float2half_rn(v1);
                *(__half2*)(g_Ohi + ob + d) = __halves2half2(h0, h1);
                *(__half2*)(g_Olo + ob + d) = __halves2half2(
                    __float2half_rn(v0 - __half2float(h0)),
                    __float2half_rn(v1 - __half2float(h1)));
            }
        }
    }
}

// ---------------------------------------------------------------------------
// Launch
// ---------------------------------------------------------------------------
extern "C" void kernel_launch(void* const* d_in, const int* in_sizes, int n_in,
                              void* d_out, int out_size)
{
    const float* hidden   = (const float*)d_in[0];
    const float* W_attn   = (const float*)d_in[1];
    const float* b_attn   = (const float*)d_in[2];
    const float* W_proj   = (const float*)d_in[3];
    const float* b_proj   = (const float*)d_in[4];
    const float* kv_scale = (const float*)d_in[5];
    const float* kv_zp    = (const float*)d_in[6];
    float* out = (float*)d_out;

    cudaFuncSetAttribute(mma_gemm_kernel<0>,
                         cudaFuncAttributeMaxDynamicSharedMemorySize, SMEM_DYN);
    cudaFuncSetAttribute(mma_gemm_kernel<1>,
                         cudaFuncAttributeMaxDynamicSharedMemorySize, SMEM_DYN);
    cudaFuncSetAttribute(flash_mma_kernel,
                         cudaFuncAttributeMaxDynamicSharedMemorySize, FS_TOTAL);

    __half *Xhi, *Xlo, *WaThi, *WaTlo, *WpThi, *WpTlo, *Ohi, *Olo;
    cudaGetSymbolAddress((void**)&Xhi, g_Xhi);
    cudaGetSymbolAddress((void**)&Xlo, g_Xlo);
    cudaGetSymbolAddress((void**)&WaThi, g_WaThi);
    cudaGetSymbolAddress((void**)&WaTlo, g_WaTlo);
    cudaGetSymbolAddress((void**)&WpThi, g_WpThi);
    cudaGetSymbolAddress((void**)&WpTlo, g_WpTlo);
    cudaGetSymbolAddress((void**)&Ohi, g_Ohi);
    cudaGetSymbolAddress((void**)&Olo, g_Olo);

    // Prep
    split_kernel<<<1024, 256>>>(hidden, Xhi, Xlo, MROWS * CDIM / 4);
    transpose_split_kernel<<<dim3(NQKV / 32, CDIM / 32), 256>>>(W_attn, WaThi, WaTlo, CDIM, NQKV);
    transpose_split_kernel<<<dim3(CDIM / 32, CDIM / 32), 256>>>(W_proj, WpThi, WpTlo, CDIM, CDIM);

    // QKV GEMM + bias + fake-quant + fp16 hi/lo scatter
    mma_gemm_kernel<0><<<dim3(NQKV / 128, MROWS / 128), 256, SMEM_DYN>>>(
        Xhi, Xlo, WaThi, WaTlo, b_attn, NQKV, kv_scale, kv_zp, nullptr);

    // Tensor-core causal flash attention
    flash_mma_kernel<<<dim3(TSEQ / 128, NHEAD, BATCH), 128, FS_TOTAL>>>();

    // Output projection
    mma_gemm_kernel<1><<<dim3(CDIM / 128, MROWS / 128), 256, SMEM_DYN>>>(
        Ohi, Olo, WpThi, WpTlo, b_proj, CDIM, nullptr, nullptr, out);
}

// round 15
// speedup vs baseline: 1.2847x; 1.1282x over previous
#include <cuda_runtime.h>
#include <cuda_fp16.h>
#include <math.h>
#include <stdint.h>

#define BATCH 2
#define TSEQ  2048
#define CDIM  1024
#define NHEAD 16
#define HD    64
#define MROWS (BATCH * TSEQ)     // 4096
#define NQKV  (3 * CDIM)         // 3072
#define KDIM  1024

// ---------------------------------------------------------------------------
// Scratch (allocation-free: __device__ globals).
// Q: fp16 hi/lo planes. K,V: SINGLE fp16 plane holding exact (q - zp) integers.
// ---------------------------------------------------------------------------
#define QKV_ELEMS (BATCH * NHEAD * TSEQ * HD)
__device__ __align__(256) __half g_Qhi[QKV_ELEMS];
__device__ __align__(256) __half g_Qlo[QKV_ELEMS];
__device__ __align__(256) __half g_Kq[QKV_ELEMS];
__device__ __align__(256) __half g_Vq[QKV_ELEMS];
__device__ __align__(256) __half g_Xhi[MROWS * CDIM];
__device__ __align__(256) __half g_Xlo[MROWS * CDIM];
__device__ __align__(256) __half g_WaThi[NQKV * CDIM];
__device__ __align__(256) __half g_WaTlo[NQKV * CDIM];
__device__ __align__(256) __half g_WpThi[CDIM * CDIM];
__device__ __align__(256) __half g_WpTlo[CDIM * CDIM];
__device__ __align__(256) __half g_Ohi[MROWS * CDIM];
__device__ __align__(256) __half g_Olo[MROWS * CDIM];

// ---------------------------------------------------------------------------
// PTX helpers (arch-generic only: cp.async, ldmatrix, mma.sync)
// ---------------------------------------------------------------------------
__device__ __forceinline__ uint32_t smem_u32(const void* p) {
    uint32_t a;
    asm("{ .reg .u64 t; cvta.to.shared.u64 t, %1; cvt.u32.u64 %0, t; }"
        : "=r"(a) : "l"(p));
    return a;
}

#define CPA16(dst, src) \
    asm volatile("cp.async.cg.shared.global [%0], [%1], 16;" :: "r"(dst), "l"(src))
#define CPA_COMMIT() asm volatile("cp.async.commit_group;" ::: "memory")
#define CPA_WAIT1()  asm volatile("cp.async.wait_group 1;" ::: "memory")
#define CPA_WAIT0()  asm volatile("cp.async.wait_group 0;" ::: "memory")

#define LDSM4(r, addr)                                                        \
    asm volatile("ldmatrix.sync.aligned.m8n8.x4.shared.b16 {%0,%1,%2,%3}, [%4];" \
        : "=r"((r)[0]), "=r"((r)[1]), "=r"((r)[2]), "=r"((r)[3]) : "r"(addr))

#define LDSM4T(r, addr)                                                       \
    asm volatile("ldmatrix.sync.aligned.m8n8.x4.trans.shared.b16 {%0,%1,%2,%3}, [%4];" \
        : "=r"((r)[0]), "=r"((r)[1]), "=r"((r)[2]), "=r"((r)[3]) : "r"(addr))

#define MMA_F16(d, a, b0v, b1v)                                               \
    asm volatile("mma.sync.aligned.m16n8k16.row.col.f32.f16.f16.f32 "         \
        "{%0,%1,%2,%3}, {%4,%5,%6,%7}, {%8,%9}, {%0,%1,%2,%3};"               \
        : "+f"((d)[0]), "+f"((d)[1]), "+f"((d)[2]), "+f"((d)[3])              \
        : "r"((a)[0]), "r"((a)[1]), "r"((a)[2]), "r"((a)[3]),                 \
          "r"(b0v), "r"(b1v))

__device__ __forceinline__ uint32_t pack_h2(__half x, __half y) {
    __half2 h = __halves2half2(x, y);
    return *(uint32_t*)&h;
}

// ---------------------------------------------------------------------------
// Prep kernels: fp16 hi/lo split (+ transpose for weights)
// ---------------------------------------------------------------------------
__global__ void split_kernel(const float* __restrict__ in,
                             __half* __restrict__ hi,
                             __half* __restrict__ lo, int n4) {
    for (int i = blockIdx.x * blockDim.x + threadIdx.x; i < n4;
         i += gridDim.x * blockDim.x) {
        float4 v = ((const float4*)in)[i];
        __half hx = __float2half_rn(v.x);
        __half hy = __float2half_rn(v.y);
        __half hz = __float2half_rn(v.z);
        __half hw = __float2half_rn(v.w);
        __half lx = __float2half_rn(v.x - __half2float(hx));
        __half ly = __float2half_rn(v.y - __half2float(hy));
        __half lz = __float2half_rn(v.z - __half2float(hz));
        __half lw = __float2half_rn(v.w - __half2float(hw));
        ((__half2*)hi)[2 * i + 0] = __halves2half2(hx, hy);
        ((__half2*)hi)[2 * i + 1] = __halves2half2(hz, hw);
        ((__half2*)lo)[2 * i + 0] = __halves2half2(lx, ly);
        ((__half2*)lo)[2 * i + 1] = __halves2half2(lz, lw);
    }
}

__global__ void transpose_split_kernel(const float* __restrict__ in,
                                       __half* __restrict__ ohi,
                                       __half* __restrict__ olo,
                                       int R, int C) {
    __shared__ float t[32][33];
    const int c0 = blockIdx.x * 32, r0 = blockIdx.y * 32;
    const int x = threadIdx.x & 31, y0 = threadIdx.x >> 5;
#pragma unroll
    for (int i = 0; i < 4; ++i) {
        int y = y0 + i * 8;
        t[y][x] = in[(size_t)(r0 + y) * C + c0 + x];
    }
    __syncthreads();
#pragma unroll
    for (int i = 0; i < 4; ++i) {
        int yy = y0 + i * 8;
        float v = t[x][yy];
        __half hi = __float2half_rn(v);
        __half lo = __float2half_rn(v - __half2float(hi));
        size_t o = (size_t)(c0 + yy) * R + r0 + x;
        ohi[o] = hi;
        olo[o] = lo;
    }
}

// ---------------------------------------------------------------------------
// mma.sync fp16 split-3 GEMM (R13 structure: 3-stage, single barrier, 2 CTA).
// MODE 0: fake-quant; K/V stored as EXACT integer-valued fp16 (q - zp); Q as
//         fp16 hi/lo planes.
// MODE 1: epilogue writes Cout row-major fp32.
// ---------------------------------------------------------------------------
#define STAGE_BYTES 32768        // Ahi 8K | Alo 8K | Bhi 8K | Blo 8K
#define NSTAGES 3
#define SMEM_DYN (STAGE_BYTES * NSTAGES)   // 98304

template <int MODE>
__global__ __launch_bounds__(256, 2) void mma_gemm_kernel(
    const __half* __restrict__ Ahi, const __half* __restrict__ Alo,
    const __half* __restrict__ Bhi, const __half* __restrict__ Blo,
    const float* __restrict__ bias, int Ncols,
    const float* __restrict__ scale_p, const float* __restrict__ zp_p,
    float* __restrict__ Cout)
{
    extern __shared__ __align__(1024) char smem[];
    const uint32_t sb = smem_u32(smem);
    const int tid = threadIdx.x;
    const int wid = tid >> 5, lane = tid & 31;
    const int m0 = blockIdx.y * 128, n0 = blockIdx.x * 128;
    const int wm = wid & 3;
    const int wn = wid >> 2;

    float acc[2][8][4];
#pragma unroll
    for (int i = 0; i < 2; ++i)
#pragma unroll
        for (int j = 0; j < 8; ++j)
#pragma unroll
            for (int k = 0; k < 4; ++k) acc[i][j][k] = 0.0f;

    auto load_stage = [&](int kt, int s) {
        const uint32_t st = sb + (uint32_t)s * STAGE_BYTES;
        const int kb = kt * 32;
#pragma unroll
        for (int p = 0; p < 2; ++p) {
            const __half* src = p ? Alo : Ahi;
            const uint32_t po = st + p * 8192;
#pragma unroll
            for (int i = 0; i < 2; ++i) {
                int idx = tid + i * 256;
                int row = idx >> 2, c = idx & 3;
                uint32_t dst = po + row * 64 + ((c ^ ((row >> 1) & 3)) << 4);
                CPA16(dst, src + (size_t)(m0 + row) * KDIM + kb + c * 8);
            }
        }
#pragma unroll
        for (int p = 0; p < 2; ++p) {
            const __half* src = p ? Blo : Bhi;
            const uint32_t po = st + 16384 + p * 8192;
#pragma unroll
            for (int i = 0; i < 2; ++i) {
                int idx = tid + i * 256;
                int row = idx >> 2, c = idx & 3;
                uint32_t dst = po + row * 64 + ((c ^ ((row >> 1) & 3)) << 4);
                CPA16(dst, src + (size_t)(n0 + row) * KDIM + kb + c * 8);
            }
        }
        CPA_COMMIT();
    };

    load_stage(0, 0);
    load_stage(1, 1);

    const int NK = KDIM / 32;   // 32
    for (int kt = 0; kt < NK; ++kt) {
        const int s = kt % NSTAGES;
        if (kt + 1 < NK) { CPA_WAIT1(); } else { CPA_WAIT0(); }
        __syncthreads();                       // single barrier per k-tile

        const uint32_t st = sb + (uint32_t)s * STAGE_BYTES;
#pragma unroll
        for (int kh = 0; kh < 2; ++kh) {
            const int cbase = kh * 2;
            uint32_t a[2][2][4];
#pragma unroll
            for (int p = 0; p < 2; ++p) {
#pragma unroll
                for (int mf = 0; mf < 2; ++mf) {
                    int row = wm * 32 + mf * 16 + ((lane >> 3) & 1) * 8 + (lane & 7);
                    int c = cbase + ((lane >> 4) & 1);
                    uint32_t addr = st + p * 8192 + row * 64
                                  + ((c ^ ((row >> 1) & 3)) << 4);
                    LDSM4(a[p][mf], addr);
                }
            }
            uint32_t b[2][16];
#pragma unroll
            for (int p = 0; p < 2; ++p) {
#pragma unroll
                for (int nq = 0; nq < 4; ++nq) {
                    int row = wn * 64 + nq * 16 + ((lane >> 4) & 1) * 8 + (lane & 7);
                    int c = cbase + ((lane >> 3) & 1);
                    uint32_t addr = st + 16384 + p * 8192 + row * 64
                                  + ((c ^ ((row >> 1) & 3)) << 4);
                    LDSM4(&b[p][nq * 4], addr);
                }
            }
#pragma unroll
            for (int mf = 0; mf < 2; ++mf)
#pragma unroll
                for (int nf = 0; nf < 8; ++nf) {
                    const int bi = (nf >> 1) * 4 + (nf & 1) * 2;
                    MMA_F16(acc[mf][nf], a[0][mf], b[0][bi], b[0][bi + 1]);
                }
#pragma unroll
            for (int mf = 0; mf < 2; ++mf)
#pragma unroll
                for (int nf = 0; nf < 8; ++nf) {
                    const int bi = (nf >> 1) * 4 + (nf & 1) * 2;
                    MMA_F16(acc[mf][nf], a[1][mf], b[0][bi], b[0][bi + 1]);
                }
#pragma unroll
            for (int mf = 0; mf < 2; ++mf)
#pragma unroll
                for (int nf = 0; nf < 8; ++nf) {
                    const int bi = (nf >> 1) * 4 + (nf & 1) * 2;
                    MMA_F16(acc[mf][nf], a[0][mf], b[1][bi], b[1][bi + 1]);
                }
        }

        if (kt + 2 < NK) load_stage(kt + 2, (kt + 2) % NSTAGES);
    }

    float scl = 1.0f, zp = 0.0f;
    if (MODE == 0) { scl = *scale_p; zp = *zp_p; }

#pragma unroll
    for (int mf = 0; mf < 2; ++mf) {
#pragma unroll
        for (int nf = 0; nf < 8; ++nf) {
            const int n = n0 + wn * 64 + nf * 8 + (lane & 3) * 2;
            const float2 bv = *(const float2*)(bias + n);
#pragma unroll
            for (int half = 0; half < 2; ++half) {
                const int m = m0 + wm * 32 + mf * 16 + (lane >> 2) + half * 8;
                float v0 = acc[mf][nf][half * 2 + 0] + bv.x;
                float v1 = acc[mf][nf][half * 2 + 1] + bv.y;
                if (MODE == 0) {
                    const int bb = m >> 11;
                    const int t = m & 2047;
                    const int which = n >> 10;
                    const int cI = n & 1023;
                    const int h = cI >> 6, d = cI & 63;
                    const size_t idx = (((size_t)(bb * NHEAD + h) * TSEQ + t) * HD + d);
                    if (which == 0) {
                        __half h0 = __float2half_rn(v0);
                        __half h1 = __float2half_rn(v1);
                        *(__half2*)(g_Qhi + idx) = __halves2half2(h0, h1);
                        *(__half2*)(g_Qlo + idx) = __halves2half2(
                            __float2half_rn(v0 - __half2float(h0)),
                            __float2half_rn(v1 - __half2float(h1)));
                    } else {
                        // exact integer-valued fp16: q - zp in [-128, 127]
                        float q0 = fminf(fmaxf(rintf(v0 / scl + zp), 0.0f), 255.0f) - zp;
                        float q1 = fminf(fmaxf(rintf(v1 / scl + zp), 0.0f), 255.0f) - zp;
                        __half2 qv = __halves2half2(__float2half_rn(q0),
                                                    __float2half_rn(q1));
                        if (which == 1) *(__half2*)(g_Kq + idx) = qv;
                        else            *(__half2*)(g_Vq + idx) = qv;
                    }
                } else {
                    *(float2*)(Cout + (size_t)m * Ncols + n) = make_float2(v0, v1);
                }
            }
        }
    }
}

// ---------------------------------------------------------------------------
// Tensor-core causal flash attention. K/V are single exact fp16 planes
// (integer-valued), scale folded into softmax scale + output epilogue.
// 2 MMAs per product (exact split, no dropped term). SMEM 64KB.
// ---------------------------------------------------------------------------
#define FS_QH 0
#define FS_QL 16384
#define FS_ST 32768
#define FS_STAGE 16384           // Kq 8K | Vq 8K
#define FS_TOTAL (FS_ST + 2 * FS_STAGE)   // 65536

__global__ __launch_bounds__(128, 2) void flash_mma_kernel(
    const float* __restrict__ scale_p)
{
    extern __shared__ __align__(1024) char fsm[];
    const uint32_t sb = smem_u32(fsm);
    const int qb = (TSEQ / 128 - 1) - blockIdx.x;   // long blocks first
    const int h = blockIdx.y, b = blockIdx.z;
    const int tid = threadIdx.x, warp = tid >> 5, lane = tid & 31;
    const size_t bh = (size_t)(b * NHEAD + h) * TSEQ * HD;
    const float kvs = *scale_p;

    const __half* Qh = g_Qhi + bh + (size_t)qb * 128 * HD;
    const __half* Ql = g_Qlo + bh + (size_t)qb * 128 * HD;
    const __half* Kq = g_Kq + bh;
    const __half* Vq = g_Vq + bh;

#pragma unroll
    for (int p = 0; p < 2; ++p) {
        const __half* src = p ? Ql : Qh;
        const uint32_t base = sb + (p ? FS_QL : FS_QH);
#pragma unroll
        for (int i = 0; i < 8; ++i) {
            int idx = tid + i * 128;
            int row = idx >> 3, c = idx & 7;
            CPA16(base + row * 128 + ((c ^ (row & 7)) << 4), src + row * 64 + c * 8);
        }
    }

    auto load_tile = [&](int j, int s) {
        const uint32_t st = sb + FS_ST + (uint32_t)s * FS_STAGE;
        const __half* srcs[2] = { Kq + (size_t)j * 64 * HD,
                                  Vq + (size_t)j * 64 * HD };
#pragma unroll
        for (int p = 0; p < 2; ++p) {
#pragma unroll
            for (int i = 0; i < 4; ++i) {
                int idx = tid + i * 128;
                int row = idx >> 3, c = idx & 7;
                CPA16(st + p * 8192 + row * 128 + ((c ^ (row & 7)) << 4),
                      srcs[p] + row * 64 + c * 8);
            }
        }
    };

    load_tile(0, 0);
    CPA_COMMIT();
    load_tile(1, 1);
    CPA_COMMIT();

    float O[2][8][4];
#pragma unroll
    for (int mf = 0; mf < 2; ++mf)
#pragma unroll
        for (int nf = 0; nf < 8; ++nf)
#pragma unroll
            for (int e = 0; e < 4; ++e) O[mf][nf][e] = 0.0f;
    float rm[2][2], rl[2][2];
#pragma unroll
    for (int mf = 0; mf < 2; ++mf)
#pragma unroll
        for (int hf = 0; hf < 2; ++hf) { rm[mf][hf] = -1e30f; rl[mf][hf] = 0.0f; }

    const int ntiles = 2 * qb + 2;
    const float sscale = 0.125f * kvs;      // 1/sqrt(64) * kv_scale
    CPA_WAIT1();

    for (int j = 0; j < ntiles; ++j) {
        const int s = j & 1;
        __syncthreads();
        const uint32_t st = sb + FS_ST + (uint32_t)s * FS_STAGE;

        float S[2][8][4];
#pragma unroll
        for (int mf = 0; mf < 2; ++mf)
#pragma unroll
            for (int nf = 0; nf < 8; ++nf)
#pragma unroll
                for (int e = 0; e < 4; ++e) S[mf][nf][e] = 0.0f;

#pragma unroll
        for (int ks = 0; ks < 4; ++ks) {
            uint32_t aQ[2][2][4];
#pragma unroll
            for (int p = 0; p < 2; ++p) {
#pragma unroll
                for (int mf = 0; mf < 2; ++mf) {
                    int row = warp * 32 + mf * 16 + ((lane >> 3) & 1) * 8 + (lane & 7);
                    int c = ks * 2 + ((lane >> 4) & 1);
                    LDSM4(aQ[p][mf], sb + (p ? FS_QL : FS_QH) + row * 128
                                     + ((c ^ (row & 7)) << 4));
                }
            }
            uint32_t bK[4][4];
#pragma unroll
            for (int kg = 0; kg < 4; ++kg) {
                int row = kg * 16 + ((lane >> 4) & 1) * 8 + (lane & 7);
                int c = ks * 2 + ((lane >> 3) & 1);
                LDSM4(bK[kg], st + row * 128 + ((c ^ (row & 7)) << 4));
            }
            // Exact: (Qhi + Qlo) * K'
#pragma unroll
            for (int mf = 0; mf < 2; ++mf)
#pragma unroll
                for (int nf = 0; nf < 8; ++nf) {
                    const int kg = nf >> 1, o = (nf & 1) * 2;
                    MMA_F16(S[mf][nf], aQ[0][mf], bK[kg][o], bK[kg][o + 1]);
                }
#pragma unroll
            for (int mf = 0; mf < 2; ++mf)
#pragma unroll
                for (int nf = 0; nf < 8; ++nf) {
                    const int kg = nf >> 1, o = (nf & 1) * 2;
                    MMA_F16(S[mf][nf], aQ[1][mf], bK[kg][o], bK[kg][o + 1]);
                }
        }

        const bool maskT = (j >= 2 * qb);
#pragma unroll
        for (int mf = 0; mf < 2; ++mf)
#pragma unroll
            for (int nf = 0; nf < 8; ++nf)
#pragma unroll
                for (int e = 0; e < 4; ++e) {
                    float sv = S[mf][nf][e] * sscale;
                    if (maskT) {
                        const int key = j * 64 + nf * 8 + (lane & 3) * 2 + (e & 1);
                        const int rowg = qb * 128 + warp * 32 + mf * 16
                                       + (lane >> 2) + (e >> 1) * 8;
                        if (key > rowg) sv = -1e30f;
                    }
                    S[mf][nf][e] = sv;
                }

#pragma unroll
        for (int mf = 0; mf < 2; ++mf) {
#pragma unroll
            for (int hf = 0; hf < 2; ++hf) {
                float mx = -1e30f;
#pragma unroll
                for (int nf = 0; nf < 8; ++nf)
                    mx = fmaxf(mx, fmaxf(S[mf][nf][hf * 2], S[mf][nf][hf * 2 + 1]));
                mx = fmaxf(mx, __shfl_xor_sync(0xFFFFFFFFu, mx, 1));
                mx = fmaxf(mx, __shfl_xor_sync(0xFFFFFFFFu, mx, 2));
                const float mnew = fmaxf(rm[mf][hf], mx);
                const float corr = __expf(rm[mf][hf] - mnew);
                rm[mf][hf] = mnew;
                float ps = 0.0f;
#pragma unroll
                for (int nf = 0; nf < 8; ++nf) {
                    float p0 = __expf(S[mf][nf][hf * 2 + 0] - mnew);
                    float p1 = __expf(S[mf][nf][hf * 2 + 1] - mnew);
                    S[mf][nf][hf * 2 + 0] = p0;
                    S[mf][nf][hf * 2 + 1] = p1;
                    ps += p0 + p1;
                }
                ps += __shfl_xor_sync(0xFFFFFFFFu, ps, 1);
                ps += __shfl_xor_sync(0xFFFFFFFFu, ps, 2);
                rl[mf][hf] = rl[mf][hf] * corr + ps;
#pragma unroll
                for (int nf = 0; nf < 8; ++nf) {
                    O[mf][nf][hf * 2 + 0] *= corr;
                    O[mf][nf][hf * 2 + 1] *= corr;
                }
            }
        }

#pragma unroll
        for (int kc = 0; kc < 4; ++kc) {
            uint32_t aP[2][2][4];
#pragma unroll
            for (int mf = 0; mf < 2; ++mf) {
#pragma unroll
                for (int e = 0; e < 2; ++e) {
                    const int nf = 2 * kc + e;
#pragma unroll
                    for (int hf = 0; hf < 2; ++hf) {
                        float x = S[mf][nf][hf * 2 + 0];
                        float y = S[mf][nf][hf * 2 + 1];
                        __half hx = __float2half_rn(x);
                        __half hy = __float2half_rn(y);
                        aP[0][mf][e * 2 + hf] = pack_h2(hx, hy);
                        aP[1][mf][e * 2 + hf] = pack_h2(
                            __float2half_rn(x - __half2float(hx)),
                            __float2half_rn(y - __half2float(hy)));
                    }
                }
            }
            uint32_t bV[4][4];
#pragma unroll
            for (int dg = 0; dg < 4; ++dg) {
                int row = kc * 16 + ((lane >> 3) & 1) * 8 + (lane & 7);
                int c = dg * 2 + ((lane >> 4) & 1);
                LDSM4T(bV[dg], st + 8192 + row * 128 + ((c ^ (row & 7)) << 4));
            }
            // Exact: (Phi + Plo) * V'
#pragma unroll
            for (int mf = 0; mf < 2; ++mf)
#pragma unroll
                for (int nf = 0; nf < 8; ++nf) {
                    const int dg = nf >> 1, o = (nf & 1) * 2;
                    MMA_F16(O[mf][nf], aP[0][mf], bV[dg][o], bV[dg][o + 1]);
                }
#pragma unroll
            for (int mf = 0; mf < 2; ++mf)
#pragma unroll
                for (int nf = 0; nf < 8; ++nf) {
                    const int dg = nf >> 1, o = (nf & 1) * 2;
                    MMA_F16(O[mf][nf], aP[1][mf], bV[dg][o], bV[dg][o + 1]);
                }
        }

        __syncthreads();
        if (j + 2 < ntiles) { load_tile(j + 2, s); CPA_COMMIT(); }
        if (j + 1 < ntiles) {
            if (j + 2 < ntiles) { CPA_WAIT1(); } else { CPA_WAIT0(); }
        }
    }

#pragma unroll
    for (int mf = 0; mf < 2; ++mf) {
#pragma unroll
        for (int hf = 0; hf < 2; ++hf) {
            const float inv = kvs / rl[mf][hf];   // fold V dequant scale here
            const int row = qb * 128 + warp * 32 + mf * 16 + (lane >> 2) + hf * 8;
            const size_t ob = ((size_t)(b * TSEQ) + row) * CDIM + h * 64;
#pragma unroll
            for (int nf = 0; nf < 8; ++nf) {
                const int d = nf * 8 + (lane & 3) * 2;
                float v0 = O[mf][nf][hf * 2 + 0] * inv;
                float v1 = O[mf][nf][hf * 2 + 1] * inv;
                __half h0 = __float2half_rn(v0);
                __half h1 = __float2half_rn(v1);
                *(__half2*)(g_Ohi + ob + d) = __halves2half2(h0, h1);
                *(__half2*)(g_Olo + ob + d) = __halves2half2(
                    __float2half_rn(v0 - __half2float(h0)),
                    __float2half_rn(v1 - __half2float(h1)));
            }
        }
    }
}

// ---------------------------------------------------------------------------
// Launch
// ---------------------------------------------------------------------------
extern "C" void kernel_launch(void* const* d_in, const int* in_sizes, int n_in,
                              void* d_out, int out_size)
{
    const float* hidden   = (const float*)d_in[0];
    const float* W_attn   = (const float*)d_in[1];
    const float* b_attn   = (const float*)d_in[2];
    const float* W_proj   = (const float*)d_in[3];
    const float* b_proj   = (const float*)d_in[4];
    const float* kv_scale = (const float*)d_in[5];
    const float* kv_zp    = (const float*)d_in[6];
    float* out = (float*)d_out;

    cudaFuncSetAttribute(mma_gemm_kernel<0>,
                         cudaFuncAttributeMaxDynamicSharedMemorySize, SMEM_DYN);
    cudaFuncSetAttribute(mma_gemm_kernel<1>,
                         cudaFuncAttributeMaxDynamicSharedMemorySize, SMEM_DYN);
    cudaFuncSetAttribute(flash_mma_kernel,
                         cudaFuncAttributeMaxDynamicSharedMemorySize, FS_TOTAL);

    __half *Xhi, *Xlo, *WaThi, *WaTlo, *WpThi, *WpTlo, *Ohi, *Olo;
    cudaGetSymbolAddress((void**)&Xhi, g_Xhi);
    cudaGetSymbolAddress((void**)&Xlo, g_Xlo);
    cudaGetSymbolAddress((void**)&WaThi, g_WaThi);
    cudaGetSymbolAddress((void**)&WaTlo, g_WaTlo);
    cudaGetSymbolAddress((void**)&WpThi, g_WpThi);
    cudaGetSymbolAddress((void**)&WpTlo, g_WpTlo);
    cudaGetSymbolAddress((void**)&Ohi, g_Ohi);
    cudaGetSymbolAddress((void**)&Olo, g_Olo);

    // Prep
    split_kernel<<<1024, 256>>>(hidden, Xhi, Xlo, MROWS * CDIM / 4);
    transpose_split_kernel<<<dim3(NQKV / 32, CDIM / 32), 256>>>(W_attn, WaThi, WaTlo, CDIM, NQKV);
    transpose_split_kernel<<<dim3(CDIM / 32, CDIM / 32), 256>>>(W_proj, WpThi, WpTlo, CDIM, CDIM);

    // QKV GEMM + bias + fake-quant (K/V exact integer fp16) + Q hi/lo
    mma_gemm_kernel<0><<<dim3(NQKV / 128, MROWS / 128), 256, SMEM_DYN>>>(
        Xhi, Xlo, WaThi, WaTlo, b_attn, NQKV, kv_scale, kv_zp, nullptr);

    // Tensor-core causal flash attention (scale folded)
    flash_mma_kernel<<<dim3(TSEQ / 128, NHEAD, BATCH), 128, FS_TOTAL>>>(kv_scale);

    // Output projection
    mma_gemm_kernel<1><<<dim3(CDIM / 128, MROWS / 128), 256, SMEM_DYN>>>(
        Ohi, Olo, WpThi, WpTlo, b_proj, CDIM, nullptr, nullptr, out);
}

// round 16
// speedup vs baseline: 1.3234x; 1.0301x over previous
#include <cuda_runtime.h>
#include <cuda_fp16.h>
#include <math.h>
#include <stdint.h>

#define BATCH 2
#define TSEQ  2048
#define CDIM  1024
#define NHEAD 16
#define HD    64
#define MROWS (BATCH * TSEQ)     // 4096
#define NQKV  (3 * CDIM)         // 3072
#define KDIM  1024

// ---------------------------------------------------------------------------
// Scratch (allocation-free: __device__ globals).
// Q: fp16 hi/lo planes. K,V: SINGLE fp16 plane holding exact (q - zp) integers.
// ---------------------------------------------------------------------------
#define QKV_ELEMS (BATCH * NHEAD * TSEQ * HD)
__device__ __align__(256) __half g_Qhi[QKV_ELEMS];
__device__ __align__(256) __half g_Qlo[QKV_ELEMS];
__device__ __align__(256) __half g_Kq[QKV_ELEMS];
__device__ __align__(256) __half g_Vq[QKV_ELEMS];
__device__ __align__(256) __half g_Xhi[MROWS * CDIM];
__device__ __align__(256) __half g_Xlo[MROWS * CDIM];
__device__ __align__(256) __half g_WaThi[NQKV * CDIM];
__device__ __align__(256) __half g_WaTlo[NQKV * CDIM];
__device__ __align__(256) __half g_WpThi[CDIM * CDIM];
__device__ __align__(256) __half g_WpTlo[CDIM * CDIM];
__device__ __align__(256) __half g_Ohi[MROWS * CDIM];
__device__ __align__(256) __half g_Olo[MROWS * CDIM];

// ---------------------------------------------------------------------------
// PTX helpers (arch-generic only: cp.async, ldmatrix, mma.sync)
// ---------------------------------------------------------------------------
__device__ __forceinline__ uint32_t smem_u32(const void* p) {
    uint32_t a;
    asm("{ .reg .u64 t; cvta.to.shared.u64 t, %1; cvt.u32.u64 %0, t; }"
        : "=r"(a) : "l"(p));
    return a;
}

#define CPA16(dst, src) \
    asm volatile("cp.async.cg.shared.global [%0], [%1], 16;" :: "r"(dst), "l"(src))
#define CPA_COMMIT() asm volatile("cp.async.commit_group;" ::: "memory")
#define CPA_WAIT1()  asm volatile("cp.async.wait_group 1;" ::: "memory")
#define CPA_WAIT0()  asm volatile("cp.async.wait_group 0;" ::: "memory")

#define LDSM4(r, addr)                                                        \
    asm volatile("ldmatrix.sync.aligned.m8n8.x4.shared.b16 {%0,%1,%2,%3}, [%4];" \
        : "=r"((r)[0]), "=r"((r)[1]), "=r"((r)[2]), "=r"((r)[3]) : "r"(addr))

#define LDSM4T(r, addr)                                                       \
    asm volatile("ldmatrix.sync.aligned.m8n8.x4.trans.shared.b16 {%0,%1,%2,%3}, [%4];" \
        : "=r"((r)[0]), "=r"((r)[1]), "=r"((r)[2]), "=r"((r)[3]) : "r"(addr))

#define MMA_F16(d, a, b0v, b1v)                                               \
    asm volatile("mma.sync.aligned.m16n8k16.row.col.f32.f16.f16.f32 "         \
        "{%0,%1,%2,%3}, {%4,%5,%6,%7}, {%8,%9}, {%0,%1,%2,%3};"               \
        : "+f"((d)[0]), "+f"((d)[1]), "+f"((d)[2]), "+f"((d)[3])              \
        : "r"((a)[0]), "r"((a)[1]), "r"((a)[2]), "r"((a)[3]),                 \
          "r"(b0v), "r"(b1v))

__device__ __forceinline__ uint32_t pack_h2(__half x, __half y) {
    __half2 h = __halves2half2(x, y);
    return *(uint32_t*)&h;
}

// ---------------------------------------------------------------------------
// Prep kernels: fp16 hi/lo split (+ transpose for weights)
// ---------------------------------------------------------------------------
__global__ void split_kernel(const float* __restrict__ in,
                             __half* __restrict__ hi,
                             __half* __restrict__ lo, int n4) {
    for (int i = blockIdx.x * blockDim.x + threadIdx.x; i < n4;
         i += gridDim.x * blockDim.x) {
        float4 v = ((const float4*)in)[i];
        __half hx = __float2half_rn(v.x);
        __half hy = __float2half_rn(v.y);
        __half hz = __float2half_rn(v.z);
        __half hw = __float2half_rn(v.w);
        __half lx = __float2half_rn(v.x - __half2float(hx));
        __half ly = __float2half_rn(v.y - __half2float(hy));
        __half lz = __float2half_rn(v.z - __half2float(hz));
        __half lw = __float2half_rn(v.w - __half2float(hw));
        ((__half2*)hi)[2 * i + 0] = __halves2half2(hx, hy);
        ((__half2*)hi)[2 * i + 1] = __halves2half2(hz, hw);
        ((__half2*)lo)[2 * i + 0] = __halves2half2(lx, ly);
        ((__half2*)lo)[2 * i + 1] = __halves2half2(lz, lw);
    }
}

__global__ void transpose_split_kernel(const float* __restrict__ in,
                                       __half* __restrict__ ohi,
                                       __half* __restrict__ olo,
                                       int R, int C) {
    __shared__ float t[32][33];
    const int c0 = blockIdx.x * 32, r0 = blockIdx.y * 32;
    const int x = threadIdx.x & 31, y0 = threadIdx.x >> 5;
#pragma unroll
    for (int i = 0; i < 4; ++i) {
        int y = y0 + i * 8;
        t[y][x] = in[(size_t)(r0 + y) * C + c0 + x];
    }
    __syncthreads();
#pragma unroll
    for (int i = 0; i < 4; ++i) {
        int yy = y0 + i * 8;
        float v = t[x][yy];
        __half hi = __float2half_rn(v);
        __half lo = __float2half_rn(v - __half2float(hi));
        size_t o = (size_t)(c0 + yy) * R + r0 + x;
        ohi[o] = hi;
        olo[o] = lo;
    }
}

// ---------------------------------------------------------------------------
// mma.sync fp16 GEMM. CTA 128x128, 8 warps, BK=32, 3-stage, single barrier,
// 2 CTAs/SM. R15: PERSISTENT tiles (grid = 296 < n_tiles) to kill the
// wave-quantization tail; next tile's cp.async prologue overlaps this
// tile's epilogue. NSPLIT: 3 = hi*hi + lo*hi + hi*lo; 2 = (hi+lo)*hi only
// (drops B-lo plane: loads AND MMAs).
// MODE 0: fake-quant; K/V stored as EXACT integer-valued fp16; Q hi/lo.
// MODE 1: epilogue writes Cout row-major fp32.
// ---------------------------------------------------------------------------
#define STAGE_BYTES 32768        // Ahi 8K | Alo 8K | Bhi 8K | Blo 8K
#define NSTAGES 3
#define SMEM_DYN (STAGE_BYTES * NSTAGES)   // 98304
#define GEMM_GRID 296

template <int MODE, int NSPLIT>
__global__ __launch_bounds__(256, 2) void mma_gemm_kernel(
    const __half* __restrict__ Ahi, const __half* __restrict__ Alo,
    const __half* __restrict__ Bhi, const __half* __restrict__ Blo,
    const float* __restrict__ bias, int Ncols,
    const float* __restrict__ scale_p, const float* __restrict__ zp_p,
    float* __restrict__ Cout)
{
    extern __shared__ __align__(1024) char smem[];
    const uint32_t sb = smem_u32(smem);
    const int tid = threadIdx.x;
    const int wid = tid >> 5, lane = tid & 31;
    const int wm = wid & 3;
    const int wn = wid >> 2;
    const int ncolt = Ncols >> 7;
    const int NT = (MROWS >> 7) * ncolt;

    int tile = blockIdx.x;
    if (tile >= NT) return;
    int m0 = (tile / ncolt) << 7;
    int n0 = (tile % ncolt) << 7;

    auto load_stage = [&](int lm0, int ln0, int kt, int s) {
        const uint32_t st = sb + (uint32_t)s * STAGE_BYTES;
        const int kb = kt * 32;
#pragma unroll
        for (int p = 0; p < 2; ++p) {
            const __half* src = p ? Alo : Ahi;
            const uint32_t po = st + p * 8192;
#pragma unroll
            for (int i = 0; i < 2; ++i) {
                int idx = tid + i * 256;
                int row = idx >> 2, c = idx & 3;
                uint32_t dst = po + row * 64 + ((c ^ ((row >> 1) & 3)) << 4);
                CPA16(dst, src + (size_t)(lm0 + row) * KDIM + kb + c * 8);
            }
        }
#pragma unroll
        for (int p = 0; p < (NSPLIT == 3 ? 2 : 1); ++p) {
            const __half* src = p ? Blo : Bhi;
            const uint32_t po = st + 16384 + p * 8192;
#pragma unroll
            for (int i = 0; i < 2; ++i) {
                int idx = tid + i * 256;
                int row = idx >> 2, c = idx & 3;
                uint32_t dst = po + row * 64 + ((c ^ ((row >> 1) & 3)) << 4);
                CPA16(dst, src + (size_t)(ln0 + row) * KDIM + kb + c * 8);
            }
        }
        CPA_COMMIT();
    };

    load_stage(m0, n0, 0, 0);
    load_stage(m0, n0, 1, 1);

    float scl = 1.0f, zp = 0.0f;
    if (MODE == 0) { scl = *scale_p; zp = *zp_p; }

    const int NK = KDIM / 32;   // 32

    while (true) {
        float acc[2][8][4];
#pragma unroll
        for (int i = 0; i < 2; ++i)
#pragma unroll
            for (int j = 0; j < 8; ++j)
#pragma unroll
                for (int k = 0; k < 4; ++k) acc[i][j][k] = 0.0f;

        for (int kt = 0; kt < NK; ++kt) {
            const int s = kt % NSTAGES;
            if (kt + 1 < NK) { CPA_WAIT1(); } else { CPA_WAIT0(); }
            __syncthreads();                   // single barrier per k-tile

            const uint32_t st = sb + (uint32_t)s * STAGE_BYTES;
#pragma unroll
            for (int kh = 0; kh < 2; ++kh) {
                const int cbase = kh * 2;
                uint32_t a[2][2][4];
#pragma unroll
                for (int p = 0; p < 2; ++p) {
#pragma unroll
                    for (int mf = 0; mf < 2; ++mf) {
                        int row = wm * 32 + mf * 16 + ((lane >> 3) & 1) * 8 + (lane & 7);
                        int c = cbase + ((lane >> 4) & 1);
                        uint32_t addr = st + p * 8192 + row * 64
                                      + ((c ^ ((row >> 1) & 3)) << 4);
                        LDSM4(a[p][mf], addr);
                    }
                }
                uint32_t b[2][16];
#pragma unroll
                for (int p = 0; p < (NSPLIT == 3 ? 2 : 1); ++p) {
#pragma unroll
                    for (int nq = 0; nq < 4; ++nq) {
                        int row = wn * 64 + nq * 16 + ((lane >> 4) & 1) * 8 + (lane & 7);
                        int c = cbase + ((lane >> 3) & 1);
                        uint32_t addr = st + 16384 + p * 8192 + row * 64
                                      + ((c ^ ((row >> 1) & 3)) << 4);
                        LDSM4(&b[p][nq * 4], addr);
                    }
                }
#pragma unroll
                for (int mf = 0; mf < 2; ++mf)
#pragma unroll
                    for (int nf = 0; nf < 8; ++nf) {
                        const int bi = (nf >> 1) * 4 + (nf & 1) * 2;
                        MMA_F16(acc[mf][nf], a[0][mf], b[0][bi], b[0][bi + 1]);
                    }
#pragma unroll
                for (int mf = 0; mf < 2; ++mf)
#pragma unroll
                    for (int nf = 0; nf < 8; ++nf) {
                        const int bi = (nf >> 1) * 4 + (nf & 1) * 2;
                        MMA_F16(acc[mf][nf], a[1][mf], b[0][bi], b[0][bi + 1]);
                    }
                if (NSPLIT == 3) {
#pragma unroll
                    for (int mf = 0; mf < 2; ++mf)
#pragma unroll
                        for (int nf = 0; nf < 8; ++nf) {
                            const int bi = (nf >> 1) * 4 + (nf & 1) * 2;
                            MMA_F16(acc[mf][nf], a[0][mf], b[1][bi], b[1][bi + 1]);
                        }
                }
            }

            if (kt + 2 < NK) load_stage(m0, n0, kt + 2, (kt + 2) % NSTAGES);
        }

        // Prologue of the NEXT tile overlaps this tile's epilogue.
        const int ntile = tile + GEMM_GRID;
        int nm0 = 0, nn0 = 0;
        __syncthreads();            // all warps done reading SMEM of this tile
        if (ntile < NT) {
            nm0 = (ntile / ncolt) << 7;
            nn0 = (ntile % ncolt) << 7;
            load_stage(nm0, nn0, 0, 0);
            load_stage(nm0, nn0, 1, 1);
        }

        // ---- epilogue ----
#pragma unroll
        for (int mf = 0; mf < 2; ++mf) {
#pragma unroll
            for (int nf = 0; nf < 8; ++nf) {
                const int n = n0 + wn * 64 + nf * 8 + (lane & 3) * 2;
                const float2 bv = *(const float2*)(bias + n);
#pragma unroll
                for (int half = 0; half < 2; ++half) {
                    const int m = m0 + wm * 32 + mf * 16 + (lane >> 2) + half * 8;
                    float v0 = acc[mf][nf][half * 2 + 0] + bv.x;
                    float v1 = acc[mf][nf][half * 2 + 1] + bv.y;
                    if (MODE == 0) {
                        const int bb = m >> 11;
                        const int t = m & 2047;
                        const int which = n >> 10;
                        const int cI = n & 1023;
                        const int h = cI >> 6, d = cI & 63;
                        const size_t idx = (((size_t)(bb * NHEAD + h) * TSEQ + t) * HD + d);
                        if (which == 0) {
                            __half h0 = __float2half_rn(v0);
                            __half h1 = __float2half_rn(v1);
                            *(__half2*)(g_Qhi + idx) = __halves2half2(h0, h1);
                            *(__half2*)(g_Qlo + idx) = __halves2half2(
                                __float2half_rn(v0 - __half2float(h0)),
                                __float2half_rn(v1 - __half2float(h1)));
                        } else {
                            float q0 = fminf(fmaxf(rintf(v0 / scl + zp), 0.0f), 255.0f) - zp;
                            float q1 = fminf(fmaxf(rintf(v1 / scl + zp), 0.0f), 255.0f) - zp;
                            __half2 qv = __halves2half2(__float2half_rn(q0),
                                                        __float2half_rn(q1));
                            if (which == 1) *(__half2*)(g_Kq + idx) = qv;
                            else            *(__half2*)(g_Vq + idx) = qv;
                        }
                    } else {
                        *(float2*)(Cout + (size_t)m * Ncols + n) = make_float2(v0, v1);
                    }
                }
            }
        }

        if (ntile >= NT) break;
        tile = ntile; m0 = nm0; n0 = nn0;
    }
}

// ---------------------------------------------------------------------------
// Tensor-core causal flash attention (R14, proven). K/V single exact fp16
// planes; scale folded into softmax scale + output epilogue.
// ---------------------------------------------------------------------------
#define FS_QH 0
#define FS_QL 16384
#define FS_ST 32768
#define FS_STAGE 16384           // Kq 8K | Vq 8K
#define FS_TOTAL (FS_ST + 2 * FS_STAGE)   // 65536

__global__ __launch_bounds__(128, 2) void flash_mma_kernel(
    const float* __restrict__ scale_p)
{
    extern __shared__ __align__(1024) char fsm[];
    const uint32_t sb = smem_u32(fsm);
    const int qb = (TSEQ / 128 - 1) - blockIdx.x;   // long blocks first
    const int h = blockIdx.y, b = blockIdx.z;
    const int tid = threadIdx.x, warp = tid >> 5, lane = tid & 31;
    const size_t bh = (size_t)(b * NHEAD + h) * TSEQ * HD;
    const float kvs = *scale_p;

    const __half* Qh = g_Qhi + bh + (size_t)qb * 128 * HD;
    const __half* Ql = g_Qlo + bh + (size_t)qb * 128 * HD;
    const __half* Kq = g_Kq + bh;
    const __half* Vq = g_Vq + bh;

#pragma unroll
    for (int p = 0; p < 2; ++p) {
        const __half* src = p ? Ql : Qh;
        const uint32_t base = sb + (p ? FS_QL : FS_QH);
#pragma unroll
        for (int i = 0; i < 8; ++i) {
            int idx = tid + i * 128;
            int row = idx >> 3, c = idx & 7;
            CPA16(base + row * 128 + ((c ^ (row & 7)) << 4), src + row * 64 + c * 8);
        }
    }

    auto load_tile = [&](int j, int s) {
        const uint32_t st = sb + FS_ST + (uint32_t)s * FS_STAGE;
        const __half* srcs[2] = { Kq + (size_t)j * 64 * HD,
                                  Vq + (size_t)j * 64 * HD };
#pragma unroll
        for (int p = 0; p < 2; ++p) {
#pragma unroll
            for (int i = 0; i < 4; ++i) {
                int idx = tid + i * 128;
                int row = idx >> 3, c = idx & 7;
                CPA16(st + p * 8192 + row * 128 + ((c ^ (row & 7)) << 4),
                      srcs[p] + row * 64 + c * 8);
            }
        }
    };

    load_tile(0, 0);
    CPA_COMMIT();
    load_tile(1, 1);
    CPA_COMMIT();

    float O[2][8][4];
#pragma unroll
    for (int mf = 0; mf < 2; ++mf)
#pragma unroll
        for (int nf = 0; nf < 8; ++nf)
#pragma unroll
            for (int e = 0; e < 4; ++e) O[mf][nf][e] = 0.0f;
    float rm[2][2], rl[2][2];
#pragma unroll
    for (int mf = 0; mf < 2; ++mf)
#pragma unroll
        for (int hf = 0; hf < 2; ++hf) { rm[mf][hf] = -1e30f; rl[mf][hf] = 0.0f; }

    const int ntiles = 2 * qb + 2;
    const float sscale = 0.125f * kvs;      // 1/sqrt(64) * kv_scale
    CPA_WAIT1();

    for (int j = 0; j < ntiles; ++j) {
        const int s = j & 1;
        __syncthreads();
        const uint32_t st = sb + FS_ST + (uint32_t)s * FS_STAGE;

        float S[2][8][4];
#pragma unroll
        for (int mf = 0; mf < 2; ++mf)
#pragma unroll
            for (int nf = 0; nf < 8; ++nf)
#pragma unroll
                for (int e = 0; e < 4; ++e) S[mf][nf][e] = 0.0f;

#pragma unroll
        for (int ks = 0; ks < 4; ++ks) {
            uint32_t aQ[2][2][4];
#pragma unroll
            for (int p = 0; p < 2; ++p) {
#pragma unroll
                for (int mf = 0; mf < 2; ++mf) {
                    int row = warp * 32 + mf * 16 + ((lane >> 3) & 1) * 8 + (lane & 7);
                    int c = ks * 2 + ((lane >> 4) & 1);
                    LDSM4(aQ[p][mf], sb + (p ? FS_QL : FS_QH) + row * 128
                                     + ((c ^ (row & 7)) << 4));
                }
            }
            uint32_t bK[4][4];
#pragma unroll
            for (int kg = 0; kg < 4; ++kg) {
                int row = kg * 16 + ((lane >> 4) & 1) * 8 + (lane & 7);
                int c = ks * 2 + ((lane >> 3) & 1);
                LDSM4(bK[kg], st + row * 128 + ((c ^ (row & 7)) << 4));
            }
#pragma unroll
            for (int mf = 0; mf < 2; ++mf)
#pragma unroll
                for (int nf = 0; nf < 8; ++nf) {
                    const int kg = nf >> 1, o = (nf & 1) * 2;
                    MMA_F16(S[mf][nf], aQ[0][mf], bK[kg][o], bK[kg][o + 1]);
                }
#pragma unroll
            for (int mf = 0; mf < 2; ++mf)
#pragma unroll
                for (int nf = 0; nf < 8; ++nf) {
                    const int kg = nf >> 1, o = (nf & 1) * 2;
                    MMA_F16(S[mf][nf], aQ[1][mf], bK[kg][o], bK[kg][o + 1]);
                }
        }

        const bool maskT = (j >= 2 * qb);
#pragma unroll
        for (int mf = 0; mf < 2; ++mf)
#pragma unroll
            for (int nf = 0; nf < 8; ++nf)
#pragma unroll
                for (int e = 0; e < 4; ++e) {
                    float sv = S[mf][nf][e] * sscale;
                    if (maskT) {
                        const int key = j * 64 + nf * 8 + (lane & 3) * 2 + (e & 1);
                        const int rowg = qb * 128 + warp * 32 + mf * 16
                                       + (lane >> 2) + (e >> 1) * 8;
                        if (key > rowg) sv = -1e30f;
                    }
                    S[mf][nf][e] = sv;
                }

#pragma unroll
        for (int mf = 0; mf < 2; ++mf) {
#pragma unroll
            for (int hf = 0; hf < 2; ++hf) {
                float mx = -1e30f;
#pragma unroll
                for (int nf = 0; nf < 8; ++nf)
                    mx = fmaxf(mx, fmaxf(S[mf][nf][hf * 2], S[mf][nf][hf * 2 + 1]));
                mx = fmaxf(mx, __shfl_xor_sync(0xFFFFFFFFu, mx, 1));
                mx = fmaxf(mx, __shfl_xor_sync(0xFFFFFFFFu, mx, 2));
                const float mnew = fmaxf(rm[mf][hf], mx);
                const float corr = __expf(rm[mf][hf] - mnew);
                rm[mf][hf] = mnew;
                float ps = 0.0f;
#pragma unroll
                for (int nf = 0; nf < 8; ++nf) {
                    float p0 = __expf(S[mf][nf][hf * 2 + 0] - mnew);
                    float p1 = __expf(S[mf][nf][hf * 2 + 1] - mnew);
                    S[mf][nf][hf * 2 + 0] = p0;
                    S[mf][nf][hf * 2 + 1] = p1;
                    ps += p0 + p1;
                }
                ps += __shfl_xor_sync(0xFFFFFFFFu, ps, 1);
                ps += __shfl_xor_sync(0xFFFFFFFFu, ps, 2);
                rl[mf][hf] = rl[mf][hf] * corr + ps;
#pragma unroll
                for (int nf = 0; nf < 8; ++nf) {
                    O[mf][nf][hf * 2 + 0] *= corr;
                    O[mf][nf][hf * 2 + 1] *= corr;
                }
            }
        }

#pragma unroll
        for (int kc = 0; kc < 4; ++kc) {
            uint32_t aP[2][2][4];
#pragma unroll
            for (int mf = 0; mf < 2; ++mf) {
#pragma unroll
                for (int e = 0; e < 2; ++e) {
                    const int nf = 2 * kc + e;
#pragma unroll
                    for (int hf = 0; hf < 2; ++hf) {
                        float x = S[mf][nf][hf * 2 + 0];
                        float y = S[mf][nf][hf * 2 + 1];
                        __half hx = __float2half_rn(x);
                        __half hy = __float2half_rn(y);
                        aP[0][mf][e * 2 + hf] = pack_h2(hx, hy);
                        aP[1][mf][e * 2 + hf] = pack_h2(
                            __float2half_rn(x - __half2float(hx)),
                            __float2half_rn(y - __half2float(hy)));
                    }
                }
            }
            uint32_t bV[4][4];
#pragma unroll
            for (int dg = 0; dg < 4; ++dg) {
                int row = kc * 16 + ((lane >> 3) & 1) * 8 + (lane & 7);
                int c = dg * 2 + ((lane >> 4) & 1);
                LDSM4T(bV[dg], st + 8192 + row * 128 + ((c ^ (row & 7)) << 4));
            }
#pragma unroll
            for (int mf = 0; mf < 2; ++mf)
#pragma unroll
                for (int nf = 0; nf < 8; ++nf) {
                    const int dg = nf >> 1, o = (nf & 1) * 2;
                    MMA_F16(O[mf][nf], aP[0][mf], bV[dg][o], bV[dg][o + 1]);
                }
#pragma unroll
            for (int mf = 0; mf < 2; ++mf)
#pragma unroll
                for (int nf = 0; nf < 8; ++nf) {
                    const int dg = nf >> 1, o = (nf & 1) * 2;
                    MMA_F16(O[mf][nf], aP[1][mf], bV[dg][o], bV[dg][o + 1]);
                }
        }

        __syncthreads();
        if (j + 2 < ntiles) { load_tile(j + 2, s); CPA_COMMIT(); }
        if (j + 1 < ntiles) {
            if (j + 2 < ntiles) { CPA_WAIT1(); } else { CPA_WAIT0(); }
        }
    }

#pragma unroll
    for (int mf = 0; mf < 2; ++mf) {
#pragma unroll
        for (int hf = 0; hf < 2; ++hf) {
            const float inv = kvs / rl[mf][hf];   // fold V dequant scale here
            const int row = qb * 128 + warp * 32 + mf * 16 + (lane >> 2) + hf * 8;
            const size_t ob = ((size_t)(b * TSEQ) + row) * CDIM + h * 64;
#pragma unroll
            for (int nf = 0; nf < 8; ++nf) {
                const int d = nf * 8 + (lane & 3) * 2;
                float v0 = O[mf][nf][hf * 2 + 0] * inv;
                float v1 = O[mf][nf][hf * 2 + 1] * inv;
                __half h0 = __float2half_rn(v0);
                __half h1 = __float2half_rn(v1);
                *(__half2*)(g_Ohi + ob + d) = __halves2half2(h0, h1);
                *(__half2*)(g_Olo + ob + d) = __halves2half2(
                    __float2half_rn(v0 - __half2float(h0)),
                    __float2half_rn(v1 - __half2float(h1)));
            }
        }
    }
}

// ---------------------------------------------------------------------------
// Launch
// ---------------------------------------------------------------------------
extern "C" void kernel_launch(void* const* d_in, const int* in_sizes, int n_in,
                              void* d_out, int out_size)
{
    const float* hidden   = (const float*)d_in[0];
    const float* W_attn   = (const float*)d_in[1];
    const float* b_attn   = (const float*)d_in[2];
    const float* W_proj   = (const float*)d_in[3];
    const float* b_proj   = (const float*)d_in[4];
    const float* kv_scale = (const float*)d_in[5];
    const float* kv_zp    = (const float*)d_in[6];
    float* out = (float*)d_out;

    cudaFuncSetAttribute((const void*)mma_gemm_kernel<0, 3>,
                         cudaFuncAttributeMaxDynamicSharedMemorySize, SMEM_DYN);
    cudaFuncSetAttribute((const void*)mma_gemm_kernel<1, 2>,
                         cudaFuncAttributeMaxDynamicSharedMemorySize, SMEM_DYN);
    cudaFuncSetAttribute(flash_mma_kernel,
                         cudaFuncAttributeMaxDynamicSharedMemorySize, FS_TOTAL);

    __half *Xhi, *Xlo, *WaThi, *WaTlo, *WpThi, *WpTlo, *Ohi, *Olo;
    cudaGetSymbolAddress((void**)&Xhi, g_Xhi);
    cudaGetSymbolAddress((void**)&Xlo, g_Xlo);
    cudaGetSymbolAddress((void**)&WaThi, g_WaThi);
    cudaGetSymbolAddress((void**)&WaTlo, g_WaTlo);
    cudaGetSymbolAddress((void**)&WpThi, g_WpThi);
    cudaGetSymbolAddress((void**)&WpTlo, g_WpTlo);
    cudaGetSymbolAddress((void**)&Ohi, g_Ohi);
    cudaGetSymbolAddress((void**)&Olo, g_Olo);

    // Prep
    split_kernel<<<1024, 256>>>(hidden, Xhi, Xlo, MROWS * CDIM / 4);
    transpose_split_kernel<<<dim3(NQKV / 32, CDIM / 32), 256>>>(W_attn, WaThi, WaTlo, CDIM, NQKV);
    transpose_split_kernel<<<dim3(CDIM / 32, CDIM / 32), 256>>>(W_proj, WpThi, WpTlo, CDIM, CDIM);

    // QKV GEMM (persistent, split-3) + bias + fake-quant + scatter
    mma_gemm_kernel<0, 3><<<GEMM_GRID, 256, SMEM_DYN>>>(
        Xhi, Xlo, WaThi, WaTlo, b_attn, NQKV, kv_scale, kv_zp, nullptr);

    // Tensor-core causal flash attention (scale folded)
    flash_mma_kernel<<<dim3(TSEQ / 128, NHEAD, BATCH), 128, FS_TOTAL>>>(kv_scale);

    // Output projection (split-2: drop O*Wp_lo term, ~2e-4 analytic error)
    mma_gemm_kernel<1, 2><<<256, 256, SMEM_DYN>>>(
        Ohi, Olo, WpThi, WpTlo, b_proj, CDIM, nullptr, nullptr, out);
}

// round 17
// speedup vs baseline: 1.3566x; 1.0251x over previous
#include <cuda_runtime.h>
#include <cuda_fp16.h>
#include <math.h>
#include <stdint.h>

#define BATCH 2
#define TSEQ  2048
#define CDIM  1024
#define NHEAD 16
#define HD    64
#define MROWS (BATCH * TSEQ)     // 4096
#define NQKV  (3 * CDIM)         // 3072
#define KDIM  1024

// ---------------------------------------------------------------------------
// Scratch (allocation-free: __device__ globals).
// Q: fp16 hi/lo planes. K,V: SINGLE fp16 plane holding exact (q - zp) integers.
// ---------------------------------------------------------------------------
#define QKV_ELEMS (BATCH * NHEAD * TSEQ * HD)
__device__ __align__(256) __half g_Qhi[QKV_ELEMS];
__device__ __align__(256) __half g_Qlo[QKV_ELEMS];
__device__ __align__(256) __half g_Kq[QKV_ELEMS];
__device__ __align__(256) __half g_Vq[QKV_ELEMS];
__device__ __align__(256) __half g_Xhi[MROWS * CDIM];
__device__ __align__(256) __half g_Xlo[MROWS * CDIM];
__device__ __align__(256) __half g_WaThi[NQKV * CDIM];
__device__ __align__(256) __half g_WaTlo[NQKV * CDIM];
__device__ __align__(256) __half g_WpThi[CDIM * CDIM];
__device__ __align__(256) __half g_WpTlo[CDIM * CDIM];
__device__ __align__(256) __half g_Ohi[MROWS * CDIM];
__device__ __align__(256) __half g_Olo[MROWS * CDIM];

// ---------------------------------------------------------------------------
// PTX helpers (arch-generic only: cp.async, ldmatrix, mma.sync)
// ---------------------------------------------------------------------------
__device__ __forceinline__ uint32_t smem_u32(const void* p) {
    uint32_t a;
    asm("{ .reg .u64 t; cvta.to.shared.u64 t, %1; cvt.u32.u64 %0, t; }"
        : "=r"(a) : "l"(p));
    return a;
}

#define CPA16(dst, src) \
    asm volatile("cp.async.cg.shared.global [%0], [%1], 16;" :: "r"(dst), "l"(src))
#define CPA_COMMIT() asm volatile("cp.async.commit_group;" ::: "memory")
#define CPA_WAIT1()  asm volatile("cp.async.wait_group 1;" ::: "memory")
#define CPA_WAIT0()  asm volatile("cp.async.wait_group 0;" ::: "memory")

#define LDSM4(r, addr)                                                        \
    asm volatile("ldmatrix.sync.aligned.m8n8.x4.shared.b16 {%0,%1,%2,%3}, [%4];" \
        : "=r"((r)[0]), "=r"((r)[1]), "=r"((r)[2]), "=r"((r)[3]) : "r"(addr))

#define LDSM4T(r, addr)                                                       \
    asm volatile("ldmatrix.sync.aligned.m8n8.x4.trans.shared.b16 {%0,%1,%2,%3}, [%4];" \
        : "=r"((r)[0]), "=r"((r)[1]), "=r"((r)[2]), "=r"((r)[3]) : "r"(addr))

#define MMA_F16(d, a, b0v, b1v)                                               \
    asm volatile("mma.sync.aligned.m16n8k16.row.col.f32.f16.f16.f32 "         \
        "{%0,%1,%2,%3}, {%4,%5,%6,%7}, {%8,%9}, {%0,%1,%2,%3};"               \
        : "+f"((d)[0]), "+f"((d)[1]), "+f"((d)[2]), "+f"((d)[3])              \
        : "r"((a)[0]), "r"((a)[1]), "r"((a)[2]), "r"((a)[3]),                 \
          "r"(b0v), "r"(b1v))

__device__ __forceinline__ uint32_t pack_h2(__half x, __half y) {
    __half2 h = __halves2half2(x, y);
    return *(uint32_t*)&h;
}

// ---------------------------------------------------------------------------
// Prep kernels: fp16 hi/lo split (+ transpose for weights)
// ---------------------------------------------------------------------------
__global__ void split_kernel(const float* __restrict__ in,
                             __half* __restrict__ hi,
                             __half* __restrict__ lo, int n4) {
    for (int i = blockIdx.x * blockDim.x + threadIdx.x; i < n4;
         i += gridDim.x * blockDim.x) {
        float4 v = ((const float4*)in)[i];
        __half hx = __float2half_rn(v.x);
        __half hy = __float2half_rn(v.y);
        __half hz = __float2half_rn(v.z);
        __half hw = __float2half_rn(v.w);
        __half lx = __float2half_rn(v.x - __half2float(hx));
        __half ly = __float2half_rn(v.y - __half2float(hy));
        __half lz = __float2half_rn(v.z - __half2float(hz));
        __half lw = __float2half_rn(v.w - __half2float(hw));
        ((__half2*)hi)[2 * i + 0] = __halves2half2(hx, hy);
        ((__half2*)hi)[2 * i + 1] = __halves2half2(hz, hw);
        ((__half2*)lo)[2 * i + 0] = __halves2half2(lx, ly);
        ((__half2*)lo)[2 * i + 1] = __halves2half2(lz, lw);
    }
}

__global__ void transpose_split_kernel(const float* __restrict__ in,
                                       __half* __restrict__ ohi,
                                       __half* __restrict__ olo,
                                       int R, int C) {
    __shared__ float t[32][33];
    const int c0 = blockIdx.x * 32, r0 = blockIdx.y * 32;
    const int x = threadIdx.x & 31, y0 = threadIdx.x >> 5;
#pragma unroll
    for (int i = 0; i < 4; ++i) {
        int y = y0 + i * 8;
        t[y][x] = in[(size_t)(r0 + y) * C + c0 + x];
    }
    __syncthreads();
#pragma unroll
    for (int i = 0; i < 4; ++i) {
        int yy = y0 + i * 8;
        float v = t[x][yy];
        __half hi = __float2half_rn(v);
        __half lo = __float2half_rn(v - __half2float(hi));
        size_t o = (size_t)(c0 + yy) * R + r0 + x;
        ohi[o] = hi;
        olo[o] = lo;
    }
}

// ---------------------------------------------------------------------------
// mma.sync fp16 GEMM (R14 structure: non-persistent, 3-stage, single barrier,
// 2 CTAs/SM). R16: per-tile split selection — Q-column tiles (n0 < CDIM in
// MODE 0) and the proj GEMM (MODE 1) use split-2 ((hi+lo)*hi, no B-lo plane);
// K/V tiles keep split-3 to avoid fake-quant flip amplification.
// MODE 0: fake-quant; K/V stored as EXACT integer-valued fp16; Q hi/lo.
// MODE 1: epilogue writes Cout row-major fp32.
// ---------------------------------------------------------------------------
#define STAGE_BYTES 32768        // Ahi 8K | Alo 8K | Bhi 8K | Blo 8K
#define NSTAGES 3
#define SMEM_DYN (STAGE_BYTES * NSTAGES)   // 98304

template <int MODE>
__global__ __launch_bounds__(256, 2) void mma_gemm_kernel(
    const __half* __restrict__ Ahi, const __half* __restrict__ Alo,
    const __half* __restrict__ Bhi, const __half* __restrict__ Blo,
    const float* __restrict__ bias, int Ncols,
    const float* __restrict__ scale_p, const float* __restrict__ zp_p,
    float* __restrict__ Cout)
{
    extern __shared__ __align__(1024) char smem[];
    const uint32_t sb = smem_u32(smem);
    const int tid = threadIdx.x;
    const int wid = tid >> 5, lane = tid & 31;
    const int m0 = blockIdx.y * 128, n0 = blockIdx.x * 128;
    const int wm = wid & 3;
    const int wn = wid >> 2;

    // split-3 only for K/V tiles of the QKV GEMM
    const bool use3 = (MODE == 0) && (n0 >= CDIM);

    float acc[2][8][4];
#pragma unroll
    for (int i = 0; i < 2; ++i)
#pragma unroll
        for (int j = 0; j < 8; ++j)
#pragma unroll
            for (int k = 0; k < 4; ++k) acc[i][j][k] = 0.0f;

    auto load_stage = [&](int kt, int s) {
        const uint32_t st = sb + (uint32_t)s * STAGE_BYTES;
        const int kb = kt * 32;
#pragma unroll
        for (int p = 0; p < 2; ++p) {
            const __half* src = p ? Alo : Ahi;
            const uint32_t po = st + p * 8192;
#pragma unroll
            for (int i = 0; i < 2; ++i) {
                int idx = tid + i * 256;
                int row = idx >> 2, c = idx & 3;
                uint32_t dst = po + row * 64 + ((c ^ ((row >> 1) & 3)) << 4);
                CPA16(dst, src + (size_t)(m0 + row) * KDIM + kb + c * 8);
            }
        }
        {
            const uint32_t po = st + 16384;
#pragma unroll
            for (int i = 0; i < 2; ++i) {
                int idx = tid + i * 256;
                int row = idx >> 2, c = idx & 3;
                uint32_t dst = po + row * 64 + ((c ^ ((row >> 1) & 3)) << 4);
                CPA16(dst, Bhi + (size_t)(n0 + row) * KDIM + kb + c * 8);
            }
        }
        if (use3) {
            const uint32_t po = st + 24576;
#pragma unroll
            for (int i = 0; i < 2; ++i) {
                int idx = tid + i * 256;
                int row = idx >> 2, c = idx & 3;
                uint32_t dst = po + row * 64 + ((c ^ ((row >> 1) & 3)) << 4);
                CPA16(dst, Blo + (size_t)(n0 + row) * KDIM + kb + c * 8);
            }
        }
        CPA_COMMIT();
    };

    load_stage(0, 0);
    load_stage(1, 1);

    const int NK = KDIM / 32;   // 32
    for (int kt = 0; kt < NK; ++kt) {
        const int s = kt % NSTAGES;
        if (kt + 1 < NK) { CPA_WAIT1(); } else { CPA_WAIT0(); }
        __syncthreads();                       // single barrier per k-tile

        const uint32_t st = sb + (uint32_t)s * STAGE_BYTES;
#pragma unroll
        for (int kh = 0; kh < 2; ++kh) {
            const int cbase = kh * 2;
            uint32_t a[2][2][4];
#pragma unroll
            for (int p = 0; p < 2; ++p) {
#pragma unroll
                for (int mf = 0; mf < 2; ++mf) {
                    int row = wm * 32 + mf * 16 + ((lane >> 3) & 1) * 8 + (lane & 7);
                    int c = cbase + ((lane >> 4) & 1);
                    uint32_t addr = st + p * 8192 + row * 64
                                  + ((c ^ ((row >> 1) & 3)) << 4);
                    LDSM4(a[p][mf], addr);
                }
            }
            uint32_t b0[16];
#pragma unroll
            for (int nq = 0; nq < 4; ++nq) {
                int row = wn * 64 + nq * 16 + ((lane >> 4) & 1) * 8 + (lane & 7);
                int c = cbase + ((lane >> 3) & 1);
                uint32_t addr = st + 16384 + row * 64
                              + ((c ^ ((row >> 1) & 3)) << 4);
                LDSM4(&b0[nq * 4], addr);
            }
#pragma unroll
            for (int mf = 0; mf < 2; ++mf)
#pragma unroll
                for (int nf = 0; nf < 8; ++nf) {
                    const int bi = (nf >> 1) * 4 + (nf & 1) * 2;
                    MMA_F16(acc[mf][nf], a[0][mf], b0[bi], b0[bi + 1]);
                }
#pragma unroll
            for (int mf = 0; mf < 2; ++mf)
#pragma unroll
                for (int nf = 0; nf < 8; ++nf) {
                    const int bi = (nf >> 1) * 4 + (nf & 1) * 2;
                    MMA_F16(acc[mf][nf], a[1][mf], b0[bi], b0[bi + 1]);
                }
            if (use3) {
                uint32_t b1[16];
#pragma unroll
                for (int nq = 0; nq < 4; ++nq) {
                    int row = wn * 64 + nq * 16 + ((lane >> 4) & 1) * 8 + (lane & 7);
                    int c = cbase + ((lane >> 3) & 1);
                    uint32_t addr = st + 24576 + row * 64
                                  + ((c ^ ((row >> 1) & 3)) << 4);
                    LDSM4(&b1[nq * 4], addr);
                }
#pragma unroll
                for (int mf = 0; mf < 2; ++mf)
#pragma unroll
                    for (int nf = 0; nf < 8; ++nf) {
                        const int bi = (nf >> 1) * 4 + (nf & 1) * 2;
                        MMA_F16(acc[mf][nf], a[0][mf], b1[bi], b1[bi + 1]);
                    }
            }
        }

        if (kt + 2 < NK) load_stage(kt + 2, (kt + 2) % NSTAGES);
    }

    float scl = 1.0f, zp = 0.0f;
    if (MODE == 0) { scl = *scale_p; zp = *zp_p; }

#pragma unroll
    for (int mf = 0; mf < 2; ++mf) {
#pragma unroll
        for (int nf = 0; nf < 8; ++nf) {
            const int n = n0 + wn * 64 + nf * 8 + (lane & 3) * 2;
            const float2 bv = *(const float2*)(bias + n);
#pragma unroll
            for (int half = 0; half < 2; ++half) {
                const int m = m0 + wm * 32 + mf * 16 + (lane >> 2) + half * 8;
                float v0 = acc[mf][nf][half * 2 + 0] + bv.x;
                float v1 = acc[mf][nf][half * 2 + 1] + bv.y;
                if (MODE == 0) {
                    const int bb = m >> 11;
                    const int t = m & 2047;
                    const int which = n >> 10;
                    const int cI = n & 1023;
                    const int h = cI >> 6, d = cI & 63;
                    const size_t idx = (((size_t)(bb * NHEAD + h) * TSEQ + t) * HD + d);
                    if (which == 0) {
                        __half h0 = __float2half_rn(v0);
                        __half h1 = __float2half_rn(v1);
                        *(__half2*)(g_Qhi + idx) = __halves2half2(h0, h1);
                        *(__half2*)(g_Qlo + idx) = __halves2half2(
                            __float2half_rn(v0 - __half2float(h0)),
                            __float2half_rn(v1 - __half2float(h1)));
                    } else {
                        // exact integer-valued fp16: q - zp in [-128, 127]
                        float q0 = fminf(fmaxf(rintf(v0 / scl + zp), 0.0f), 255.0f) - zp;
                        float q1 = fminf(fmaxf(rintf(v1 / scl + zp), 0.0f), 255.0f) - zp;
                        __half2 qv = __halves2half2(__float2half_rn(q0),
                                                    __float2half_rn(q1));
                        if (which == 1) *(__half2*)(g_Kq + idx) = qv;
                        else            *(__half2*)(g_Vq + idx) = qv;
                    }
                } else {
                    *(float2*)(Cout + (size_t)m * Ncols + n) = make_float2(v0, v1);
                }
            }
        }
    }
}

// ---------------------------------------------------------------------------
// Tensor-core causal flash attention (R14, proven). K/V single exact fp16
// planes; scale folded. R16: occupancy 3 (3 x 64KB SMEM fits in 228KB).
// ---------------------------------------------------------------------------
#define FS_QH 0
#define FS_QL 16384
#define FS_ST 32768
#define FS_STAGE 16384           // Kq 8K | Vq 8K
#define FS_TOTAL (FS_ST + 2 * FS_STAGE)   // 65536

__global__ __launch_bounds__(128, 3) void flash_mma_kernel(
    const float* __restrict__ scale_p)
{
    extern __shared__ __align__(1024) char fsm[];
    const uint32_t sb = smem_u32(fsm);
    const int qb = (TSEQ / 128 - 1) - blockIdx.x;   // long blocks first
    const int h = blockIdx.y, b = blockIdx.z;
    const int tid = threadIdx.x, warp = tid >> 5, lane = tid & 31;
    const size_t bh = (size_t)(b * NHEAD + h) * TSEQ * HD;
    const float kvs = *scale_p;

    const __half* Qh = g_Qhi + bh + (size_t)qb * 128 * HD;
    const __half* Ql = g_Qlo + bh + (size_t)qb * 128 * HD;
    const __half* Kq = g_Kq + bh;
    const __half* Vq = g_Vq + bh;

#pragma unroll
    for (int p = 0; p < 2; ++p) {
        const __half* src = p ? Ql : Qh;
        const uint32_t base = sb + (p ? FS_QL : FS_QH);
#pragma unroll
        for (int i = 0; i < 8; ++i) {
            int idx = tid + i * 128;
            int row = idx >> 3, c = idx & 7;
            CPA16(base + row * 128 + ((c ^ (row & 7)) << 4), src + row * 64 + c * 8);
        }
    }

    auto load_tile = [&](int j, int s) {
        const uint32_t st = sb + FS_ST + (uint32_t)s * FS_STAGE;
        const __half* srcs[2] = { Kq + (size_t)j * 64 * HD,
                                  Vq + (size_t)j * 64 * HD };
#pragma unroll
        for (int p = 0; p < 2; ++p) {
#pragma unroll
            for (int i = 0; i < 4; ++i) {
                int idx = tid + i * 128;
                int row = idx >> 3, c = idx & 7;
                CPA16(st + p * 8192 + row * 128 + ((c ^ (row & 7)) << 4),
                      srcs[p] + row * 64 + c * 8);
            }
        }
    };

    load_tile(0, 0);
    CPA_COMMIT();
    load_tile(1, 1);
    CPA_COMMIT();

    float O[2][8][4];
#pragma unroll
    for (int mf = 0; mf < 2; ++mf)
#pragma unroll
        for (int nf = 0; nf < 8; ++nf)
#pragma unroll
            for (int e = 0; e < 4; ++e) O[mf][nf][e] = 0.0f;
    float rm[2][2], rl[2][2];
#pragma unroll
    for (int mf = 0; mf < 2; ++mf)
#pragma unroll
        for (int hf = 0; hf < 2; ++hf) { rm[mf][hf] = -1e30f; rl[mf][hf] = 0.0f; }

    const int ntiles = 2 * qb + 2;
    const float sscale = 0.125f * kvs;      // 1/sqrt(64) * kv_scale
    CPA_WAIT1();

    for (int j = 0; j < ntiles; ++j) {
        const int s = j & 1;
        __syncthreads();
        const uint32_t st = sb + FS_ST + (uint32_t)s * FS_STAGE;

        float S[2][8][4];
#pragma unroll
        for (int mf = 0; mf < 2; ++mf)
#pragma unroll
            for (int nf = 0; nf < 8; ++nf)
#pragma unroll
                for (int e = 0; e < 4; ++e) S[mf][nf][e] = 0.0f;

#pragma unroll
        for (int ks = 0; ks < 4; ++ks) {
            uint32_t aQ[2][2][4];
#pragma unroll
            for (int p = 0; p < 2; ++p) {
#pragma unroll
                for (int mf = 0; mf < 2; ++mf) {
                    int row = warp * 32 + mf * 16 + ((lane >> 3) & 1) * 8 + (lane & 7);
                    int c = ks * 2 + ((lane >> 4) & 1);
                    LDSM4(aQ[p][mf], sb + (p ? FS_QL : FS_QH) + row * 128
                                     + ((c ^ (row & 7)) << 4));
                }
            }
            uint32_t bK[4][4];
#pragma unroll
            for (int kg = 0; kg < 4; ++kg) {
                int row = kg * 16 + ((lane >> 4) & 1) * 8 + (lane & 7);
                int c = ks * 2 + ((lane >> 3) & 1);
                LDSM4(bK[kg], st + row * 128 + ((c ^ (row & 7)) << 4));
            }
#pragma unroll
            for (int mf = 0; mf < 2; ++mf)
#pragma unroll
                for (int nf = 0; nf < 8; ++nf) {
                    const int kg = nf >> 1, o = (nf & 1) * 2;
                    MMA_F16(S[mf][nf], aQ[0][mf], bK[kg][o], bK[kg][o + 1]);
                }
#pragma unroll
            for (int mf = 0; mf < 2; ++mf)
#pragma unroll
                for (int nf = 0; nf < 8; ++nf) {
                    const int kg = nf >> 1, o = (nf & 1) * 2;
                    MMA_F16(S[mf][nf], aQ[1][mf], bK[kg][o], bK[kg][o + 1]);
                }
        }

        const bool maskT = (j >= 2 * qb);
#pragma unroll
        for (int mf = 0; mf < 2; ++mf)
#pragma unroll
            for (int nf = 0; nf < 8; ++nf)
#pragma unroll
                for (int e = 0; e < 4; ++e) {
                    float sv = S[mf][nf][e] * sscale;
                    if (maskT) {
                        const int key = j * 64 + nf * 8 + (lane & 3) * 2 + (e & 1);
                        const int rowg = qb * 128 + warp * 32 + mf * 16
                                       + (lane >> 2) + (e >> 1) * 8;
                        if (key > rowg) sv = -1e30f;
                    }
                    S[mf][nf][e] = sv;
                }

#pragma unroll
        for (int mf = 0; mf < 2; ++mf) {
#pragma unroll
            for (int hf = 0; hf < 2; ++hf) {
                float mx = -1e30f;
#pragma unroll
                for (int nf = 0; nf < 8; ++nf)
                    mx = fmaxf(mx, fmaxf(S[mf][nf][hf * 2], S[mf][nf][hf * 2 + 1]));
                mx = fmaxf(mx, __shfl_xor_sync(0xFFFFFFFFu, mx, 1));
                mx = fmaxf(mx, __shfl_xor_sync(0xFFFFFFFFu, mx, 2));
                const float mnew = fmaxf(rm[mf][hf], mx);
                const float corr = __expf(rm[mf][hf] - mnew);
                rm[mf][hf] = mnew;
                float ps = 0.0f;
#pragma unroll
                for (int nf = 0; nf < 8; ++nf) {
                    float p0 = __expf(S[mf][nf][hf * 2 + 0] - mnew);
                    float p1 = __expf(S[mf][nf][hf * 2 + 1] - mnew);
                    S[mf][nf][hf * 2 + 0] = p0;
                    S[mf][nf][hf * 2 + 1] = p1;
                    ps += p0 + p1;
                }
                ps += __shfl_xor_sync(0xFFFFFFFFu, ps, 1);
                ps += __shfl_xor_sync(0xFFFFFFFFu, ps, 2);
                rl[mf][hf] = rl[mf][hf] * corr + ps;
#pragma unroll
                for (int nf = 0; nf < 8; ++nf) {
                    O[mf][nf][hf * 2 + 0] *= corr;
                    O[mf][nf][hf * 2 + 1] *= corr;
                }
            }
        }

#pragma unroll
        for (int kc = 0; kc < 4; ++kc) {
            uint32_t aP[2][2][4];
#pragma unroll
            for (int mf = 0; mf < 2; ++mf) {
#pragma unroll
                for (int e = 0; e < 2; ++e) {
                    const int nf = 2 * kc + e;
#pragma unroll
                    for (int hf = 0; hf < 2; ++hf) {
                        float x = S[mf][nf][hf * 2 + 0];
                        float y = S[mf][nf][hf * 2 + 1];
                        __half hx = __float2half_rn(x);
                        __half hy = __float2half_rn(y);
                        aP[0][mf][e * 2 + hf] = pack_h2(hx, hy);
                        aP[1][mf][e * 2 + hf] = pack_h2(
                            __float2half_rn(x - __half2float(hx)),
                            __float2half_rn(y - __half2float(hy)));
                    }
                }
            }
            uint32_t bV[4][4];
#pragma unroll
            for (int dg = 0; dg < 4; ++dg) {
                int row = kc * 16 + ((lane >> 3) & 1) * 8 + (lane & 7);
                int c = dg * 2 + ((lane >> 4) & 1);
                LDSM4T(bV[dg], st + 8192 + row * 128 + ((c ^ (row & 7)) << 4));
            }
#pragma unroll
            for (int mf = 0; mf < 2; ++mf)
#pragma unroll
                for (int nf = 0; nf < 8; ++nf) {
                    const int dg = nf >> 1, o = (nf & 1) * 2;
                    MMA_F16(O[mf][nf], aP[0][mf], bV[dg][o], bV[dg][o + 1]);
                }
#pragma unroll
            for (int mf = 0; mf < 2; ++mf)
#pragma unroll
                for (int nf = 0; nf < 8; ++nf) {
                    const int dg = nf >> 1, o = (nf & 1) * 2;
                    MMA_F16(O[mf][nf], aP[1][mf], bV[dg][o], bV[dg][o + 1]);
                }
        }

        __syncthreads();
        if (j + 2 < ntiles) { load_tile(j + 2, s); CPA_COMMIT(); }
        if (j + 1 < ntiles) {
            if (j + 2 < ntiles) { CPA_WAIT1(); } else { CPA_WAIT0(); }
        }
    }

#pragma unroll
    for (int mf = 0; mf < 2; ++mf) {
#pragma unroll
        for (int hf = 0; hf < 2; ++hf) {
            const float inv = kvs / rl[mf][hf];   // fold V dequant scale here
            const int row = qb * 128 + warp * 32 + mf * 16 + (lane >> 2) + hf * 8;
            const size_t ob = ((size_t)(b * TSEQ) + row) * CDIM + h * 64;
#pragma unroll
            for (int nf = 0; nf < 8; ++nf) {
                const int d = nf * 8 + (lane & 3) * 2;
                float v0 = O[mf][nf][hf * 2 + 0] * inv;
                float v1 = O[mf][nf][hf * 2 + 1] * inv;
                __half h0 = __float2half_rn(v0);
                __half h1 = __float2half_rn(v1);
                *(__half2*)(g_Ohi + ob + d) = __halves2half2(h0, h1);
                *(__half2*)(g_Olo + ob + d) = __halves2half2(
                    __float2half_rn(v0 - __half2float(h0)),
                    __float2half_rn(v1 - __half2float(h1)));
            }
        }
    }
}

// ---------------------------------------------------------------------------
// Launch
// ---------------------------------------------------------------------------
extern "C" void kernel_launch(void* const* d_in, const int* in_sizes, int n_in,
                              void* d_out, int out_size)
{
    const float* hidden   = (const float*)d_in[0];
    const float* W_attn   = (const float*)d_in[1];
    const float* b_attn   = (const float*)d_in[2];
    const float* W_proj   = (const float*)d_in[3];
    const float* b_proj   = (const float*)d_in[4];
    const float* kv_scale = (const float*)d_in[5];
    const float* kv_zp    = (const float*)d_in[6];
    float* out = (float*)d_out;

    cudaFuncSetAttribute(mma_gemm_kernel<0>,
                         cudaFuncAttributeMaxDynamicSharedMemorySize, SMEM_DYN);
    cudaFuncSetAttribute(mma_gemm_kernel<1>,
                         cudaFuncAttributeMaxDynamicSharedMemorySize, SMEM_DYN);
    cudaFuncSetAttribute(flash_mma_kernel,
                         cudaFuncAttributeMaxDynamicSharedMemorySize, FS_TOTAL);

    __half *Xhi, *Xlo, *WaThi, *WaTlo, *WpThi, *WpTlo, *Ohi, *Olo;
    cudaGetSymbolAddress((void**)&Xhi, g_Xhi);
    cudaGetSymbolAddress((void**)&Xlo, g_Xlo);
    cudaGetSymbolAddress((void**)&WaThi, g_WaThi);
    cudaGetSymbolAddress((void**)&WaTlo, g_WaTlo);
    cudaGetSymbolAddress((void**)&WpThi, g_WpThi);
    cudaGetSymbolAddress((void**)&WpTlo, g_WpTlo);
    cudaGetSymbolAddress((void**)&Ohi, g_Ohi);
    cudaGetSymbolAddress((void**)&Olo, g_Olo);

    // Prep
    split_kernel<<<1024, 256>>>(hidden, Xhi, Xlo, MROWS * CDIM / 4);
    transpose_split_kernel<<<dim3(NQKV / 32, CDIM / 32), 256>>>(W_attn, WaThi, WaTlo, CDIM, NQKV);
    transpose_split_kernel<<<dim3(CDIM / 32, CDIM / 32), 256>>>(W_proj, WpThi, WpTlo, CDIM, CDIM);

    // QKV GEMM (Q tiles split-2, K/V tiles split-3) + fake-quant + scatter
    mma_gemm_kernel<0><<<dim3(NQKV / 128, MROWS / 128), 256, SMEM_DYN>>>(
        Xhi, Xlo, WaThi, WaTlo, b_attn, NQKV, kv_scale, kv_zp, nullptr);

    // Tensor-core causal flash attention (scale folded)
    flash_mma_kernel<<<dim3(TSEQ / 128, NHEAD, BATCH), 128, FS_TOTAL>>>(kv_scale);

    // Output projection (split-2)
    mma_gemm_kernel<1><<<dim3(CDIM / 128, MROWS / 128), 256, SMEM_DYN>>>(
        Ohi, Olo, WpThi, WpTlo, b_proj, CDIM, nullptr, nullptr, out);
}